// round 3
// baseline (speedup 1.0000x reference)
#include <cuda_runtime.h>
#include <cuda_bf16.h>
#include <cstdint>

// Problem constants (shapes fixed by the dataset).
#define B_   2
#define S_   3072
#define D_   2048
#define H_   16
#define HD_  128
#define M_   (B_ * S_)     // 6144 tokens

// ---------------------------------------------------------------------------
// Scratch (static device globals; no allocation anywhere)
// ---------------------------------------------------------------------------
__device__ float g_q[M_ * D_];
__device__ float g_k[M_ * D_];
__device__ float g_v[M_ * D_];
__device__ float g_attn[M_ * D_];

// ---------------------------------------------------------------------------
// tf32 helpers
// ---------------------------------------------------------------------------
__device__ __forceinline__ uint32_t f2tf32(float x) {
    uint32_t r;
    asm("cvt.rna.tf32.f32 %0, %1;" : "=r"(r) : "f"(x));
    return r;
}
__device__ __forceinline__ void split_tf32(float x, uint32_t& hi, uint32_t& lo) {
    hi = f2tf32(x);
    float r = x - __uint_as_float(hi);
    lo = f2tf32(r);
}
__device__ __forceinline__ void mma_tf32(float c[4], const uint32_t a[4],
                                         const uint32_t b[2]) {
    asm volatile(
        "mma.sync.aligned.m16n8k8.row.col.f32.tf32.tf32.f32 "
        "{%0,%1,%2,%3}, {%4,%5,%6,%7}, {%8,%9}, {%0,%1,%2,%3};"
        : "+f"(c[0]), "+f"(c[1]), "+f"(c[2]), "+f"(c[3])
        : "r"(a[0]), "r"(a[1]), "r"(a[2]), "r"(a[3]), "r"(b[0]), "r"(b[1]));
}

// ---------------------------------------------------------------------------
// GEMM (3xTF32 tensor-core):  O[m,n] = sum_k X[m,k] * W[n,k] + bias[n]
// X: (M_, 2048) row-major, W: (2048, 2048) row-major, O: (M_, 2048)
// Block tile 128x128, BK=32, 256 threads = 8 warps (2x4), warp tile 64x32.
// smem planes: A_hi, A_lo, B_hi, B_lo, each 128 rows x stride 36 (padded).
// ---------------------------------------------------------------------------
#define GBK   32
#define GSTR  36
#define GPLANE (128 * GSTR)
#define GEMM_SMEM (4 * GPLANE * 4)   // bytes = 73728

__global__ void __launch_bounds__(256, 1) gemm_tf32(
    const float* __restrict__ X,
    const float* __restrict__ W,
    const float* __restrict__ bias,
    float*       __restrict__ O)
{
    extern __shared__ uint32_t gsm[];
    uint32_t* Ah = gsm;
    uint32_t* Al = gsm + GPLANE;
    uint32_t* Bh = gsm + 2 * GPLANE;
    uint32_t* Bl = gsm + 3 * GPLANE;

    const int bm   = blockIdx.y * 128;
    const int bn   = blockIdx.x * 128;
    const int tid  = threadIdx.x;
    const int warp = tid >> 5;
    const int lane = tid & 31;
    const int lr   = lane >> 2;   // 0..7
    const int lc   = lane & 3;    // 0..3
    const int wm   = (warp & 1) * 64;   // 2 warps along M
    const int wn   = (warp >> 1) * 32;  // 4 warps along N

    // global-load mapping: each thread loads 4 float4 of A and 4 of B per tile
    const int grow = tid >> 3;          // 0..31
    const int gcol = (tid & 7) * 4;     // 0,4,...,28

    float acc[4][4][4];
    #pragma unroll
    for (int mi = 0; mi < 4; mi++)
        #pragma unroll
        for (int ni = 0; ni < 4; ni++)
            #pragma unroll
            for (int r = 0; r < 4; r++) acc[mi][ni][r] = 0.0f;

    float4 ra[4], rb[4];
    #pragma unroll
    for (int i = 0; i < 4; i++) {
        ra[i] = *(const float4*)(X + (size_t)(bm + grow + i * 32) * D_ + gcol);
        rb[i] = *(const float4*)(W + (size_t)(bn + grow + i * 32) * D_ + gcol);
    }

    for (int kt = 0; kt < D_; kt += GBK) {
        __syncthreads();   // previous tile fully consumed
        #pragma unroll
        for (int i = 0; i < 4; i++) {
            const int base = (grow + i * 32) * GSTR + gcol;
            uint4 h, l;
            split_tf32(ra[i].x, h.x, l.x);
            split_tf32(ra[i].y, h.y, l.y);
            split_tf32(ra[i].z, h.z, l.z);
            split_tf32(ra[i].w, h.w, l.w);
            *(uint4*)(Ah + base) = h;
            *(uint4*)(Al + base) = l;
            split_tf32(rb[i].x, h.x, l.x);
            split_tf32(rb[i].y, h.y, l.y);
            split_tf32(rb[i].z, h.z, l.z);
            split_tf32(rb[i].w, h.w, l.w);
            *(uint4*)(Bh + base) = h;
            *(uint4*)(Bl + base) = l;
        }
        __syncthreads();

        if (kt + GBK < D_) {
            #pragma unroll
            for (int i = 0; i < 4; i++) {
                ra[i] = *(const float4*)(X + (size_t)(bm + grow + i * 32) * D_ +
                                         kt + GBK + gcol);
                rb[i] = *(const float4*)(W + (size_t)(bn + grow + i * 32) * D_ +
                                         kt + GBK + gcol);
            }
        }

        #pragma unroll
        for (int kk = 0; kk < GBK; kk += 8) {
            uint32_t ah[4][4], al[4][4], bh[4][2], bl[4][2];
            #pragma unroll
            for (int mi = 0; mi < 4; mi++) {
                const int r0 = (wm + mi * 16 + lr) * GSTR + kk + lc;
                ah[mi][0] = Ah[r0];
                ah[mi][1] = Ah[r0 + 8 * GSTR];
                ah[mi][2] = Ah[r0 + 4];
                ah[mi][3] = Ah[r0 + 8 * GSTR + 4];
                al[mi][0] = Al[r0];
                al[mi][1] = Al[r0 + 8 * GSTR];
                al[mi][2] = Al[r0 + 4];
                al[mi][3] = Al[r0 + 8 * GSTR + 4];
            }
            #pragma unroll
            for (int ni = 0; ni < 4; ni++) {
                const int r0 = (wn + ni * 8 + lr) * GSTR + kk + lc;
                bh[ni][0] = Bh[r0];
                bh[ni][1] = Bh[r0 + 4];
                bl[ni][0] = Bl[r0];
                bl[ni][1] = Bl[r0 + 4];
            }
            #pragma unroll
            for (int mi = 0; mi < 4; mi++)
                #pragma unroll
                for (int ni = 0; ni < 4; ni++) {
                    mma_tf32(acc[mi][ni], ah[mi], bh[ni]);
                    mma_tf32(acc[mi][ni], al[mi], bh[ni]);
                    mma_tf32(acc[mi][ni], ah[mi], bl[ni]);
                }
        }
    }

    // epilogue: acc + bias -> O
    #pragma unroll
    for (int ni = 0; ni < 4; ni++) {
        const int c = bn + wn + ni * 8 + 2 * lc;
        const float b0 = __ldg(bias + c);
        const float b1 = __ldg(bias + c + 1);
        #pragma unroll
        for (int mi = 0; mi < 4; mi++) {
            const int r = bm + wm + mi * 16 + lr;
            float2 v0 = {acc[mi][ni][0] + b0, acc[mi][ni][1] + b1};
            float2 v1 = {acc[mi][ni][2] + b0, acc[mi][ni][3] + b1};
            *(float2*)(O + (size_t)r * D_ + c)       = v0;
            *(float2*)(O + (size_t)(r + 8) * D_ + c) = v1;
        }
    }
}

// ---------------------------------------------------------------------------
// Fused RMSNorm + interleaved RoPE, in place, for Q (blockIdx.y==0) and K (==1)
// ---------------------------------------------------------------------------
__global__ void __launch_bounds__(256) rms_rope(
    float* __restrict__ Tq, float* __restrict__ Tk,
    const float* __restrict__ gq, const float* __restrict__ gk,
    const float* __restrict__ rot)
{
    const int token = blockIdx.x;        // b*S + s
    const int s     = token % S_;
    float*       T  = (blockIdx.y == 0) ? Tq : Tk;
    const float* g  = (blockIdx.y == 0) ? gq : gk;
    const int t     = threadIdx.x;

    float* row = T + (size_t)token * D_;
    float4 v0 = *(const float4*)(row + t * 8);
    float4 v1 = *(const float4*)(row + t * 8 + 4);
    float x[8] = {v0.x, v0.y, v0.z, v0.w, v1.x, v1.y, v1.z, v1.w};

    float ss = 0.0f;
    #pragma unroll
    for (int i = 0; i < 8; i++) ss += x[i] * x[i];
    #pragma unroll
    for (int o = 16; o; o >>= 1) ss += __shfl_xor_sync(0xffffffffu, ss, o);

    __shared__ float red[8];
    __shared__ float rs_s;
    if ((t & 31) == 0) red[t >> 5] = ss;
    __syncthreads();
    if (t == 0) {
        float tot = 0.0f;
        #pragma unroll
        for (int i = 0; i < 8; i++) tot += red[i];
        rs_s = rsqrtf(tot * (1.0f / (float)D_) + 1e-6f);
    }
    __syncthreads();
    const float rs = rs_s;

    const float* rc = rot + (size_t)s * (2 * HD_);
    float out[8];
    #pragma unroll
    for (int j = 0; j < 4; j++) {
        const int d0 = t * 8 + 2 * j;          // even dim
        const int i2 = d0 & (HD_ - 1);         // 2*i within the head
        const float c  = rc[i2];               // cos[2i]
        const float sn = rc[HD_ + i2 + 1];     // sin[2i+1]
        const float x1 = x[2 * j]     * rs * g[d0];
        const float x2 = x[2 * j + 1] * rs * g[d0 + 1];
        out[2 * j]     = x1 * c - x2 * sn;
        out[2 * j + 1] = x1 * sn + x2 * c;
    }
    float4 o0 = {out[0], out[1], out[2], out[3]};
    float4 o1 = {out[4], out[5], out[6], out[7]};
    *(float4*)(row + t * 8)     = o0;
    *(float4*)(row + t * 8 + 4) = o1;
}

// ---------------------------------------------------------------------------
// Flash-style SDPA, fp32 SIMT (unchanged this round).
// ---------------------------------------------------------------------------
#define BM 64
#define BN 64
#define QK_STR 129
#define PS_STR 68

__global__ void __launch_bounds__(256) attn_kernel(
    const float* __restrict__ Q, const float* __restrict__ K,
    const float* __restrict__ V, float* __restrict__ Oa,
    const int* __restrict__ ctxp, const int* __restrict__ nseqp)
{
    extern __shared__ float sm[];
    float* Qs = sm;                           // BM * 129
    float* Ks = Qs + BM * QK_STR;             // BN * 129
    float* Ps = Ks + BN * QK_STR;             // BM * 68
    float* Vs = Ps + BM * PS_STR;             // BN * 128

    const int tid = threadIdx.x;
    const int tx  = tid & 15;
    const int ty  = tid >> 4;
    const int q0  = blockIdx.x * BM;
    const int h   = blockIdx.y;
    const int b   = blockIdx.z;
    const int hist = (S_ - ctxp[0]) / nseqp[0];

    const float scale = 0.08838834764831845f;   // 1/sqrt(128)

    const float* Qg = Q + (size_t)(b * S_ + q0) * D_ + h * HD_;
    #pragma unroll
    for (int i = 0; i < 8; i++) {
        int f  = tid + i * 256;                // 2048 float4s
        int r  = f >> 5;
        int c4 = (f & 31) * 4;
        float4 v = *(const float4*)(Qg + (size_t)r * D_ + c4);
        float* dst = Qs + r * QK_STR + c4;
        dst[0] = v.x * scale; dst[1] = v.y * scale;
        dst[2] = v.z * scale; dst[3] = v.w * scale;
    }

    float m[4], l[4], o[4][8];
    int kvlen[4];
    #pragma unroll
    for (int i = 0; i < 4; i++) {
        m[i] = -1e30f; l[i] = 0.0f;
        #pragma unroll
        for (int d = 0; d < 8; d++) o[i][d] = 0.0f;
        const int sq = q0 + ty * 4 + i;
        kvlen[i] = (sq < hist) ? hist : S_;
    }
    const int kv_end = (q0 + BM - 1 < hist) ? hist : S_;

    const float* Kg = K + (size_t)b * S_ * D_ + h * HD_;
    const float* Vg = V + (size_t)b * S_ * D_ + h * HD_;

    for (int kt = 0; kt < kv_end; kt += BN) {
        __syncthreads();
        #pragma unroll
        for (int i = 0; i < 8; i++) {
            int f  = tid + i * 256;
            int r  = f >> 5;
            int c4 = (f & 31) * 4;
            float4 kv = *(const float4*)(Kg + (size_t)(kt + r) * D_ + c4);
            float* kd = Ks + r * QK_STR + c4;
            kd[0] = kv.x; kd[1] = kv.y; kd[2] = kv.z; kd[3] = kv.w;
            float4 vv = *(const float4*)(Vg + (size_t)(kt + r) * D_ + c4);
            *(float4*)(Vs + r * HD_ + c4) = vv;
        }
        __syncthreads();

        float sc[4][4];
        #pragma unroll
        for (int i = 0; i < 4; i++)
            #pragma unroll
            for (int j = 0; j < 4; j++) sc[i][j] = 0.0f;

        const float* qb = Qs + (ty * 4) * QK_STR;
        const float* kb = Ks + (tx * 4) * QK_STR;
        #pragma unroll 4
        for (int kk = 0; kk < HD_; kk++) {
            float qf[4], kf[4];
            #pragma unroll
            for (int i = 0; i < 4; i++) qf[i] = qb[i * QK_STR + kk];
            #pragma unroll
            for (int j = 0; j < 4; j++) kf[j] = kb[j * QK_STR + kk];
            #pragma unroll
            for (int i = 0; i < 4; i++)
                #pragma unroll
                for (int j = 0; j < 4; j++)
                    sc[i][j] = fmaf(qf[i], kf[j], sc[i][j]);
        }

        #pragma unroll
        for (int i = 0; i < 4; i++)
            #pragma unroll
            for (int j = 0; j < 4; j++)
                if (kt + tx * 4 + j >= kvlen[i]) sc[i][j] = -1e30f;

        #pragma unroll
        for (int i = 0; i < 4; i++) {
            float mx = fmaxf(fmaxf(sc[i][0], sc[i][1]), fmaxf(sc[i][2], sc[i][3]));
            mx = fmaxf(mx, __shfl_xor_sync(0xffffffffu, mx, 1));
            mx = fmaxf(mx, __shfl_xor_sync(0xffffffffu, mx, 2));
            mx = fmaxf(mx, __shfl_xor_sync(0xffffffffu, mx, 4));
            mx = fmaxf(mx, __shfl_xor_sync(0xffffffffu, mx, 8));
            const float mn   = fmaxf(m[i], mx);
            const float corr = __expf(m[i] - mn);
            m[i] = mn;
            float p0 = __expf(sc[i][0] - mn);
            float p1 = __expf(sc[i][1] - mn);
            float p2 = __expf(sc[i][2] - mn);
            float p3 = __expf(sc[i][3] - mn);
            float psum = p0 + p1 + p2 + p3;
            psum += __shfl_xor_sync(0xffffffffu, psum, 1);
            psum += __shfl_xor_sync(0xffffffffu, psum, 2);
            psum += __shfl_xor_sync(0xffffffffu, psum, 4);
            psum += __shfl_xor_sync(0xffffffffu, psum, 8);
            l[i] = l[i] * corr + psum;
            #pragma unroll
            for (int d = 0; d < 8; d++) o[i][d] *= corr;
            float4 pv4 = {p0, p1, p2, p3};
            *(float4*)(Ps + (ty * 4 + i) * PS_STR + tx * 4) = pv4;
        }
        __syncthreads();

        const float* pb = Ps + (ty * 4) * PS_STR;
        #pragma unroll 2
        for (int k = 0; k < BN; k++) {
            float4 v0 = *(const float4*)(Vs + k * HD_ + tx * 8);
            float4 v1 = *(const float4*)(Vs + k * HD_ + tx * 8 + 4);
            #pragma unroll
            for (int i = 0; i < 4; i++) {
                const float p = pb[i * PS_STR + k];
                o[i][0] = fmaf(p, v0.x, o[i][0]);
                o[i][1] = fmaf(p, v0.y, o[i][1]);
                o[i][2] = fmaf(p, v0.z, o[i][2]);
                o[i][3] = fmaf(p, v0.w, o[i][3]);
                o[i][4] = fmaf(p, v1.x, o[i][4]);
                o[i][5] = fmaf(p, v1.y, o[i][5]);
                o[i][6] = fmaf(p, v1.z, o[i][6]);
                o[i][7] = fmaf(p, v1.w, o[i][7]);
            }
        }
    }

    float* Og = Oa + (size_t)(b * S_ + q0 + ty * 4) * D_ + h * HD_ + tx * 8;
    #pragma unroll
    for (int i = 0; i < 4; i++) {
        const float inv = 1.0f / l[i];
        float4 r0 = {o[i][0] * inv, o[i][1] * inv, o[i][2] * inv, o[i][3] * inv};
        float4 r1 = {o[i][4] * inv, o[i][5] * inv, o[i][6] * inv, o[i][7] * inv};
        *(float4*)(Og + (size_t)i * D_)     = r0;
        *(float4*)(Og + (size_t)i * D_ + 4) = r1;
    }
}

// ---------------------------------------------------------------------------
// kernel_launch
// ---------------------------------------------------------------------------
extern "C" void kernel_launch(void* const* d_in, const int* in_sizes, int n_in,
                              void* d_out, int out_size)
{
    const float* hidden = (const float*)d_in[0];
    const float* rot    = (const float*)d_in[1];
    const float* Wq = (const float*)d_in[2];
    const float* bq = (const float*)d_in[3];
    const float* Wk = (const float*)d_in[4];
    const float* bk = (const float*)d_in[5];
    const float* Wv = (const float*)d_in[6];
    const float* bv = (const float*)d_in[7];
    const float* gq = (const float*)d_in[8];
    const float* gk = (const float*)d_in[9];
    const float* Wo = (const float*)d_in[10];
    const float* bo = (const float*)d_in[11];
    const int*   ctx  = (const int*)d_in[12];
    const int*   nseq = (const int*)d_in[13];
    float* out = (float*)d_out;

    float *q, *k, *v, *a;
    cudaGetSymbolAddress((void**)&q, g_q);
    cudaGetSymbolAddress((void**)&k, g_k);
    cudaGetSymbolAddress((void**)&v, g_v);
    cudaGetSymbolAddress((void**)&a, g_attn);

    cudaFuncSetAttribute(gemm_tf32, cudaFuncAttributeMaxDynamicSharedMemorySize,
                         GEMM_SMEM);

    const dim3 gemm_grid(D_ / 128, M_ / 128);   // (16, 48)

    // QKV projections (3xTF32 tensor cores)
    gemm_tf32<<<gemm_grid, 256, GEMM_SMEM>>>(hidden, Wq, bq, q);
    gemm_tf32<<<gemm_grid, 256, GEMM_SMEM>>>(hidden, Wk, bk, k);
    gemm_tf32<<<gemm_grid, 256, GEMM_SMEM>>>(hidden, Wv, bv, v);

    // RMSNorm + RoPE on q and k (in place)
    rms_rope<<<dim3(M_, 2), 256>>>(q, k, gq, gk, rot);

    // Attention
    const int smem_bytes = (BM * QK_STR + BN * QK_STR + BM * PS_STR + BN * HD_) * 4;
    cudaFuncSetAttribute(attn_kernel, cudaFuncAttributeMaxDynamicSharedMemorySize,
                         smem_bytes);
    attn_kernel<<<dim3(S_ / BM, H_, B_), 256, smem_bytes>>>(q, k, v, a, ctx, nseq);

    // Output projection -> d_out
    gemm_tf32<<<gemm_grid, 256, GEMM_SMEM>>>(a, Wo, bo, out);
}

// round 5
// speedup vs baseline: 2.3439x; 2.3439x over previous
#include <cuda_runtime.h>
#include <cuda_fp16.h>
#include <cstdint>

#define B_   2
#define S_   3072
#define D_   2048
#define H_   16
#define HD_  128
#define M_   (B_ * S_)     // 6144 tokens

// ---------------- scratch (no allocation anywhere) -------------------------
__device__ float  g_q[M_ * D_];
__device__ float  g_k[M_ * D_];
__device__ float  g_v[M_ * D_];
__device__ float  g_attn[M_ * D_];
__device__ __half g_xh[M_ * D_], g_xl[M_ * D_];         // hidden hi/lo
__device__ __half g_ah[M_ * D_], g_al[M_ * D_];         // attn-out hi/lo
__device__ __half g_wh[4 * D_ * D_], g_wl[4 * D_ * D_]; // Wq,Wk,Wv,Wo hi/lo
__device__ __half g_qh[M_ * D_], g_ql[M_ * D_];
__device__ __half g_kh[M_ * D_], g_kl[M_ * D_];
__device__ __half g_vh[M_ * D_], g_vl[M_ * D_];

// ---------------- helpers ----------------------------------------------------
__device__ __forceinline__ uint32_t smem_u32(const void* p) {
    uint32_t a;
    asm("{ .reg .u64 t; cvta.to.shared.u64 t, %1; cvt.u32.u64 %0, t; }"
        : "=r"(a) : "l"(p));
    return a;
}
__device__ __forceinline__ void mma_f16(float c[4], const uint32_t a[4],
                                        const uint32_t b[2]) {
    asm volatile(
        "mma.sync.aligned.m16n8k16.row.col.f32.f16.f16.f32 "
        "{%0,%1,%2,%3}, {%4,%5,%6,%7}, {%8,%9}, {%0,%1,%2,%3};"
        : "+f"(c[0]), "+f"(c[1]), "+f"(c[2]), "+f"(c[3])
        : "r"(a[0]), "r"(a[1]), "r"(a[2]), "r"(a[3]), "r"(b[0]), "r"(b[1]));
}
__device__ __forceinline__ void ldsm_x4_t(uint32_t& r0, uint32_t& r1,
                                          uint32_t& r2, uint32_t& r3, uint32_t a) {
    asm volatile("ldmatrix.sync.aligned.m8n8.x4.trans.shared.b16 "
                 "{%0,%1,%2,%3}, [%4];"
                 : "=r"(r0), "=r"(r1), "=r"(r2), "=r"(r3) : "r"(a));
}
__device__ __forceinline__ uint32_t pack_h2(__half a, __half b) {
    __half2 t = __halves2half2(a, b);
    return *reinterpret_cast<uint32_t*>(&t);
}
#define CP_ASYNC16(s, g) \
    asm volatile("cp.async.cg.shared.global [%0], [%1], 16;" :: "r"(s), "l"(g))
#define CP_COMMIT()  asm volatile("cp.async.commit_group;" ::: "memory")
#define CP_WAIT(n)   asm volatile("cp.async.wait_group %0;" :: "n"(n) : "memory")

// ---------------- split fp32 -> fp16 hi/lo -----------------------------------
__global__ void __launch_bounds__(256) split_fp16(
    const float* __restrict__ in, __half* __restrict__ hp, __half* __restrict__ lp,
    int n, float prescale)
{
    int i = (blockIdx.x * 256 + threadIdx.x) * 4;
    if (i >= n) return;
    float4 v = *(const float4*)(in + i);
    float x[4] = {v.x * prescale, v.y * prescale, v.z * prescale, v.w * prescale};
    __half h[4], l[4];
    #pragma unroll
    for (int j = 0; j < 4; j++) {
        h[j] = __float2half_rn(x[j]);
        l[j] = __float2half_rn(x[j] - __half2float(h[j]));
    }
    *(__half2*)(hp + i)     = __halves2half2(h[0], h[1]);
    *(__half2*)(hp + i + 2) = __halves2half2(h[2], h[3]);
    *(__half2*)(lp + i)     = __halves2half2(l[0], l[1]);
    *(__half2*)(lp + i + 2) = __halves2half2(l[2], l[3]);
}

// ---------------------------------------------------------------------------
// fp16 3-term tensor GEMM:  O[m,n] = unscale * sum_k A[m,k]*B[n,k] + bias[n]
// Inputs pre-split into hi/lo fp16 planes, K = 2048 contiguous.
// Block 128x128, BK=32 halves, 8 warps (2x4), warp 64x32.
// ---------------------------------------------------------------------------
#define GSTRW 20                 // words per smem row (40 halves)
#define GPLW  (128 * GSTRW)      // words per plane

__global__ void __launch_bounds__(256, 1) gemm_f16(
    const __half* __restrict__ Ahg, const __half* __restrict__ Alg,
    const __half* __restrict__ Bhg, const __half* __restrict__ Blg,
    const float*  __restrict__ bias, float* __restrict__ O, float unscale)
{
    __shared__ uint32_t gsm[4 * GPLW];   // 40 KB
    uint32_t* Ah = gsm;
    uint32_t* Al = gsm + GPLW;
    uint32_t* Bh = gsm + 2 * GPLW;
    uint32_t* Bl = gsm + 3 * GPLW;

    const int bm   = blockIdx.y * 128;
    const int bn   = blockIdx.x * 128;
    const int tid  = threadIdx.x;
    const int warp = tid >> 5;
    const int lane = tid & 31;
    const int lr   = lane >> 2;
    const int lc   = lane & 3;
    const int wm   = (warp & 1) * 64;
    const int wn   = (warp >> 1) * 32;

    const int row0 = tid >> 2;        // 0..63
    const int c0   = (tid & 3) * 8;   // halves offset of 16B chunk

    float acc[4][4][4];
    #pragma unroll
    for (int mi = 0; mi < 4; mi++)
        #pragma unroll
        for (int ni = 0; ni < 4; ni++)
            #pragma unroll
            for (int r = 0; r < 4; r++) acc[mi][ni][r] = 0.0f;

    uint4 pa[2][2], pb[2][2];
    #pragma unroll
    for (int p = 0; p < 2; p++) {
        const __half* sa = p ? Alg : Ahg;
        const __half* sb2 = p ? Blg : Bhg;
        pa[p][0] = *(const uint4*)(sa + (size_t)(bm + row0) * D_ + c0);
        pa[p][1] = *(const uint4*)(sa + (size_t)(bm + row0 + 64) * D_ + c0);
        pb[p][0] = *(const uint4*)(sb2 + (size_t)(bn + row0) * D_ + c0);
        pb[p][1] = *(const uint4*)(sb2 + (size_t)(bn + row0 + 64) * D_ + c0);
    }

    for (int s = 0; s < 64; s++) {
        __syncthreads();
        const int w0 = row0 * GSTRW + (c0 >> 1);           // word dst
        const int w1 = (row0 + 64) * GSTRW + (c0 >> 1);
        *(uint4*)(Ah + w0) = pa[0][0]; *(uint4*)(Ah + w1) = pa[0][1];
        *(uint4*)(Al + w0) = pa[1][0]; *(uint4*)(Al + w1) = pa[1][1];
        *(uint4*)(Bh + w0) = pb[0][0]; *(uint4*)(Bh + w1) = pb[0][1];
        *(uint4*)(Bl + w0) = pb[1][0]; *(uint4*)(Bl + w1) = pb[1][1];
        __syncthreads();

        if (s < 63) {
            const int kt = (s + 1) * 32;
            #pragma unroll
            for (int p = 0; p < 2; p++) {
                const __half* sa = p ? Alg : Ahg;
                const __half* sb2 = p ? Blg : Bhg;
                pa[p][0] = *(const uint4*)(sa + (size_t)(bm + row0) * D_ + kt + c0);
                pa[p][1] = *(const uint4*)(sa + (size_t)(bm + row0 + 64) * D_ + kt + c0);
                pb[p][0] = *(const uint4*)(sb2 + (size_t)(bn + row0) * D_ + kt + c0);
                pb[p][1] = *(const uint4*)(sb2 + (size_t)(bn + row0 + 64) * D_ + kt + c0);
            }
        }

        #pragma unroll
        for (int kk = 0; kk < 2; kk++) {
            const int kw = kk * 8;
            uint32_t ah[4][4], al[4][4], bh[4][2], bl[4][2];
            #pragma unroll
            for (int mi = 0; mi < 4; mi++) {
                const int w = (wm + mi * 16 + lr) * GSTRW + kw + lc;
                ah[mi][0] = Ah[w];       ah[mi][1] = Ah[w + 8 * GSTRW];
                ah[mi][2] = Ah[w + 4];   ah[mi][3] = Ah[w + 8 * GSTRW + 4];
                al[mi][0] = Al[w];       al[mi][1] = Al[w + 8 * GSTRW];
                al[mi][2] = Al[w + 4];   al[mi][3] = Al[w + 8 * GSTRW + 4];
            }
            #pragma unroll
            for (int ni = 0; ni < 4; ni++) {
                const int w = (wn + ni * 8 + lr) * GSTRW + kw + lc;
                bh[ni][0] = Bh[w]; bh[ni][1] = Bh[w + 4];
                bl[ni][0] = Bl[w]; bl[ni][1] = Bl[w + 4];
            }
            #pragma unroll
            for (int mi = 0; mi < 4; mi++)
                #pragma unroll
                for (int ni = 0; ni < 4; ni++) {
                    mma_f16(acc[mi][ni], ah[mi], bh[ni]);
                    mma_f16(acc[mi][ni], al[mi], bh[ni]);
                    mma_f16(acc[mi][ni], ah[mi], bl[ni]);
                }
        }
    }

    #pragma unroll
    for (int ni = 0; ni < 4; ni++) {
        const int c = bn + wn + ni * 8 + 2 * lc;
        const float b0 = __ldg(bias + c);
        const float b1 = __ldg(bias + c + 1);
        #pragma unroll
        for (int mi = 0; mi < 4; mi++) {
            const int r = bm + wm + mi * 16 + lr;
            float2 v0 = {acc[mi][ni][0] * unscale + b0, acc[mi][ni][1] * unscale + b1};
            float2 v1 = {acc[mi][ni][2] * unscale + b0, acc[mi][ni][3] * unscale + b1};
            *(float2*)(O + (size_t)r * D_ + c)       = v0;
            *(float2*)(O + (size_t)(r + 8) * D_ + c) = v1;
        }
    }
}

// ---------------------------------------------------------------------------
// RMSNorm + interleaved RoPE -> fp16 hi/lo planes (q scaled by 1/sqrt(HD))
// ---------------------------------------------------------------------------
__global__ void __launch_bounds__(256) rms_rope_split(
    const float* __restrict__ Tq, const float* __restrict__ Tk,
    const float* __restrict__ gq, const float* __restrict__ gk,
    const float* __restrict__ rot,
    __half* __restrict__ qh, __half* __restrict__ ql,
    __half* __restrict__ kh, __half* __restrict__ kl)
{
    const int token = blockIdx.x;
    const int s     = token % S_;
    const bool isq  = (blockIdx.y == 0);
    const float* T  = isq ? Tq : Tk;
    const float* g  = isq ? gq : gk;
    __half* hp = isq ? qh : kh;
    __half* lp = isq ? ql : kl;
    const float post = isq ? 0.08838834764831845f : 1.0f;
    const int t = threadIdx.x;

    const float* row = T + (size_t)token * D_;
    float4 v0 = *(const float4*)(row + t * 8);
    float4 v1 = *(const float4*)(row + t * 8 + 4);
    float x[8] = {v0.x, v0.y, v0.z, v0.w, v1.x, v1.y, v1.z, v1.w};

    float ss = 0.0f;
    #pragma unroll
    for (int i = 0; i < 8; i++) ss += x[i] * x[i];
    #pragma unroll
    for (int o = 16; o; o >>= 1) ss += __shfl_xor_sync(0xffffffffu, ss, o);

    __shared__ float red[8];
    __shared__ float rs_s;
    if ((t & 31) == 0) red[t >> 5] = ss;
    __syncthreads();
    if (t == 0) {
        float tot = 0.0f;
        #pragma unroll
        for (int i = 0; i < 8; i++) tot += red[i];
        rs_s = rsqrtf(tot * (1.0f / (float)D_) + 1e-6f);
    }
    __syncthreads();
    const float rs = rs_s;

    const float* rc = rot + (size_t)s * (2 * HD_);
    float out[8];
    #pragma unroll
    for (int j = 0; j < 4; j++) {
        const int d0 = t * 8 + 2 * j;
        const int i2 = d0 & (HD_ - 1);
        const float c  = rc[i2];
        const float sn = rc[HD_ + i2 + 1];
        const float x1 = x[2 * j]     * rs * g[d0];
        const float x2 = x[2 * j + 1] * rs * g[d0 + 1];
        out[2 * j]     = (x1 * c - x2 * sn) * post;
        out[2 * j + 1] = (x1 * sn + x2 * c) * post;
    }
    __half hh[8], ll[8];
    #pragma unroll
    for (int j = 0; j < 8; j++) {
        hh[j] = __float2half_rn(out[j]);
        ll[j] = __float2half_rn(out[j] - __half2float(hh[j]));
    }
    uint32_t* hd = (uint32_t*)(hp + (size_t)token * D_ + t * 8);
    uint32_t* ld = (uint32_t*)(lp + (size_t)token * D_ + t * 8);
    #pragma unroll
    for (int j = 0; j < 4; j++) {
        hd[j] = pack_h2(hh[2 * j], hh[2 * j + 1]);
        ld[j] = pack_h2(ll[2 * j], ll[2 * j + 1]);
    }
}

// ---------------------------------------------------------------------------
// fp16 tensor flash attention.  CTA = 128 queries of one (b,h); key tiles 64.
// 8 warps, each owns 16 q rows (softmax warp-local).  QK: qh*kh+ql*kh+qh*kl.
// PV: ph*vh+pl*vh+ph*vl with P split in registers, V via ldmatrix.trans.
// ---------------------------------------------------------------------------
#define AQ 128
#define AK 64
#define KSH 136                       // halves per smem row
#define QPH (128 * KSH)               // 17408 halves per Q plane
#define KVPH (64 * KSH)               // 8704 halves per KV plane
#define ATT_SMEM ((2 * QPH + 8 * KVPH) * 2)   // 208896 bytes

__global__ void __launch_bounds__(256, 1) attn_f16(
    const __half* __restrict__ Qh, const __half* __restrict__ Ql,
    const __half* __restrict__ Kh, const __half* __restrict__ Kl,
    const __half* __restrict__ Vh, const __half* __restrict__ Vl,
    float* __restrict__ Oa,
    const int* __restrict__ ctxp, const int* __restrict__ nseqp)
{
    extern __shared__ __align__(16) __half smh[];
    const uint32_t sb = smem_u32(smh);
    const uint32_t* SW = reinterpret_cast<const uint32_t*>(smh);

    const int tid  = threadIdx.x;
    const int warp = tid >> 5;
    const int lane = tid & 31;
    const int lr   = lane >> 2;
    const int lc   = lane & 3;
    const int q0   = blockIdx.x * AQ;
    const int h    = blockIdx.y;
    const int b    = blockIdx.z;
    const int hist = (S_ - ctxp[0]) / nseqp[0];

    const int wm = warp * 16;
    const int q_lo = q0 + wm + lr;
    const int kvlen_lo = (q_lo < hist) ? hist : S_;
    const int kvlen_hi = (q_lo + 8 < hist) ? hist : S_;
    const int kv_end = (q0 + AQ <= hist) ? hist : S_;
    const int ntiles = (kv_end + AK - 1) / AK;

    // ---- stage Q (both planes) ----
    const size_t qoff = ((size_t)(b * S_ + q0)) * D_ + h * HD_;
    #pragma unroll
    for (int i = 0; i < 16; i++) {
        int idx = i * 256 + tid;
        int pl = idx >> 11, w = idx & 2047, r = w >> 4, c = w & 15;
        uint32_t dst = sb + (pl * QPH + r * KSH + c * 8) * 2;
        const __half* src = (pl ? Ql : Qh) + qoff + (size_t)r * D_ + c * 8;
        CP_ASYNC16(dst, src);
    }
    CP_COMMIT();

    const size_t kvo = ((size_t)(b * S_)) * D_ + h * HD_;
    const __half* Khp = Kh + kvo;
    const __half* Klp = Kl + kvo;
    const __half* Vhp = Vh + kvo;
    const __half* Vlp = Vl + kvo;

    auto load_kv = [&](int kt, int bi) {
        const uint32_t baseh = 2 * QPH + bi * 4 * KVPH;
        #pragma unroll
        for (int i = 0; i < 16; i++) {
            int idx = i * 256 + tid;
            int pl = idx >> 10, w = idx & 1023, r = w >> 4, c = w & 15;
            const __half* s = (pl == 0) ? Khp : (pl == 1) ? Klp
                            : (pl == 2) ? Vhp : Vlp;
            uint32_t dst = sb + (baseh + pl * KVPH + r * KSH + c * 8) * 2;
            CP_ASYNC16(dst, s + (size_t)(kt + r) * D_ + c * 8);
        }
        CP_COMMIT();
    };

    load_kv(0, 0);
    load_kv(AK, 1);   // kt=64 < S always valid to read; masked if beyond kv_end

    float oc[16][4];
    #pragma unroll
    for (int f = 0; f < 16; f++)
        #pragma unroll
        for (int e = 0; e < 4; e++) oc[f][e] = 0.0f;
    float m_lo = -1e30f, m_hi = -1e30f, l_lo = 0.0f, l_hi = 0.0f;

    for (int t = 0; t < ntiles; t++) {
        const int kt = t * AK;
        if (t + 1 < ntiles) { CP_WAIT(1); } else { CP_WAIT(0); }
        __syncthreads();

        const uint32_t bufw = (2 * QPH + (t & 1) * 4 * KVPH) >> 1;  // words
        const uint32_t khw = bufw, klw = bufw + (KVPH >> 1);

        // ---- S = Q K^T (3 terms) ----
        float sc[8][4];
        #pragma unroll
        for (int j = 0; j < 8; j++)
            #pragma unroll
            for (int e = 0; e < 4; e++) sc[j][e] = 0.0f;

        #pragma unroll
        for (int kd = 0; kd < 8; kd++) {
            uint32_t a_h[4], a_l[4];
            const int qw = (wm + lr) * (KSH >> 1) + kd * 8 + lc;
            a_h[0] = SW[qw];       a_h[1] = SW[qw + 8 * (KSH >> 1)];
            a_h[2] = SW[qw + 4];   a_h[3] = SW[qw + 8 * (KSH >> 1) + 4];
            const int qlw = qw + (QPH >> 1);
            a_l[0] = SW[qlw];      a_l[1] = SW[qlw + 8 * (KSH >> 1)];
            a_l[2] = SW[qlw + 4];  a_l[3] = SW[qlw + 8 * (KSH >> 1) + 4];
            #pragma unroll
            for (int j = 0; j < 8; j++) {
                const int kw = (j * 8 + lr) * (KSH >> 1) + kd * 8 + lc;
                uint32_t b_h[2] = {SW[khw + kw], SW[khw + kw + 4]};
                uint32_t b_l[2] = {SW[klw + kw], SW[klw + kw + 4]};
                mma_f16(sc[j], a_h, b_h);
                mma_f16(sc[j], a_l, b_h);
                mma_f16(sc[j], a_h, b_l);
            }
        }

        // ---- mask ----
        if (kt + AK > kvlen_lo || kt + AK > kvlen_hi) {
            #pragma unroll
            for (int j = 0; j < 8; j++) {
                const int c0 = kt + j * 8 + 2 * lc;
                if (c0     >= kvlen_lo) sc[j][0] = -1e30f;
                if (c0 + 1 >= kvlen_lo) sc[j][1] = -1e30f;
                if (c0     >= kvlen_hi) sc[j][2] = -1e30f;
                if (c0 + 1 >= kvlen_hi) sc[j][3] = -1e30f;
            }
        }

        // ---- online softmax (warp-local rows) ----
        float mx_lo = -1e30f, mx_hi = -1e30f;
        #pragma unroll
        for (int j = 0; j < 8; j++) {
            mx_lo = fmaxf(mx_lo, fmaxf(sc[j][0], sc[j][1]));
            mx_hi = fmaxf(mx_hi, fmaxf(sc[j][2], sc[j][3]));
        }
        mx_lo = fmaxf(mx_lo, __shfl_xor_sync(0xffffffffu, mx_lo, 1));
        mx_lo = fmaxf(mx_lo, __shfl_xor_sync(0xffffffffu, mx_lo, 2));
        mx_hi = fmaxf(mx_hi, __shfl_xor_sync(0xffffffffu, mx_hi, 1));
        mx_hi = fmaxf(mx_hi, __shfl_xor_sync(0xffffffffu, mx_hi, 2));
        const float mn_lo = fmaxf(m_lo, mx_lo);
        const float mn_hi = fmaxf(m_hi, mx_hi);
        const float corr_lo = __expf(m_lo - mn_lo);
        const float corr_hi = __expf(m_hi - mn_hi);
        m_lo = mn_lo; m_hi = mn_hi;

        uint32_t ph01[8], ph23[8], pl01[8], pl23[8];
        float s_lo = 0.0f, s_hi = 0.0f;
        #pragma unroll
        for (int j = 0; j < 8; j++) {
            float p0 = __expf(sc[j][0] - mn_lo);
            float p1 = __expf(sc[j][1] - mn_lo);
            float p2 = __expf(sc[j][2] - mn_hi);
            float p3 = __expf(sc[j][3] - mn_hi);
            s_lo += p0 + p1; s_hi += p2 + p3;
            __half h0 = __float2half_rn(p0), h1 = __float2half_rn(p1);
            __half h2 = __float2half_rn(p2), h3 = __float2half_rn(p3);
            ph01[j] = pack_h2(h0, h1);
            ph23[j] = pack_h2(h2, h3);
            pl01[j] = pack_h2(__float2half_rn(p0 - __half2float(h0)),
                              __float2half_rn(p1 - __half2float(h1)));
            pl23[j] = pack_h2(__float2half_rn(p2 - __half2float(h2)),
                              __float2half_rn(p3 - __half2float(h3)));
        }
        s_lo += __shfl_xor_sync(0xffffffffu, s_lo, 1);
        s_lo += __shfl_xor_sync(0xffffffffu, s_lo, 2);
        s_hi += __shfl_xor_sync(0xffffffffu, s_hi, 1);
        s_hi += __shfl_xor_sync(0xffffffffu, s_hi, 2);
        l_lo = l_lo * corr_lo + s_lo;
        l_hi = l_hi * corr_hi + s_hi;
        #pragma unroll
        for (int f = 0; f < 16; f++) {
            oc[f][0] *= corr_lo; oc[f][1] *= corr_lo;
            oc[f][2] *= corr_hi; oc[f][3] *= corr_hi;
        }

        // ---- O += P V (3 terms) ----
        const uint32_t vh_h = (bufw << 1) + 2 * KVPH;   // halves
        const uint32_t vl_h = vh_h + KVPH;
        const int vrow = lane & 15;
        const int vcol = (lane >> 4) * 8;
        #pragma unroll
        for (int ks = 0; ks < 4; ks++) {
            uint32_t a_h[4] = {ph01[2 * ks], ph23[2 * ks],
                               ph01[2 * ks + 1], ph23[2 * ks + 1]};
            uint32_t a_l[4] = {pl01[2 * ks], pl23[2 * ks],
                               pl01[2 * ks + 1], pl23[2 * ks + 1]};
            const int vr = ks * 16 + vrow;
            #pragma unroll
            for (int jp = 0; jp < 8; jp++) {
                uint32_t r0, r1, r2, r3, s0, s1, s2, s3;
                uint32_t ah_addr = sb + (vh_h + vr * KSH + jp * 16 + vcol) * 2;
                uint32_t al_addr = sb + (vl_h + vr * KSH + jp * 16 + vcol) * 2;
                ldsm_x4_t(r0, r1, r2, r3, ah_addr);
                ldsm_x4_t(s0, s1, s2, s3, al_addr);
                uint32_t bh0[2] = {r0, r1}, bh1[2] = {r2, r3};
                uint32_t bl0[2] = {s0, s1}, bl1[2] = {s2, s3};
                mma_f16(oc[2 * jp],     a_h, bh0);
                mma_f16(oc[2 * jp + 1], a_h, bh1);
                mma_f16(oc[2 * jp],     a_l, bh0);
                mma_f16(oc[2 * jp + 1], a_l, bh1);
                mma_f16(oc[2 * jp],     a_h, bl0);
                mma_f16(oc[2 * jp + 1], a_h, bl1);
            }
        }

        __syncthreads();
        if (t + 2 < ntiles) load_kv((t + 2) * AK, t & 1);
    }
    CP_WAIT(0);

    // ---- epilogue ----
    const float inv_lo = 1.0f / l_lo;
    const float inv_hi = 1.0f / l_hi;
    float* olo = Oa + ((size_t)(b * S_ + q0 + wm + lr)) * D_ + h * HD_;
    float* ohi = olo + (size_t)8 * D_;
    #pragma unroll
    for (int f = 0; f < 16; f++) {
        const int hd = f * 8 + 2 * lc;
        float2 vlo = {oc[f][0] * inv_lo, oc[f][1] * inv_lo};
        float2 vhi = {oc[f][2] * inv_hi, oc[f][3] * inv_hi};
        *(float2*)(olo + hd) = vlo;
        *(float2*)(ohi + hd) = vhi;
    }
}

// ---------------- kernel_launch ---------------------------------------------
extern "C" void kernel_launch(void* const* d_in, const int* in_sizes, int n_in,
                              void* d_out, int out_size)
{
    const float* hidden = (const float*)d_in[0];
    const float* rot    = (const float*)d_in[1];
    const float* Wq = (const float*)d_in[2];
    const float* bq = (const float*)d_in[3];
    const float* Wk = (const float*)d_in[4];
    const float* bk = (const float*)d_in[5];
    const float* Wv = (const float*)d_in[6];
    const float* bv = (const float*)d_in[7];
    const float* gq = (const float*)d_in[8];
    const float* gk = (const float*)d_in[9];
    const float* Wo = (const float*)d_in[10];
    const float* bo = (const float*)d_in[11];
    const int*   ctx  = (const int*)d_in[12];
    const int*   nseq = (const int*)d_in[13];
    float* out = (float*)d_out;

    float *q, *k, *v, *a;
    __half *xh, *xl, *ah, *al, *wh, *wl, *qh, *ql, *kh, *kl, *vh, *vl;
    cudaGetSymbolAddress((void**)&q, g_q);
    cudaGetSymbolAddress((void**)&k, g_k);
    cudaGetSymbolAddress((void**)&v, g_v);
    cudaGetSymbolAddress((void**)&a, g_attn);
    cudaGetSymbolAddress((void**)&xh, g_xh);
    cudaGetSymbolAddress((void**)&xl, g_xl);
    cudaGetSymbolAddress((void**)&ah, g_ah);
    cudaGetSymbolAddress((void**)&al, g_al);
    cudaGetSymbolAddress((void**)&wh, g_wh);
    cudaGetSymbolAddress((void**)&wl, g_wl);
    cudaGetSymbolAddress((void**)&qh, g_qh);
    cudaGetSymbolAddress((void**)&ql, g_ql);
    cudaGetSymbolAddress((void**)&kh, g_kh);
    cudaGetSymbolAddress((void**)&kl, g_kl);
    cudaGetSymbolAddress((void**)&vh, g_vh);
    cudaGetSymbolAddress((void**)&vl, g_vl);

    const float WS = 1024.0f, IWS = 1.0f / 1024.0f;
    const int nX = M_ * D_, nW = D_ * D_;

    split_fp16<<<nX / 1024, 256>>>(hidden, xh, xl, nX, 1.0f);
    split_fp16<<<nW / 1024, 256>>>(Wq, wh + 0 * (size_t)nW, wl + 0 * (size_t)nW, nW, WS);
    split_fp16<<<nW / 1024, 256>>>(Wk, wh + 1 * (size_t)nW, wl + 1 * (size_t)nW, nW, WS);
    split_fp16<<<nW / 1024, 256>>>(Wv, wh + 2 * (size_t)nW, wl + 2 * (size_t)nW, nW, WS);
    split_fp16<<<nW / 1024, 256>>>(Wo, wh + 3 * (size_t)nW, wl + 3 * (size_t)nW, nW, WS);

    const dim3 gg(D_ / 128, M_ / 128);   // (16, 48)
    gemm_f16<<<gg, 256>>>(xh, xl, wh + 0 * (size_t)nW, wl + 0 * (size_t)nW, bq, q, IWS);
    gemm_f16<<<gg, 256>>>(xh, xl, wh + 1 * (size_t)nW, wl + 1 * (size_t)nW, bk, k, IWS);
    gemm_f16<<<gg, 256>>>(xh, xl, wh + 2 * (size_t)nW, wl + 2 * (size_t)nW, bv, v, IWS);

    rms_rope_split<<<dim3(M_, 2), 256>>>(q, k, gq, gk, rot, qh, ql, kh, kl);
    split_fp16<<<nX / 1024, 256>>>(v, vh, vl, nX, 1.0f);

    cudaFuncSetAttribute(attn_f16, cudaFuncAttributeMaxDynamicSharedMemorySize,
                         ATT_SMEM);
    attn_f16<<<dim3(S_ / AQ, H_, B_), 256, ATT_SMEM>>>(qh, ql, kh, kl, vh, vl,
                                                       a, ctx, nseq);

    split_fp16<<<nX / 1024, 256>>>(a, ah, al, nX, 1.0f);
    gemm_f16<<<gg, 256>>>(ah, al, wh + 3 * (size_t)nW, wl + 3 * (size_t)nW, bo, out, IWS);
}

// round 6
// speedup vs baseline: 2.7755x; 1.1842x over previous
#include <cuda_runtime.h>
#include <cuda_fp16.h>
#include <cstdint>

#define B_   2
#define S_   3072
#define D_   2048
#define H_   16
#define HD_  128
#define M_   (B_ * S_)     // 6144 tokens

// ---------------- scratch (no allocation anywhere) -------------------------
__device__ float  g_q[M_ * D_];
__device__ float  g_k[M_ * D_];
__device__ __half g_xh[M_ * D_], g_xl[M_ * D_];         // hidden hi/lo
__device__ __half g_ah[M_ * D_], g_al[M_ * D_];         // attn-out hi/lo
__device__ __half g_wh[4 * D_ * D_], g_wl[4 * D_ * D_]; // Wq,Wk,Wv,Wo hi/lo
__device__ __half g_qh[M_ * D_], g_ql[M_ * D_];
__device__ __half g_kh[M_ * D_];
__device__ __half g_vh[M_ * D_];

// ---------------- helpers ----------------------------------------------------
__device__ __forceinline__ uint32_t smem_u32(const void* p) {
    uint32_t a;
    asm("{ .reg .u64 t; cvta.to.shared.u64 t, %1; cvt.u32.u64 %0, t; }"
        : "=r"(a) : "l"(p));
    return a;
}
__device__ __forceinline__ void mma_f16(float c[4], const uint32_t a[4],
                                        const uint32_t b[2]) {
    asm volatile(
        "mma.sync.aligned.m16n8k16.row.col.f32.f16.f16.f32 "
        "{%0,%1,%2,%3}, {%4,%5,%6,%7}, {%8,%9}, {%0,%1,%2,%3};"
        : "+f"(c[0]), "+f"(c[1]), "+f"(c[2]), "+f"(c[3])
        : "r"(a[0]), "r"(a[1]), "r"(a[2]), "r"(a[3]), "r"(b[0]), "r"(b[1]));
}
__device__ __forceinline__ void ldsm_x4_t(uint32_t& r0, uint32_t& r1,
                                          uint32_t& r2, uint32_t& r3, uint32_t a) {
    asm volatile("ldmatrix.sync.aligned.m8n8.x4.trans.shared.b16 "
                 "{%0,%1,%2,%3}, [%4];"
                 : "=r"(r0), "=r"(r1), "=r"(r2), "=r"(r3) : "r"(a));
}
__device__ __forceinline__ uint32_t pack_h2(__half a, __half b) {
    __half2 t = __halves2half2(a, b);
    return *reinterpret_cast<uint32_t*>(&t);
}
#define CP_ASYNC16(s, g) \
    asm volatile("cp.async.cg.shared.global [%0], [%1], 16;" :: "r"(s), "l"(g))
#define CP_COMMIT()  asm volatile("cp.async.commit_group;" ::: "memory")
#define CP_WAIT(n)   asm volatile("cp.async.wait_group %0;" :: "n"(n) : "memory")

// ---------------- split fp32 -> fp16 hi/lo -----------------------------------
__global__ void __launch_bounds__(256) split_fp16(
    const float* __restrict__ in, __half* __restrict__ hp, __half* __restrict__ lp,
    int n, float prescale)
{
    int i = (blockIdx.x * 256 + threadIdx.x) * 4;
    if (i >= n) return;
    float4 v = *(const float4*)(in + i);
    float x[4] = {v.x * prescale, v.y * prescale, v.z * prescale, v.w * prescale};
    __half h[4], l[4];
    #pragma unroll
    for (int j = 0; j < 4; j++) {
        h[j] = __float2half_rn(x[j]);
        l[j] = __float2half_rn(x[j] - __half2float(h[j]));
    }
    *(__half2*)(hp + i)     = __halves2half2(h[0], h[1]);
    *(__half2*)(hp + i + 2) = __halves2half2(h[2], h[3]);
    *(__half2*)(lp + i)     = __halves2half2(l[0], l[1]);
    *(__half2*)(lp + i + 2) = __halves2half2(l[2], l[3]);
}

// ---------------------------------------------------------------------------
// fp16 3-term tensor GEMM, cp.async triple-buffered.
//   O[m,n] = unscale * sum_k A[m,k]*B[n,k] + bias[n]
// If Oh != nullptr: write fp16(O) to Oh instead of float to Of.
// Block 128x128, BK=32 halves, 8 warps (2x4), warp 64x32.
// ---------------------------------------------------------------------------
#define GSTRW 20                  // words per smem row (40 halves)
#define GPLW  (128 * GSTRW)       // words per plane (10 KB)
#define GBUFW (4 * GPLW)          // words per stage (40 KB)
#define GEMM_SMEM (3 * GBUFW * 4) // 122880 bytes

__global__ void __launch_bounds__(256, 1) gemm_f16(
    const __half* __restrict__ Ahg, const __half* __restrict__ Alg,
    const __half* __restrict__ Bhg, const __half* __restrict__ Blg,
    const float*  __restrict__ bias, float* __restrict__ Of,
    __half* __restrict__ Oh, float unscale)
{
    extern __shared__ uint32_t gsm[];

    const int bm   = blockIdx.y * 128;
    const int bn   = blockIdx.x * 128;
    const int tid  = threadIdx.x;
    const int warp = tid >> 5;
    const int lane = tid & 31;
    const int lr   = lane >> 2;
    const int lc   = lane & 3;
    const int wm   = (warp & 1) * 64;
    const int wn   = (warp >> 1) * 32;

    const __half* gsrc[4] = {Ahg + (size_t)bm * D_, Alg + (size_t)bm * D_,
                             Bhg + (size_t)bn * D_, Blg + (size_t)bn * D_};
    const uint32_t sbase = smem_u32(gsm);

    auto load_stage = [&](int s, int buf) {
        const int kt = s * 32;
        #pragma unroll
        for (int i = 0; i < 8; i++) {
            const int g   = i * 256 + tid;      // 0..2047
            const int pl  = g >> 9;
            const int w   = g & 511;
            const int row = w >> 2;
            const int c   = w & 3;
            uint32_t dst = sbase +
                (buf * GBUFW + pl * GPLW + row * GSTRW + c * 4) * 4;
            CP_ASYNC16(dst, gsrc[pl] + (size_t)row * D_ + kt + c * 8);
        }
        CP_COMMIT();
    };

    float acc[4][4][4];
    #pragma unroll
    for (int mi = 0; mi < 4; mi++)
        #pragma unroll
        for (int ni = 0; ni < 4; ni++)
            #pragma unroll
            for (int r = 0; r < 4; r++) acc[mi][ni][r] = 0.0f;

    load_stage(0, 0);
    load_stage(1, 1);

    for (int s = 0; s < 64; s++) {
        CP_WAIT(1);
        __syncthreads();
        if (s + 2 < 64) load_stage(s + 2, (s + 2) % 3);

        const uint32_t* Ah = gsm + (s % 3) * GBUFW;
        const uint32_t* Al = Ah + GPLW;
        const uint32_t* Bh = Ah + 2 * GPLW;
        const uint32_t* Bl = Ah + 3 * GPLW;

        #pragma unroll
        for (int kk = 0; kk < 2; kk++) {
            const int kw = kk * 8;
            uint32_t ah[4][4], al[4][4], bh[4][2], bl[4][2];
            #pragma unroll
            for (int mi = 0; mi < 4; mi++) {
                const int w = (wm + mi * 16 + lr) * GSTRW + kw + lc;
                ah[mi][0] = Ah[w];       ah[mi][1] = Ah[w + 8 * GSTRW];
                ah[mi][2] = Ah[w + 4];   ah[mi][3] = Ah[w + 8 * GSTRW + 4];
                al[mi][0] = Al[w];       al[mi][1] = Al[w + 8 * GSTRW];
                al[mi][2] = Al[w + 4];   al[mi][3] = Al[w + 8 * GSTRW + 4];
            }
            #pragma unroll
            for (int ni = 0; ni < 4; ni++) {
                const int w = (wn + ni * 8 + lr) * GSTRW + kw + lc;
                bh[ni][0] = Bh[w]; bh[ni][1] = Bh[w + 4];
                bl[ni][0] = Bl[w]; bl[ni][1] = Bl[w + 4];
            }
            #pragma unroll
            for (int mi = 0; mi < 4; mi++)
                #pragma unroll
                for (int ni = 0; ni < 4; ni++) {
                    mma_f16(acc[mi][ni], ah[mi], bh[ni]);
                    mma_f16(acc[mi][ni], al[mi], bh[ni]);
                    mma_f16(acc[mi][ni], ah[mi], bl[ni]);
                }
        }
    }

    #pragma unroll
    for (int ni = 0; ni < 4; ni++) {
        const int c = bn + wn + ni * 8 + 2 * lc;
        const float b0 = __ldg(bias + c);
        const float b1 = __ldg(bias + c + 1);
        #pragma unroll
        for (int mi = 0; mi < 4; mi++) {
            const int r = bm + wm + mi * 16 + lr;
            const float v00 = acc[mi][ni][0] * unscale + b0;
            const float v01 = acc[mi][ni][1] * unscale + b1;
            const float v10 = acc[mi][ni][2] * unscale + b0;
            const float v11 = acc[mi][ni][3] * unscale + b1;
            if (Oh) {
                *(__half2*)(Oh + (size_t)r * D_ + c) =
                    __halves2half2(__float2half_rn(v00), __float2half_rn(v01));
                *(__half2*)(Oh + (size_t)(r + 8) * D_ + c) =
                    __halves2half2(__float2half_rn(v10), __float2half_rn(v11));
            } else {
                *(float2*)(Of + (size_t)r * D_ + c)       = float2{v00, v01};
                *(float2*)(Of + (size_t)(r + 8) * D_ + c) = float2{v10, v11};
            }
        }
    }
}

// ---------------------------------------------------------------------------
// RMSNorm + interleaved RoPE -> fp16 planes: qh+ql (q scaled 1/sqrt(HD)), kh.
// ---------------------------------------------------------------------------
__global__ void __launch_bounds__(256) rms_rope_split(
    const float* __restrict__ Tq, const float* __restrict__ Tk,
    const float* __restrict__ gq, const float* __restrict__ gk,
    const float* __restrict__ rot,
    __half* __restrict__ qh, __half* __restrict__ ql,
    __half* __restrict__ kh)
{
    const int token = blockIdx.x;
    const int s     = token % S_;
    const bool isq  = (blockIdx.y == 0);
    const float* T  = isq ? Tq : Tk;
    const float* g  = isq ? gq : gk;
    const float post = isq ? 0.08838834764831845f : 1.0f;
    const int t = threadIdx.x;

    const float* row = T + (size_t)token * D_;
    float4 v0 = *(const float4*)(row + t * 8);
    float4 v1 = *(const float4*)(row + t * 8 + 4);
    float x[8] = {v0.x, v0.y, v0.z, v0.w, v1.x, v1.y, v1.z, v1.w};

    float ss = 0.0f;
    #pragma unroll
    for (int i = 0; i < 8; i++) ss += x[i] * x[i];
    #pragma unroll
    for (int o = 16; o; o >>= 1) ss += __shfl_xor_sync(0xffffffffu, ss, o);

    __shared__ float red[8];
    __shared__ float rs_s;
    if ((t & 31) == 0) red[t >> 5] = ss;
    __syncthreads();
    if (t == 0) {
        float tot = 0.0f;
        #pragma unroll
        for (int i = 0; i < 8; i++) tot += red[i];
        rs_s = rsqrtf(tot * (1.0f / (float)D_) + 1e-6f);
    }
    __syncthreads();
    const float rs = rs_s;

    const float* rc = rot + (size_t)s * (2 * HD_);
    float out[8];
    #pragma unroll
    for (int j = 0; j < 4; j++) {
        const int d0 = t * 8 + 2 * j;
        const int i2 = d0 & (HD_ - 1);
        const float c  = rc[i2];
        const float sn = rc[HD_ + i2 + 1];
        const float x1 = x[2 * j]     * rs * g[d0];
        const float x2 = x[2 * j + 1] * rs * g[d0 + 1];
        out[2 * j]     = (x1 * c - x2 * sn) * post;
        out[2 * j + 1] = (x1 * sn + x2 * c) * post;
    }
    __half hh[8];
    #pragma unroll
    for (int j = 0; j < 8; j++) hh[j] = __float2half_rn(out[j]);

    if (isq) {
        uint32_t* hd = (uint32_t*)(qh + (size_t)token * D_ + t * 8);
        uint32_t* ld = (uint32_t*)(ql + (size_t)token * D_ + t * 8);
        #pragma unroll
        for (int j = 0; j < 4; j++) {
            __half l0 = __float2half_rn(out[2 * j]     - __half2float(hh[2 * j]));
            __half l1 = __float2half_rn(out[2 * j + 1] - __half2float(hh[2 * j + 1]));
            hd[j] = pack_h2(hh[2 * j], hh[2 * j + 1]);
            ld[j] = pack_h2(l0, l1);
        }
    } else {
        uint32_t* hd = (uint32_t*)(kh + (size_t)token * D_ + t * 8);
        #pragma unroll
        for (int j = 0; j < 4; j++) hd[j] = pack_h2(hh[2 * j], hh[2 * j + 1]);
    }
}

// ---------------------------------------------------------------------------
// fp16 tensor flash attention, 2-term QK (qh*kh + ql*kh), 2-term PV
// (ph*vh + pl*vh).  CTA = 128 queries of one (b,h); key tiles 64.
// Output written directly as fp16 hi/lo planes for the Wo GEMM.
// ---------------------------------------------------------------------------
#define AQ 128
#define AK 64
#define KSH 136                        // halves per smem row
#define QPH (128 * KSH)                // halves per Q plane
#define KVPH (64 * KSH)                // halves per KV plane
#define ATT_SMEM ((2 * QPH + 4 * KVPH) * 2)   // 139264 bytes

__global__ void __launch_bounds__(256, 1) attn_f16(
    const __half* __restrict__ Qh, const __half* __restrict__ Ql,
    const __half* __restrict__ Kh, const __half* __restrict__ Vh,
    __half* __restrict__ Oah, __half* __restrict__ Oal,
    const int* __restrict__ ctxp, const int* __restrict__ nseqp)
{
    extern __shared__ __align__(16) __half smh[];
    const uint32_t sb = smem_u32(smh);
    const uint32_t* SW = reinterpret_cast<const uint32_t*>(smh);

    const int tid  = threadIdx.x;
    const int warp = tid >> 5;
    const int lane = tid & 31;
    const int lr   = lane >> 2;
    const int lc   = lane & 3;
    const int q0   = blockIdx.x * AQ;
    const int h    = blockIdx.y;
    const int b    = blockIdx.z;
    const int hist = (S_ - ctxp[0]) / nseqp[0];

    const int wm = warp * 16;
    const int q_lo = q0 + wm + lr;
    const int kvlen_lo = (q_lo < hist) ? hist : S_;
    const int kvlen_hi = (q_lo + 8 < hist) ? hist : S_;
    const int kv_end = (q0 + AQ <= hist) ? hist : S_;
    const int ntiles = (kv_end + AK - 1) / AK;

    // ---- stage Q (hi+lo planes) ----
    const size_t qoff = ((size_t)(b * S_ + q0)) * D_ + h * HD_;
    #pragma unroll
    for (int i = 0; i < 16; i++) {
        int idx = i * 256 + tid;
        int pl = idx >> 11, w = idx & 2047, r = w >> 4, c = w & 15;
        uint32_t dst = sb + (pl * QPH + r * KSH + c * 8) * 2;
        const __half* src = (pl ? Ql : Qh) + qoff + (size_t)r * D_ + c * 8;
        CP_ASYNC16(dst, src);
    }
    CP_COMMIT();

    const size_t kvo = ((size_t)(b * S_)) * D_ + h * HD_;
    const __half* Khp = Kh + kvo;
    const __half* Vhp = Vh + kvo;

    auto load_kv = [&](int kt, int bi) {
        const uint32_t baseh = 2 * QPH + bi * 2 * KVPH;
        #pragma unroll
        for (int i = 0; i < 8; i++) {
            int idx = i * 256 + tid;
            int pl = idx >> 10, w = idx & 1023, r = w >> 4, c = w & 15;
            const __half* s = pl ? Vhp : Khp;
            uint32_t dst = sb + (baseh + pl * KVPH + r * KSH + c * 8) * 2;
            CP_ASYNC16(dst, s + (size_t)(kt + r) * D_ + c * 8);
        }
        CP_COMMIT();
    };

    load_kv(0, 0);
    load_kv(AK, 1);

    float oc[16][4];
    #pragma unroll
    for (int f = 0; f < 16; f++)
        #pragma unroll
        for (int e = 0; e < 4; e++) oc[f][e] = 0.0f;
    float m_lo = -1e30f, m_hi = -1e30f, l_lo = 0.0f, l_hi = 0.0f;

    for (int t = 0; t < ntiles; t++) {
        const int kt = t * AK;
        if (t + 1 < ntiles) { CP_WAIT(1); } else { CP_WAIT(0); }
        __syncthreads();

        const uint32_t khw = (2 * QPH + (t & 1) * 2 * KVPH) >> 1;  // words

        // ---- S = Q K^T (2 terms) ----
        float sc[8][4];
        #pragma unroll
        for (int j = 0; j < 8; j++)
            #pragma unroll
            for (int e = 0; e < 4; e++) sc[j][e] = 0.0f;

        #pragma unroll
        for (int kd = 0; kd < 8; kd++) {
            uint32_t a_h[4], a_l[4];
            const int qw = (wm + lr) * (KSH >> 1) + kd * 8 + lc;
            a_h[0] = SW[qw];       a_h[1] = SW[qw + 8 * (KSH >> 1)];
            a_h[2] = SW[qw + 4];   a_h[3] = SW[qw + 8 * (KSH >> 1) + 4];
            const int qlw = qw + (QPH >> 1);
            a_l[0] = SW[qlw];      a_l[1] = SW[qlw + 8 * (KSH >> 1)];
            a_l[2] = SW[qlw + 4];  a_l[3] = SW[qlw + 8 * (KSH >> 1) + 4];
            #pragma unroll
            for (int j = 0; j < 8; j++) {
                const int kw = (j * 8 + lr) * (KSH >> 1) + kd * 8 + lc;
                uint32_t b_h[2] = {SW[khw + kw], SW[khw + kw + 4]};
                mma_f16(sc[j], a_h, b_h);
                mma_f16(sc[j], a_l, b_h);
            }
        }

        // ---- mask ----
        if (kt + AK > kvlen_lo || kt + AK > kvlen_hi) {
            #pragma unroll
            for (int j = 0; j < 8; j++) {
                const int c0 = kt + j * 8 + 2 * lc;
                if (c0     >= kvlen_lo) sc[j][0] = -1e30f;
                if (c0 + 1 >= kvlen_lo) sc[j][1] = -1e30f;
                if (c0     >= kvlen_hi) sc[j][2] = -1e30f;
                if (c0 + 1 >= kvlen_hi) sc[j][3] = -1e30f;
            }
        }

        // ---- online softmax (warp-local rows) ----
        float mx_lo = -1e30f, mx_hi = -1e30f;
        #pragma unroll
        for (int j = 0; j < 8; j++) {
            mx_lo = fmaxf(mx_lo, fmaxf(sc[j][0], sc[j][1]));
            mx_hi = fmaxf(mx_hi, fmaxf(sc[j][2], sc[j][3]));
        }
        mx_lo = fmaxf(mx_lo, __shfl_xor_sync(0xffffffffu, mx_lo, 1));
        mx_lo = fmaxf(mx_lo, __shfl_xor_sync(0xffffffffu, mx_lo, 2));
        mx_hi = fmaxf(mx_hi, __shfl_xor_sync(0xffffffffu, mx_hi, 1));
        mx_hi = fmaxf(mx_hi, __shfl_xor_sync(0xffffffffu, mx_hi, 2));
        const float mn_lo = fmaxf(m_lo, mx_lo);
        const float mn_hi = fmaxf(m_hi, mx_hi);
        const float corr_lo = __expf(m_lo - mn_lo);
        const float corr_hi = __expf(m_hi - mn_hi);
        m_lo = mn_lo; m_hi = mn_hi;

        uint32_t ph01[8], ph23[8], pl01[8], pl23[8];
        float s_lo = 0.0f, s_hi = 0.0f;
        #pragma unroll
        for (int j = 0; j < 8; j++) {
            float p0 = __expf(sc[j][0] - mn_lo);
            float p1 = __expf(sc[j][1] - mn_lo);
            float p2 = __expf(sc[j][2] - mn_hi);
            float p3 = __expf(sc[j][3] - mn_hi);
            s_lo += p0 + p1; s_hi += p2 + p3;
            __half h0 = __float2half_rn(p0), h1 = __float2half_rn(p1);
            __half h2 = __float2half_rn(p2), h3 = __float2half_rn(p3);
            ph01[j] = pack_h2(h0, h1);
            ph23[j] = pack_h2(h2, h3);
            pl01[j] = pack_h2(__float2half_rn(p0 - __half2float(h0)),
                              __float2half_rn(p1 - __half2float(h1)));
            pl23[j] = pack_h2(__float2half_rn(p2 - __half2float(h2)),
                              __float2half_rn(p3 - __half2float(h3)));
        }
        s_lo += __shfl_xor_sync(0xffffffffu, s_lo, 1);
        s_lo += __shfl_xor_sync(0xffffffffu, s_lo, 2);
        s_hi += __shfl_xor_sync(0xffffffffu, s_hi, 1);
        s_hi += __shfl_xor_sync(0xffffffffu, s_hi, 2);
        l_lo = l_lo * corr_lo + s_lo;
        l_hi = l_hi * corr_hi + s_hi;
        #pragma unroll
        for (int f = 0; f < 16; f++) {
            oc[f][0] *= corr_lo; oc[f][1] *= corr_lo;
            oc[f][2] *= corr_hi; oc[f][3] *= corr_hi;
        }

        // ---- O += P V (2 terms) ----
        const uint32_t vh_h = 2 * QPH + (t & 1) * 2 * KVPH + KVPH;   // halves
        const int vrow = lane & 15;
        const int vcol = (lane >> 4) * 8;
        #pragma unroll
        for (int ks = 0; ks < 4; ks++) {
            uint32_t a_h[4] = {ph01[2 * ks], ph23[2 * ks],
                               ph01[2 * ks + 1], ph23[2 * ks + 1]};
            uint32_t a_l[4] = {pl01[2 * ks], pl23[2 * ks],
                               pl01[2 * ks + 1], pl23[2 * ks + 1]};
            const int vr = ks * 16 + vrow;
            #pragma unroll
            for (int jp = 0; jp < 8; jp++) {
                uint32_t r0, r1, r2, r3;
                uint32_t vaddr = sb + (vh_h + vr * KSH + jp * 16 + vcol) * 2;
                ldsm_x4_t(r0, r1, r2, r3, vaddr);
                uint32_t bh0[2] = {r0, r1}, bh1[2] = {r2, r3};
                mma_f16(oc[2 * jp],     a_h, bh0);
                mma_f16(oc[2 * jp + 1], a_h, bh1);
                mma_f16(oc[2 * jp],     a_l, bh0);
                mma_f16(oc[2 * jp + 1], a_l, bh1);
            }
        }

        __syncthreads();
        if (t + 2 < ntiles) load_kv((t + 2) * AK, t & 1);
    }
    CP_WAIT(0);

    // ---- epilogue: write fp16 hi/lo planes directly ----
    const float inv_lo = 1.0f / l_lo;
    const float inv_hi = 1.0f / l_hi;
    const size_t orow = ((size_t)(b * S_ + q0 + wm + lr)) * D_ + h * HD_;
    #pragma unroll
    for (int f = 0; f < 16; f++) {
        const int hd = f * 8 + 2 * lc;
        float v0 = oc[f][0] * inv_lo, v1 = oc[f][1] * inv_lo;
        float v2 = oc[f][2] * inv_hi, v3 = oc[f][3] * inv_hi;
        __half h0 = __float2half_rn(v0), h1 = __float2half_rn(v1);
        __half h2 = __float2half_rn(v2), h3 = __float2half_rn(v3);
        *(__half2*)(Oah + orow + hd)                = __halves2half2(h0, h1);
        *(__half2*)(Oah + orow + (size_t)8 * D_ + hd) = __halves2half2(h2, h3);
        *(__half2*)(Oal + orow + hd) = __halves2half2(
            __float2half_rn(v0 - __half2float(h0)),
            __float2half_rn(v1 - __half2float(h1)));
        *(__half2*)(Oal + orow + (size_t)8 * D_ + hd) = __halves2half2(
            __float2half_rn(v2 - __half2float(h2)),
            __float2half_rn(v3 - __half2float(h3)));
    }
}

// ---------------- kernel_launch ---------------------------------------------
extern "C" void kernel_launch(void* const* d_in, const int* in_sizes, int n_in,
                              void* d_out, int out_size)
{
    const float* hidden = (const float*)d_in[0];
    const float* rot    = (const float*)d_in[1];
    const float* Wq = (const float*)d_in[2];
    const float* bq = (const float*)d_in[3];
    const float* Wk = (const float*)d_in[4];
    const float* bk = (const float*)d_in[5];
    const float* Wv = (const float*)d_in[6];
    const float* bv = (const float*)d_in[7];
    const float* gq = (const float*)d_in[8];
    const float* gk = (const float*)d_in[9];
    const float* Wo = (const float*)d_in[10];
    const float* bo = (const float*)d_in[11];
    const int*   ctx  = (const int*)d_in[12];
    const int*   nseq = (const int*)d_in[13];
    float* out = (float*)d_out;

    float *q, *k;
    __half *xh, *xl, *ah, *al, *wh, *wl, *qh, *ql, *kh, *vh;
    cudaGetSymbolAddress((void**)&q, g_q);
    cudaGetSymbolAddress((void**)&k, g_k);
    cudaGetSymbolAddress((void**)&xh, g_xh);
    cudaGetSymbolAddress((void**)&xl, g_xl);
    cudaGetSymbolAddress((void**)&ah, g_ah);
    cudaGetSymbolAddress((void**)&al, g_al);
    cudaGetSymbolAddress((void**)&wh, g_wh);
    cudaGetSymbolAddress((void**)&wl, g_wl);
    cudaGetSymbolAddress((void**)&qh, g_qh);
    cudaGetSymbolAddress((void**)&ql, g_ql);
    cudaGetSymbolAddress((void**)&kh, g_kh);
    cudaGetSymbolAddress((void**)&vh, g_vh);

    const float WS = 1024.0f, IWS = 1.0f / 1024.0f;
    const int nX = M_ * D_, nW = D_ * D_;

    split_fp16<<<nX / 1024, 256>>>(hidden, xh, xl, nX, 1.0f);
    split_fp16<<<nW / 1024, 256>>>(Wq, wh + 0 * (size_t)nW, wl + 0 * (size_t)nW, nW, WS);
    split_fp16<<<nW / 1024, 256>>>(Wk, wh + 1 * (size_t)nW, wl + 1 * (size_t)nW, nW, WS);
    split_fp16<<<nW / 1024, 256>>>(Wv, wh + 2 * (size_t)nW, wl + 2 * (size_t)nW, nW, WS);
    split_fp16<<<nW / 1024, 256>>>(Wo, wh + 3 * (size_t)nW, wl + 3 * (size_t)nW, nW, WS);

    cudaFuncSetAttribute(gemm_f16, cudaFuncAttributeMaxDynamicSharedMemorySize,
                         GEMM_SMEM);

    const dim3 gg(D_ / 128, M_ / 128);   // (16, 48)
    gemm_f16<<<gg, 256, GEMM_SMEM>>>(xh, xl, wh + 0 * (size_t)nW, wl + 0 * (size_t)nW,
                                     bq, q, nullptr, IWS);
    gemm_f16<<<gg, 256, GEMM_SMEM>>>(xh, xl, wh + 1 * (size_t)nW, wl + 1 * (size_t)nW,
                                     bk, k, nullptr, IWS);
    gemm_f16<<<gg, 256, GEMM_SMEM>>>(xh, xl, wh + 2 * (size_t)nW, wl + 2 * (size_t)nW,
                                     bv, nullptr, vh, IWS);   // V -> fp16 directly

    rms_rope_split<<<dim3(M_, 2), 256>>>(q, k, gq, gk, rot, qh, ql, kh);

    cudaFuncSetAttribute(attn_f16, cudaFuncAttributeMaxDynamicSharedMemorySize,
                         ATT_SMEM);
    attn_f16<<<dim3(S_ / AQ, H_, B_), 256, ATT_SMEM>>>(qh, ql, kh, vh,
                                                       ah, al, ctx, nseq);

    gemm_f16<<<gg, 256, GEMM_SMEM>>>(ah, al, wh + 3 * (size_t)nW, wl + 3 * (size_t)nW,
                                     bo, out, nullptr, IWS);
}

// round 8
// speedup vs baseline: 3.3392x; 1.2031x over previous
#include <cuda_runtime.h>
#include <cuda_fp16.h>
#include <cstdint>

#define B_   2
#define S_   3072
#define D_   2048
#define H_   16
#define HD_  128
#define M_   (B_ * S_)     // 6144 tokens

// ---------------- scratch (no allocation anywhere) -------------------------
__device__ float  g_q[M_ * D_];
__device__ float  g_k[M_ * D_];
__device__ __half g_xh[M_ * D_], g_xl[M_ * D_];         // hidden hi/lo
__device__ __half g_ah[M_ * D_], g_al[M_ * D_];         // attn-out hi/lo
__device__ __half g_wh[4 * D_ * D_], g_wl[4 * D_ * D_]; // Wq,Wk,Wv,Wo hi/lo
__device__ __half g_qh[M_ * D_], g_ql[M_ * D_];
__device__ __half g_kh[M_ * D_];
__device__ __half g_vh[M_ * D_];

// ---------------- helpers ----------------------------------------------------
__device__ __forceinline__ uint32_t smem_u32(const void* p) {
    uint32_t a;
    asm("{ .reg .u64 t; cvta.to.shared.u64 t, %1; cvt.u32.u64 %0, t; }"
        : "=r"(a) : "l"(p));
    return a;
}
__device__ __forceinline__ void mma_f16(float c[4], const uint32_t a[4],
                                        const uint32_t b[2]) {
    asm volatile(
        "mma.sync.aligned.m16n8k16.row.col.f32.f16.f16.f32 "
        "{%0,%1,%2,%3}, {%4,%5,%6,%7}, {%8,%9}, {%0,%1,%2,%3};"
        : "+f"(c[0]), "+f"(c[1]), "+f"(c[2]), "+f"(c[3])
        : "r"(a[0]), "r"(a[1]), "r"(a[2]), "r"(a[3]), "r"(b[0]), "r"(b[1]));
}
__device__ __forceinline__ void ldsm_x4(uint32_t& r0, uint32_t& r1,
                                        uint32_t& r2, uint32_t& r3, uint32_t a) {
    asm volatile("ldmatrix.sync.aligned.m8n8.x4.shared.b16 {%0,%1,%2,%3}, [%4];"
                 : "=r"(r0), "=r"(r1), "=r"(r2), "=r"(r3) : "r"(a));
}
__device__ __forceinline__ void ldsm_x4_t(uint32_t& r0, uint32_t& r1,
                                          uint32_t& r2, uint32_t& r3, uint32_t a) {
    asm volatile("ldmatrix.sync.aligned.m8n8.x4.trans.shared.b16 "
                 "{%0,%1,%2,%3}, [%4];"
                 : "=r"(r0), "=r"(r1), "=r"(r2), "=r"(r3) : "r"(a));
}
__device__ __forceinline__ uint32_t pack_h2(__half a, __half b) {
    __half2 t = __halves2half2(a, b);
    return *reinterpret_cast<uint32_t*>(&t);
}
#define CP_ASYNC16(s, g) \
    asm volatile("cp.async.cg.shared.global [%0], [%1], 16;" :: "r"(s), "l"(g))
#define CP_COMMIT()  asm volatile("cp.async.commit_group;" ::: "memory")
#define CP_WAIT(n)   asm volatile("cp.async.wait_group %0;" :: "n"(n) : "memory")

// ---------------- split fp32 -> fp16 hi/lo -----------------------------------
__global__ void __launch_bounds__(256) split_fp16(
    const float* __restrict__ in, __half* __restrict__ hp, __half* __restrict__ lp,
    int n, float prescale)
{
    int i = (blockIdx.x * 256 + threadIdx.x) * 4;
    if (i >= n) return;
    float4 v = *(const float4*)(in + i);
    float x[4] = {v.x * prescale, v.y * prescale, v.z * prescale, v.w * prescale};
    __half h[4], l[4];
    #pragma unroll
    for (int j = 0; j < 4; j++) {
        h[j] = __float2half_rn(x[j]);
        l[j] = __float2half_rn(x[j] - __half2float(h[j]));
    }
    *(__half2*)(hp + i)     = __halves2half2(h[0], h[1]);
    *(__half2*)(hp + i + 2) = __halves2half2(h[2], h[3]);
    *(__half2*)(lp + i)     = __halves2half2(l[0], l[1]);
    *(__half2*)(lp + i + 2) = __halves2half2(l[2], l[3]);
}

// ---------------------------------------------------------------------------
// fp16 3-term tensor GEMM, 128x256 CTA tile, ldmatrix frags, cp.async 3-stage.
//   O[m,n] = unscale * sum_k A[m,k]*W[n,k] + bias[n]
// blockIdx.z selects weight/bias/output (fused QKV); z=2 writes fp16.
// 8 warps (2m x 4n), warp tile 64x64.
// Row stride 40 halves = 80 B: 16B-aligned for cp.async/ldmatrix,
// conflict-free for ldmatrix (banks 20r mod 32 cover all 32 banks).
// ---------------------------------------------------------------------------
#define G2_STR  40                        // halves per smem row (80 B)
#define G2_APLH (128 * G2_STR)            // 5120 halves
#define G2_BPLH (256 * G2_STR)            // 10240 halves
#define G2_STGH (2 * G2_APLH + 2 * G2_BPLH)   // 30720 halves / stage
#define GEMM2_SMEM (3 * G2_STGH * 2)      // 184320 bytes

__global__ void __launch_bounds__(256, 1) gemm_f16_n256(
    const __half* __restrict__ Ahg, const __half* __restrict__ Alg,
    const __half* __restrict__ WhB, const __half* __restrict__ WlB,
    const float* __restrict__ b0p, const float* __restrict__ b1p,
    const float* __restrict__ b2p,
    float* __restrict__ o0, float* __restrict__ o1, __half* __restrict__ o2,
    float unscale)
{
    extern __shared__ __align__(16) __half g2sm[];
    const uint32_t sb = smem_u32(g2sm);

    const int z    = blockIdx.z;
    const __half* Bhg = WhB + (size_t)z * D_ * D_;
    const __half* Blg = WlB + (size_t)z * D_ * D_;
    const float* bias = (z == 0) ? b0p : (z == 1) ? b1p : b2p;

    const int bm   = blockIdx.y * 128;
    const int bn   = blockIdx.x * 256;
    const int tid  = threadIdx.x;
    const int warp = tid >> 5;
    const int lane = tid & 31;
    const int lr   = lane >> 2;
    const int lc   = lane & 3;
    const int g    = lane >> 3;
    const int sub  = lane & 7;
    const int wm   = (warp & 1) * 64;
    const int wn   = (warp >> 1) * 64;

    // ldmatrix lane offsets (halves, plane-relative)
    int aoff[4], boff[4];
    #pragma unroll
    for (int mi = 0; mi < 4; mi++)
        aoff[mi] = (wm + mi * 16 + (g & 1) * 8 + sub) * G2_STR + (g >> 1) * 8;
    #pragma unroll
    for (int nip = 0; nip < 4; nip++)
        boff[nip] = (wn + nip * 16 + (g >> 1) * 8 + sub) * G2_STR + (g & 1) * 8;

    auto load_stage = [&](int s, int buf) {
        const int kt = s * 32;
        const uint32_t stg = buf * G2_STGH;
        #pragma unroll
        for (int i = 0; i < 12; i++) {
            const int idx = i * 256 + tid;
            uint32_t dsth;
            const __half* src;
            if (idx < 1024) {                 // A planes
                const int pl = idx >> 9, w = idx & 511;
                const int row = w >> 2, c = w & 3;
                dsth = stg + pl * G2_APLH + row * G2_STR + c * 8;
                src = (pl ? Alg : Ahg) + (size_t)(bm + row) * D_ + kt + c * 8;
            } else {                           // B planes
                const int j = idx - 1024;
                const int pl = j >> 10, w = j & 1023;
                const int row = w >> 2, c = w & 3;
                dsth = stg + 2 * G2_APLH + pl * G2_BPLH + row * G2_STR + c * 8;
                src = (pl ? Blg : Bhg) + (size_t)(bn + row) * D_ + kt + c * 8;
            }
            CP_ASYNC16(sb + dsth * 2, src);
        }
        CP_COMMIT();
    };

    float acc[4][8][4];
    #pragma unroll
    for (int mi = 0; mi < 4; mi++)
        #pragma unroll
        for (int ni = 0; ni < 8; ni++)
            #pragma unroll
            for (int r = 0; r < 4; r++) acc[mi][ni][r] = 0.0f;

    load_stage(0, 0);
    load_stage(1, 1);

    for (int s = 0; s < 64; s++) {
        CP_WAIT(1);
        __syncthreads();
        if (s + 2 < 64) load_stage(s + 2, (s + 2) % 3);

        const uint32_t stg = (s % 3) * G2_STGH;
        #pragma unroll
        for (int kk = 0; kk < 2; kk++) {
            const int kh = kk * 16;
            uint32_t ah[4][4], al[4][4];
            #pragma unroll
            for (int mi = 0; mi < 4; mi++) {
                ldsm_x4(ah[mi][0], ah[mi][1], ah[mi][2], ah[mi][3],
                        sb + (stg + aoff[mi] + kh) * 2);
                ldsm_x4(al[mi][0], al[mi][1], al[mi][2], al[mi][3],
                        sb + (stg + G2_APLH + aoff[mi] + kh) * 2);
            }
            #pragma unroll
            for (int nip = 0; nip < 4; nip++) {
                uint32_t bh[4], bl[4];
                ldsm_x4(bh[0], bh[1], bh[2], bh[3],
                        sb + (stg + 2 * G2_APLH + boff[nip] + kh) * 2);
                ldsm_x4(bl[0], bl[1], bl[2], bl[3],
                        sb + (stg + 2 * G2_APLH + G2_BPLH + boff[nip] + kh) * 2);
                uint32_t bh01[2] = {bh[0], bh[1]}, bh23[2] = {bh[2], bh[3]};
                uint32_t bl01[2] = {bl[0], bl[1]}, bl23[2] = {bl[2], bl[3]};
                #pragma unroll
                for (int mi = 0; mi < 4; mi++) {
                    mma_f16(acc[mi][2 * nip],     ah[mi], bh01);
                    mma_f16(acc[mi][2 * nip],     al[mi], bh01);
                    mma_f16(acc[mi][2 * nip],     ah[mi], bl01);
                    mma_f16(acc[mi][2 * nip + 1], ah[mi], bh23);
                    mma_f16(acc[mi][2 * nip + 1], al[mi], bh23);
                    mma_f16(acc[mi][2 * nip + 1], ah[mi], bl23);
                }
            }
        }
    }

    // epilogue
    #pragma unroll
    for (int ni = 0; ni < 8; ni++) {
        const int c = bn + wn + ni * 8 + 2 * lc;
        const float bb0 = __ldg(bias + c);
        const float bb1 = __ldg(bias + c + 1);
        #pragma unroll
        for (int mi = 0; mi < 4; mi++) {
            const int r = bm + wm + mi * 16 + lr;
            const float v00 = acc[mi][ni][0] * unscale + bb0;
            const float v01 = acc[mi][ni][1] * unscale + bb1;
            const float v10 = acc[mi][ni][2] * unscale + bb0;
            const float v11 = acc[mi][ni][3] * unscale + bb1;
            if (z == 2) {
                *(__half2*)(o2 + (size_t)r * D_ + c) =
                    __halves2half2(__float2half_rn(v00), __float2half_rn(v01));
                *(__half2*)(o2 + (size_t)(r + 8) * D_ + c) =
                    __halves2half2(__float2half_rn(v10), __float2half_rn(v11));
            } else {
                float* Of = (z == 0) ? o0 : o1;
                *(float2*)(Of + (size_t)r * D_ + c)       = float2{v00, v01};
                *(float2*)(Of + (size_t)(r + 8) * D_ + c) = float2{v10, v11};
            }
        }
    }
}

// ---------------------------------------------------------------------------
// RMSNorm + interleaved RoPE -> fp16 planes: qh+ql (q scaled 1/sqrt(HD)), kh.
// ---------------------------------------------------------------------------
__global__ void __launch_bounds__(256) rms_rope_split(
    const float* __restrict__ Tq, const float* __restrict__ Tk,
    const float* __restrict__ gq, const float* __restrict__ gk,
    const float* __restrict__ rot,
    __half* __restrict__ qh, __half* __restrict__ ql,
    __half* __restrict__ kh)
{
    const int token = blockIdx.x;
    const int s     = token % S_;
    const bool isq  = (blockIdx.y == 0);
    const float* T  = isq ? Tq : Tk;
    const float* g  = isq ? gq : gk;
    const float post = isq ? 0.08838834764831845f : 1.0f;
    const int t = threadIdx.x;

    const float* row = T + (size_t)token * D_;
    float4 v0 = *(const float4*)(row + t * 8);
    float4 v1 = *(const float4*)(row + t * 8 + 4);
    float x[8] = {v0.x, v0.y, v0.z, v0.w, v1.x, v1.y, v1.z, v1.w};

    float ss = 0.0f;
    #pragma unroll
    for (int i = 0; i < 8; i++) ss += x[i] * x[i];
    #pragma unroll
    for (int o = 16; o; o >>= 1) ss += __shfl_xor_sync(0xffffffffu, ss, o);

    __shared__ float red[8];
    __shared__ float rs_s;
    if ((t & 31) == 0) red[t >> 5] = ss;
    __syncthreads();
    if (t == 0) {
        float tot = 0.0f;
        #pragma unroll
        for (int i = 0; i < 8; i++) tot += red[i];
        rs_s = rsqrtf(tot * (1.0f / (float)D_) + 1e-6f);
    }
    __syncthreads();
    const float rs = rs_s;

    const float* rc = rot + (size_t)s * (2 * HD_);
    float out[8];
    #pragma unroll
    for (int j = 0; j < 4; j++) {
        const int d0 = t * 8 + 2 * j;
        const int i2 = d0 & (HD_ - 1);
        const float c  = rc[i2];
        const float sn = rc[HD_ + i2 + 1];
        const float x1 = x[2 * j]     * rs * g[d0];
        const float x2 = x[2 * j + 1] * rs * g[d0 + 1];
        out[2 * j]     = (x1 * c - x2 * sn) * post;
        out[2 * j + 1] = (x1 * sn + x2 * c) * post;
    }
    __half hh[8];
    #pragma unroll
    for (int j = 0; j < 8; j++) hh[j] = __float2half_rn(out[j]);

    if (isq) {
        uint32_t* hd = (uint32_t*)(qh + (size_t)token * D_ + t * 8);
        uint32_t* ld = (uint32_t*)(ql + (size_t)token * D_ + t * 8);
        #pragma unroll
        for (int j = 0; j < 4; j++) {
            __half l0 = __float2half_rn(out[2 * j]     - __half2float(hh[2 * j]));
            __half l1 = __float2half_rn(out[2 * j + 1] - __half2float(hh[2 * j + 1]));
            hd[j] = pack_h2(hh[2 * j], hh[2 * j + 1]);
            ld[j] = pack_h2(l0, l1);
        }
    } else {
        uint32_t* hd = (uint32_t*)(kh + (size_t)token * D_ + t * 8);
        #pragma unroll
        for (int j = 0; j < 4; j++) hd[j] = pack_h2(hh[2 * j], hh[2 * j + 1]);
    }
}

// ---------------------------------------------------------------------------
// fp16 tensor flash attention, 2-term QK + 2-term PV, ldmatrix frag loads.
// ---------------------------------------------------------------------------
#define AQ 128
#define AK 64
#define KSH 136                        // halves per smem row (272 B, 16-aligned)
#define QPH (128 * KSH)                // halves per Q plane
#define KVPH (64 * KSH)                // halves per KV plane
#define ATT_SMEM ((2 * QPH + 4 * KVPH) * 2)   // 139264 bytes

__global__ void __launch_bounds__(256, 1) attn_f16(
    const __half* __restrict__ Qh, const __half* __restrict__ Ql,
    const __half* __restrict__ Kh, const __half* __restrict__ Vh,
    __half* __restrict__ Oah, __half* __restrict__ Oal,
    const int* __restrict__ ctxp, const int* __restrict__ nseqp)
{
    extern __shared__ __align__(16) __half smh[];
    const uint32_t sb = smem_u32(smh);

    const int tid  = threadIdx.x;
    const int warp = tid >> 5;
    const int lane = tid & 31;
    const int lr   = lane >> 2;
    const int lc   = lane & 3;
    const int g    = lane >> 3;
    const int sub  = lane & 7;
    const int q0   = blockIdx.x * AQ;
    const int h    = blockIdx.y;
    const int b    = blockIdx.z;
    const int hist = (S_ - ctxp[0]) / nseqp[0];

    const int wm = warp * 16;
    const int q_lo = q0 + wm + lr;
    const int kvlen_lo = (q_lo < hist) ? hist : S_;
    const int kvlen_hi = (q_lo + 8 < hist) ? hist : S_;
    const int kv_end = (q0 + AQ <= hist) ? hist : S_;
    const int ntiles = (kv_end + AK - 1) / AK;

    // ldmatrix lane offsets (halves)
    const int qrow_off = (wm + (g & 1) * 8 + sub) * KSH + (g >> 1) * 8;
    const int krow_off = ((g >> 1) * 8 + sub) * KSH + (g & 1) * 8;

    // ---- stage Q (hi+lo planes) ----
    const size_t qoff = ((size_t)(b * S_ + q0)) * D_ + h * HD_;
    #pragma unroll
    for (int i = 0; i < 16; i++) {
        int idx = i * 256 + tid;
        int pl = idx >> 11, w = idx & 2047, r = w >> 4, c = w & 15;
        uint32_t dst = sb + (pl * QPH + r * KSH + c * 8) * 2;
        const __half* src = (pl ? Ql : Qh) + qoff + (size_t)r * D_ + c * 8;
        CP_ASYNC16(dst, src);
    }
    CP_COMMIT();

    const size_t kvo = ((size_t)(b * S_)) * D_ + h * HD_;
    const __half* Khp = Kh + kvo;
    const __half* Vhp = Vh + kvo;

    auto load_kv = [&](int kt, int bi) {
        const uint32_t baseh = 2 * QPH + bi * 2 * KVPH;
        #pragma unroll
        for (int i = 0; i < 8; i++) {
            int idx = i * 256 + tid;
            int pl = idx >> 10, w = idx & 1023, r = w >> 4, c = w & 15;
            const __half* s = pl ? Vhp : Khp;
            uint32_t dst = sb + (baseh + pl * KVPH + r * KSH + c * 8) * 2;
            CP_ASYNC16(dst, s + (size_t)(kt + r) * D_ + c * 8);
        }
        CP_COMMIT();
    };

    load_kv(0, 0);
    load_kv(AK, 1);

    float oc[16][4];
    #pragma unroll
    for (int f = 0; f < 16; f++)
        #pragma unroll
        for (int e = 0; e < 4; e++) oc[f][e] = 0.0f;
    float m_lo = -1e30f, m_hi = -1e30f, l_lo = 0.0f, l_hi = 0.0f;

    for (int t = 0; t < ntiles; t++) {
        const int kt = t * AK;
        if (t + 1 < ntiles) { CP_WAIT(1); } else { CP_WAIT(0); }
        __syncthreads();

        const uint32_t kbaseH = 2 * QPH + (t & 1) * 2 * KVPH;  // halves

        // ---- S = Q K^T (2 terms) ----
        float sc[8][4];
        #pragma unroll
        for (int j = 0; j < 8; j++)
            #pragma unroll
            for (int e = 0; e < 4; e++) sc[j][e] = 0.0f;

        #pragma unroll
        for (int kd = 0; kd < 8; kd++) {
            uint32_t a_h[4], a_l[4];
            ldsm_x4(a_h[0], a_h[1], a_h[2], a_h[3],
                    sb + (qrow_off + kd * 16) * 2);
            ldsm_x4(a_l[0], a_l[1], a_l[2], a_l[3],
                    sb + (QPH + qrow_off + kd * 16) * 2);
            #pragma unroll
            for (int jp = 0; jp < 4; jp++) {
                uint32_t kb[4];
                ldsm_x4(kb[0], kb[1], kb[2], kb[3],
                        sb + (kbaseH + jp * 16 * KSH + krow_off + kd * 16) * 2);
                uint32_t b01[2] = {kb[0], kb[1]}, b23[2] = {kb[2], kb[3]};
                mma_f16(sc[2 * jp],     a_h, b01);
                mma_f16(sc[2 * jp],     a_l, b01);
                mma_f16(sc[2 * jp + 1], a_h, b23);
                mma_f16(sc[2 * jp + 1], a_l, b23);
            }
        }

        // ---- mask ----
        if (kt + AK > kvlen_lo || kt + AK > kvlen_hi) {
            #pragma unroll
            for (int j = 0; j < 8; j++) {
                const int c0 = kt + j * 8 + 2 * lc;
                if (c0     >= kvlen_lo) sc[j][0] = -1e30f;
                if (c0 + 1 >= kvlen_lo) sc[j][1] = -1e30f;
                if (c0     >= kvlen_hi) sc[j][2] = -1e30f;
                if (c0 + 1 >= kvlen_hi) sc[j][3] = -1e30f;
            }
        }

        // ---- online softmax (warp-local rows) ----
        float mx_lo = -1e30f, mx_hi = -1e30f;
        #pragma unroll
        for (int j = 0; j < 8; j++) {
            mx_lo = fmaxf(mx_lo, fmaxf(sc[j][0], sc[j][1]));
            mx_hi = fmaxf(mx_hi, fmaxf(sc[j][2], sc[j][3]));
        }
        mx_lo = fmaxf(mx_lo, __shfl_xor_sync(0xffffffffu, mx_lo, 1));
        mx_lo = fmaxf(mx_lo, __shfl_xor_sync(0xffffffffu, mx_lo, 2));
        mx_hi = fmaxf(mx_hi, __shfl_xor_sync(0xffffffffu, mx_hi, 1));
        mx_hi = fmaxf(mx_hi, __shfl_xor_sync(0xffffffffu, mx_hi, 2));
        const float mn_lo = fmaxf(m_lo, mx_lo);
        const float mn_hi = fmaxf(m_hi, mx_hi);
        const float corr_lo = __expf(m_lo - mn_lo);
        const float corr_hi = __expf(m_hi - mn_hi);
        m_lo = mn_lo; m_hi = mn_hi;

        uint32_t ph01[8], ph23[8], pl01[8], pl23[8];
        float s_lo = 0.0f, s_hi = 0.0f;
        #pragma unroll
        for (int j = 0; j < 8; j++) {
            float p0 = __expf(sc[j][0] - mn_lo);
            float p1 = __expf(sc[j][1] - mn_lo);
            float p2 = __expf(sc[j][2] - mn_hi);
            float p3 = __expf(sc[j][3] - mn_hi);
            s_lo += p0 + p1; s_hi += p2 + p3;
            __half h0 = __float2half_rn(p0), h1 = __float2half_rn(p1);
            __half h2 = __float2half_rn(p2), h3 = __float2half_rn(p3);
            ph01[j] = pack_h2(h0, h1);
            ph23[j] = pack_h2(h2, h3);
            pl01[j] = pack_h2(__float2half_rn(p0 - __half2float(h0)),
                              __float2half_rn(p1 - __half2float(h1)));
            pl23[j] = pack_h2(__float2half_rn(p2 - __half2float(h2)),
                              __float2half_rn(p3 - __half2float(h3)));
        }
        s_lo += __shfl_xor_sync(0xffffffffu, s_lo, 1);
        s_lo += __shfl_xor_sync(0xffffffffu, s_lo, 2);
        s_hi += __shfl_xor_sync(0xffffffffu, s_hi, 1);
        s_hi += __shfl_xor_sync(0xffffffffu, s_hi, 2);
        l_lo = l_lo * corr_lo + s_lo;
        l_hi = l_hi * corr_hi + s_hi;
        #pragma unroll
        for (int f = 0; f < 16; f++) {
            oc[f][0] *= corr_lo; oc[f][1] *= corr_lo;
            oc[f][2] *= corr_hi; oc[f][3] *= corr_hi;
        }

        // ---- O += P V (2 terms) ----
        const uint32_t vh_h = 2 * QPH + (t & 1) * 2 * KVPH + KVPH;   // halves
        const int vrow = lane & 15;
        const int vcol = (lane >> 4) * 8;
        #pragma unroll
        for (int ks = 0; ks < 4; ks++) {
            uint32_t a_h[4] = {ph01[2 * ks], ph23[2 * ks],
                               ph01[2 * ks + 1], ph23[2 * ks + 1]};
            uint32_t a_l[4] = {pl01[2 * ks], pl23[2 * ks],
                               pl01[2 * ks + 1], pl23[2 * ks + 1]};
            const int vr = ks * 16 + vrow;
            #pragma unroll
            for (int jp = 0; jp < 8; jp++) {
                uint32_t r0, r1, r2, r3;
                uint32_t vaddr = sb + (vh_h + vr * KSH + jp * 16 + vcol) * 2;
                ldsm_x4_t(r0, r1, r2, r3, vaddr);
                uint32_t bh0[2] = {r0, r1}, bh1[2] = {r2, r3};
                mma_f16(oc[2 * jp],     a_h, bh0);
                mma_f16(oc[2 * jp + 1], a_h, bh1);
                mma_f16(oc[2 * jp],     a_l, bh0);
                mma_f16(oc[2 * jp + 1], a_l, bh1);
            }
        }

        __syncthreads();
        if (t + 2 < ntiles) load_kv((t + 2) * AK, t & 1);
    }
    CP_WAIT(0);

    // ---- epilogue: write fp16 hi/lo planes directly ----
    const float inv_lo = 1.0f / l_lo;
    const float inv_hi = 1.0f / l_hi;
    const size_t orow = ((size_t)(b * S_ + q0 + wm + lr)) * D_ + h * HD_;
    #pragma unroll
    for (int f = 0; f < 16; f++) {
        const int hd = f * 8 + 2 * lc;
        float v0 = oc[f][0] * inv_lo, v1 = oc[f][1] * inv_lo;
        float v2 = oc[f][2] * inv_hi, v3 = oc[f][3] * inv_hi;
        __half h0 = __float2half_rn(v0), h1 = __float2half_rn(v1);
        __half h2 = __float2half_rn(v2), h3 = __float2half_rn(v3);
        *(__half2*)(Oah + orow + hd)                  = __halves2half2(h0, h1);
        *(__half2*)(Oah + orow + (size_t)8 * D_ + hd) = __halves2half2(h2, h3);
        *(__half2*)(Oal + orow + hd) = __halves2half2(
            __float2half_rn(v0 - __half2float(h0)),
            __float2half_rn(v1 - __half2float(h1)));
        *(__half2*)(Oal + orow + (size_t)8 * D_ + hd) = __halves2half2(
            __float2half_rn(v2 - __half2float(h2)),
            __float2half_rn(v3 - __half2float(h3)));
    }
}

// ---------------- kernel_launch ---------------------------------------------
extern "C" void kernel_launch(void* const* d_in, const int* in_sizes, int n_in,
                              void* d_out, int out_size)
{
    const float* hidden = (const float*)d_in[0];
    const float* rot    = (const float*)d_in[1];
    const float* Wq = (const float*)d_in[2];
    const float* bq = (const float*)d_in[3];
    const float* Wk = (const float*)d_in[4];
    const float* bk = (const float*)d_in[5];
    const float* Wv = (const float*)d_in[6];
    const float* bv = (const float*)d_in[7];
    const float* gq = (const float*)d_in[8];
    const float* gk = (const float*)d_in[9];
    const float* Wo = (const float*)d_in[10];
    const float* bo = (const float*)d_in[11];
    const int*   ctx  = (const int*)d_in[12];
    const int*   nseq = (const int*)d_in[13];
    float* out = (float*)d_out;

    float *q, *k;
    __half *xh, *xl, *ah, *al, *wh, *wl, *qh, *ql, *kh, *vh;
    cudaGetSymbolAddress((void**)&q, g_q);
    cudaGetSymbolAddress((void**)&k, g_k);
    cudaGetSymbolAddress((void**)&xh, g_xh);
    cudaGetSymbolAddress((void**)&xl, g_xl);
    cudaGetSymbolAddress((void**)&ah, g_ah);
    cudaGetSymbolAddress((void**)&al, g_al);
    cudaGetSymbolAddress((void**)&wh, g_wh);
    cudaGetSymbolAddress((void**)&wl, g_wl);
    cudaGetSymbolAddress((void**)&qh, g_qh);
    cudaGetSymbolAddress((void**)&ql, g_ql);
    cudaGetSymbolAddress((void**)&kh, g_kh);
    cudaGetSymbolAddress((void**)&vh, g_vh);

    const float WS = 1024.0f, IWS = 1.0f / 1024.0f;
    const int nX = M_ * D_, nW = D_ * D_;

    split_fp16<<<nX / 1024, 256>>>(hidden, xh, xl, nX, 1.0f);
    split_fp16<<<nW / 1024, 256>>>(Wq, wh + 0 * (size_t)nW, wl + 0 * (size_t)nW, nW, WS);
    split_fp16<<<nW / 1024, 256>>>(Wk, wh + 1 * (size_t)nW, wl + 1 * (size_t)nW, nW, WS);
    split_fp16<<<nW / 1024, 256>>>(Wv, wh + 2 * (size_t)nW, wl + 2 * (size_t)nW, nW, WS);
    split_fp16<<<nW / 1024, 256>>>(Wo, wh + 3 * (size_t)nW, wl + 3 * (size_t)nW, nW, WS);

    cudaFuncSetAttribute(gemm_f16_n256, cudaFuncAttributeMaxDynamicSharedMemorySize,
                         GEMM2_SMEM);

    // Fused QKV projections: z = 0 -> q (f32), 1 -> k (f32), 2 -> v (fp16)
    gemm_f16_n256<<<dim3(D_ / 256, M_ / 128, 3), 256, GEMM2_SMEM>>>(
        xh, xl, wh, wl, bq, bk, bv, q, k, vh, IWS);

    rms_rope_split<<<dim3(M_, 2), 256>>>(q, k, gq, gk, rot, qh, ql, kh);

    cudaFuncSetAttribute(attn_f16, cudaFuncAttributeMaxDynamicSharedMemorySize,
                         ATT_SMEM);
    attn_f16<<<dim3(S_ / AQ, H_, B_), 256, ATT_SMEM>>>(qh, ql, kh, vh,
                                                       ah, al, ctx, nseq);

    // Output projection (z = 0 path -> float out)
    gemm_f16_n256<<<dim3(D_ / 256, M_ / 128, 1), 256, GEMM2_SMEM>>>(
        ah, al, wh + 3 * (size_t)nW, wl + 3 * (size_t)nW,
        bo, bo, bo, out, nullptr, nullptr, IWS);
}

// round 9
// speedup vs baseline: 4.2418x; 1.2703x over previous
#include <cuda_runtime.h>
#include <cuda_fp16.h>
#include <cstdint>

#define B_   2
#define S_   3072
#define D_   2048
#define H_   16
#define HD_  128
#define M_   (B_ * S_)     // 6144 tokens

// ---------------- scratch (no allocation anywhere) -------------------------
__device__ float  g_q[M_ * D_];
__device__ float  g_k[M_ * D_];
__device__ __half g_xh[M_ * D_], g_xl[M_ * D_];         // hidden hi/lo
__device__ __half g_ah[M_ * D_], g_al[M_ * D_];         // attn-out hi/lo
__device__ __half g_wh[4 * D_ * D_];                    // Wq,Wk,Wv,Wo fp16
__device__ __half g_qh[M_ * D_], g_ql[M_ * D_];
__device__ __half g_kh[M_ * D_];
__device__ __half g_vh[M_ * D_];

// ---------------- helpers ----------------------------------------------------
__device__ __forceinline__ uint32_t smem_u32(const void* p) {
    uint32_t a;
    asm("{ .reg .u64 t; cvta.to.shared.u64 t, %1; cvt.u32.u64 %0, t; }"
        : "=r"(a) : "l"(p));
    return a;
}
__device__ __forceinline__ void mma_f16(float c[4], const uint32_t a[4],
                                        const uint32_t b[2]) {
    asm volatile(
        "mma.sync.aligned.m16n8k16.row.col.f32.f16.f16.f32 "
        "{%0,%1,%2,%3}, {%4,%5,%6,%7}, {%8,%9}, {%0,%1,%2,%3};"
        : "+f"(c[0]), "+f"(c[1]), "+f"(c[2]), "+f"(c[3])
        : "r"(a[0]), "r"(a[1]), "r"(a[2]), "r"(a[3]), "r"(b[0]), "r"(b[1]));
}
__device__ __forceinline__ void ldsm_x4(uint32_t& r0, uint32_t& r1,
                                        uint32_t& r2, uint32_t& r3, uint32_t a) {
    asm volatile("ldmatrix.sync.aligned.m8n8.x4.shared.b16 {%0,%1,%2,%3}, [%4];"
                 : "=r"(r0), "=r"(r1), "=r"(r2), "=r"(r3) : "r"(a));
}
__device__ __forceinline__ void ldsm_x4_t(uint32_t& r0, uint32_t& r1,
                                          uint32_t& r2, uint32_t& r3, uint32_t a) {
    asm volatile("ldmatrix.sync.aligned.m8n8.x4.trans.shared.b16 "
                 "{%0,%1,%2,%3}, [%4];"
                 : "=r"(r0), "=r"(r1), "=r"(r2), "=r"(r3) : "r"(a));
}
__device__ __forceinline__ uint32_t pack_h2(__half a, __half b) {
    __half2 t = __halves2half2(a, b);
    return *reinterpret_cast<uint32_t*>(&t);
}
__device__ __forceinline__ uint32_t pack_f2(float a, float b) {
    __half2 t = __floats2half2_rn(a, b);
    return *reinterpret_cast<uint32_t*>(&t);
}
#define CP_ASYNC16(s, g) \
    asm volatile("cp.async.cg.shared.global [%0], [%1], 16;" :: "r"(s), "l"(g))
#define CP_COMMIT()  asm volatile("cp.async.commit_group;" ::: "memory")
#define CP_WAIT(n)   asm volatile("cp.async.wait_group %0;" :: "n"(n) : "memory")

// ---------------- split fp32 -> fp16 hi/lo -----------------------------------
__global__ void __launch_bounds__(256) split_fp16(
    const float* __restrict__ in, __half* __restrict__ hp, __half* __restrict__ lp,
    int n)
{
    int i = (blockIdx.x * 256 + threadIdx.x) * 4;
    if (i >= n) return;
    float4 v = *(const float4*)(in + i);
    float x[4] = {v.x, v.y, v.z, v.w};
    __half h[4];
    float  r[4];
    #pragma unroll
    for (int j = 0; j < 4; j++) {
        h[j] = __float2half_rn(x[j]);
        r[j] = x[j] - __half2float(h[j]);
    }
    *(uint32_t*)(hp + i)     = pack_h2(h[0], h[1]);
    *(uint32_t*)(hp + i + 2) = pack_h2(h[2], h[3]);
    *(uint32_t*)(lp + i)     = pack_f2(r[0], r[1]);
    *(uint32_t*)(lp + i + 2) = pack_f2(r[2], r[3]);
}

// ---------------- convert fp32 -> fp16 (single plane, for weights) ----------
__global__ void __launch_bounds__(256) cvt_f16(
    const float* __restrict__ in, __half* __restrict__ out, int n)
{
    int i = (blockIdx.x * 256 + threadIdx.x) * 4;
    if (i >= n) return;
    float4 v = *(const float4*)(in + i);
    *(uint32_t*)(out + i)     = pack_f2(v.x, v.y);
    *(uint32_t*)(out + i + 2) = pack_f2(v.z, v.w);
}

// ---------------------------------------------------------------------------
// fp16 2-term tensor GEMM: O[m,n] = sum_k (Ah+Al)[m,k] * W16[n,k] + bias[n]
// A split hi/lo fp16; W single fp16 plane.  128x256 CTA tile, ldmatrix frags,
// cp.async 3-stage.  blockIdx.z selects weight/bias/output (fused QKV);
// z=2 writes fp16.  8 warps (2m x 4n), warp tile 64x64.
// Row stride 40 halves = 80 B: 16B-aligned, ldmatrix conflict-free.
// ---------------------------------------------------------------------------
#define G2_STR  40                        // halves per smem row (80 B)
#define G2_APLH (128 * G2_STR)            // 5120 halves
#define G2_BPLH (256 * G2_STR)            // 10240 halves
#define G2_STGH (2 * G2_APLH + G2_BPLH)   // 20480 halves / stage
#define GEMM2_SMEM (3 * G2_STGH * 2)      // 122880 bytes

__global__ void __launch_bounds__(256, 1) gemm_f16_n256(
    const __half* __restrict__ Ahg, const __half* __restrict__ Alg,
    const __half* __restrict__ WhB,
    const float* __restrict__ b0p, const float* __restrict__ b1p,
    const float* __restrict__ b2p,
    float* __restrict__ o0, float* __restrict__ o1, __half* __restrict__ o2)
{
    extern __shared__ __align__(16) __half g2sm[];
    const uint32_t sb = smem_u32(g2sm);

    const int z    = blockIdx.z;
    const __half* Bhg = WhB + (size_t)z * D_ * D_;
    const float* bias = (z == 0) ? b0p : (z == 1) ? b1p : b2p;

    const int bm   = blockIdx.y * 128;
    const int bn   = blockIdx.x * 256;
    const int tid  = threadIdx.x;
    const int warp = tid >> 5;
    const int lane = tid & 31;
    const int lr   = lane >> 2;
    const int lc   = lane & 3;
    const int g    = lane >> 3;
    const int sub  = lane & 7;
    const int wm   = (warp & 1) * 64;
    const int wn   = (warp >> 1) * 64;

    // ldmatrix lane offsets (halves, plane-relative)
    int aoff[4], boff[4];
    #pragma unroll
    for (int mi = 0; mi < 4; mi++)
        aoff[mi] = (wm + mi * 16 + (g & 1) * 8 + sub) * G2_STR + (g >> 1) * 8;
    #pragma unroll
    for (int nip = 0; nip < 4; nip++)
        boff[nip] = (wn + nip * 16 + (g >> 1) * 8 + sub) * G2_STR + (g & 1) * 8;

    auto load_stage = [&](int s, int buf) {
        const int kt = s * 32;
        const uint32_t stg = buf * G2_STGH;
        #pragma unroll
        for (int i = 0; i < 8; i++) {
            const int idx = i * 256 + tid;        // 0..2047
            uint32_t dsth;
            const __half* src;
            if (idx < 1024) {                     // A planes (hi, lo)
                const int pl = idx >> 9, w = idx & 511;
                const int row = w >> 2, c = w & 3;
                dsth = stg + pl * G2_APLH + row * G2_STR + c * 8;
                src = (pl ? Alg : Ahg) + (size_t)(bm + row) * D_ + kt + c * 8;
            } else {                               // W plane
                const int j = idx - 1024;
                const int row = j >> 2, c = j & 3;
                dsth = stg + 2 * G2_APLH + row * G2_STR + c * 8;
                src = Bhg + (size_t)(bn + row) * D_ + kt + c * 8;
            }
            CP_ASYNC16(sb + dsth * 2, src);
        }
        CP_COMMIT();
    };

    float acc[4][8][4];
    #pragma unroll
    for (int mi = 0; mi < 4; mi++)
        #pragma unroll
        for (int ni = 0; ni < 8; ni++)
            #pragma unroll
            for (int r = 0; r < 4; r++) acc[mi][ni][r] = 0.0f;

    load_stage(0, 0);
    load_stage(1, 1);

    for (int s = 0; s < 64; s++) {
        CP_WAIT(1);
        __syncthreads();
        if (s + 2 < 64) load_stage(s + 2, (s + 2) % 3);

        const uint32_t stg = (s % 3) * G2_STGH;
        #pragma unroll
        for (int kk = 0; kk < 2; kk++) {
            const int kh = kk * 16;
            uint32_t ah[4][4], al[4][4];
            #pragma unroll
            for (int mi = 0; mi < 4; mi++) {
                ldsm_x4(ah[mi][0], ah[mi][1], ah[mi][2], ah[mi][3],
                        sb + (stg + aoff[mi] + kh) * 2);
                ldsm_x4(al[mi][0], al[mi][1], al[mi][2], al[mi][3],
                        sb + (stg + G2_APLH + aoff[mi] + kh) * 2);
            }
            #pragma unroll
            for (int nip = 0; nip < 4; nip++) {
                uint32_t bh[4];
                ldsm_x4(bh[0], bh[1], bh[2], bh[3],
                        sb + (stg + 2 * G2_APLH + boff[nip] + kh) * 2);
                uint32_t bh01[2] = {bh[0], bh[1]}, bh23[2] = {bh[2], bh[3]};
                #pragma unroll
                for (int mi = 0; mi < 4; mi++) {
                    mma_f16(acc[mi][2 * nip],     ah[mi], bh01);
                    mma_f16(acc[mi][2 * nip],     al[mi], bh01);
                    mma_f16(acc[mi][2 * nip + 1], ah[mi], bh23);
                    mma_f16(acc[mi][2 * nip + 1], al[mi], bh23);
                }
            }
        }
    }

    // epilogue
    #pragma unroll
    for (int ni = 0; ni < 8; ni++) {
        const int c = bn + wn + ni * 8 + 2 * lc;
        const float bb0 = __ldg(bias + c);
        const float bb1 = __ldg(bias + c + 1);
        #pragma unroll
        for (int mi = 0; mi < 4; mi++) {
            const int r = bm + wm + mi * 16 + lr;
            const float v00 = acc[mi][ni][0] + bb0;
            const float v01 = acc[mi][ni][1] + bb1;
            const float v10 = acc[mi][ni][2] + bb0;
            const float v11 = acc[mi][ni][3] + bb1;
            if (z == 2) {
                *(uint32_t*)(o2 + (size_t)r * D_ + c)       = pack_f2(v00, v01);
                *(uint32_t*)(o2 + (size_t)(r + 8) * D_ + c) = pack_f2(v10, v11);
            } else {
                float* Of = (z == 0) ? o0 : o1;
                *(float2*)(Of + (size_t)r * D_ + c)       = float2{v00, v01};
                *(float2*)(Of + (size_t)(r + 8) * D_ + c) = float2{v10, v11};
            }
        }
    }
}

// ---------------------------------------------------------------------------
// RMSNorm + interleaved RoPE -> fp16 planes: qh+ql (q scaled 1/sqrt(HD)), kh.
// ---------------------------------------------------------------------------
__global__ void __launch_bounds__(256) rms_rope_split(
    const float* __restrict__ Tq, const float* __restrict__ Tk,
    const float* __restrict__ gq, const float* __restrict__ gk,
    const float* __restrict__ rot,
    __half* __restrict__ qh, __half* __restrict__ ql,
    __half* __restrict__ kh)
{
    const int token = blockIdx.x;
    const int s     = token % S_;
    const bool isq  = (blockIdx.y == 0);
    const float* T  = isq ? Tq : Tk;
    const float* g  = isq ? gq : gk;
    const float post = isq ? 0.08838834764831845f : 1.0f;
    const int t = threadIdx.x;

    const float* row = T + (size_t)token * D_;
    float4 v0 = *(const float4*)(row + t * 8);
    float4 v1 = *(const float4*)(row + t * 8 + 4);
    float x[8] = {v0.x, v0.y, v0.z, v0.w, v1.x, v1.y, v1.z, v1.w};

    float ss = 0.0f;
    #pragma unroll
    for (int i = 0; i < 8; i++) ss += x[i] * x[i];
    #pragma unroll
    for (int o = 16; o; o >>= 1) ss += __shfl_xor_sync(0xffffffffu, ss, o);

    __shared__ float red[8];
    __shared__ float rs_s;
    if ((t & 31) == 0) red[t >> 5] = ss;
    __syncthreads();
    if (t == 0) {
        float tot = 0.0f;
        #pragma unroll
        for (int i = 0; i < 8; i++) tot += red[i];
        rs_s = rsqrtf(tot * (1.0f / (float)D_) + 1e-6f);
    }
    __syncthreads();
    const float rs = rs_s;

    const float* rc = rot + (size_t)s * (2 * HD_);
    float out[8];
    #pragma unroll
    for (int j = 0; j < 4; j++) {
        const int d0 = t * 8 + 2 * j;
        const int i2 = d0 & (HD_ - 1);
        const float c  = rc[i2];
        const float sn = rc[HD_ + i2 + 1];
        const float x1 = x[2 * j]     * rs * g[d0];
        const float x2 = x[2 * j + 1] * rs * g[d0 + 1];
        out[2 * j]     = (x1 * c - x2 * sn) * post;
        out[2 * j + 1] = (x1 * sn + x2 * c) * post;
    }

    if (isq) {
        uint32_t* hd = (uint32_t*)(qh + (size_t)token * D_ + t * 8);
        uint32_t* ld = (uint32_t*)(ql + (size_t)token * D_ + t * 8);
        #pragma unroll
        for (int j = 0; j < 4; j++) {
            __half h0 = __float2half_rn(out[2 * j]);
            __half h1 = __float2half_rn(out[2 * j + 1]);
            hd[j] = pack_h2(h0, h1);
            ld[j] = pack_f2(out[2 * j]     - __half2float(h0),
                            out[2 * j + 1] - __half2float(h1));
        }
    } else {
        uint32_t* hd = (uint32_t*)(kh + (size_t)token * D_ + t * 8);
        #pragma unroll
        for (int j = 0; j < 4; j++)
            hd[j] = pack_f2(out[2 * j], out[2 * j + 1]);
    }
}

// ---------------------------------------------------------------------------
// fp16 tensor flash attention, 2-term QK + 2-term PV, ldmatrix frag loads.
// ---------------------------------------------------------------------------
#define AQ 128
#define AK 64
#define KSH 136                        // halves per smem row (272 B, 16-aligned)
#define QPH (128 * KSH)                // halves per Q plane
#define KVPH (64 * KSH)                // halves per KV plane
#define ATT_SMEM ((2 * QPH + 4 * KVPH) * 2)   // 139264 bytes

__global__ void __launch_bounds__(256, 1) attn_f16(
    const __half* __restrict__ Qh, const __half* __restrict__ Ql,
    const __half* __restrict__ Kh, const __half* __restrict__ Vh,
    __half* __restrict__ Oah, __half* __restrict__ Oal,
    const int* __restrict__ ctxp, const int* __restrict__ nseqp)
{
    extern __shared__ __align__(16) __half smh[];
    const uint32_t sb = smem_u32(smh);

    const int tid  = threadIdx.x;
    const int warp = tid >> 5;
    const int lane = tid & 31;
    const int lr   = lane >> 2;
    const int lc   = lane & 3;
    const int g    = lane >> 3;
    const int sub  = lane & 7;
    const int q0   = blockIdx.x * AQ;
    const int h    = blockIdx.y;
    const int b    = blockIdx.z;
    const int hist = (S_ - ctxp[0]) / nseqp[0];

    const int wm = warp * 16;
    const int q_lo = q0 + wm + lr;
    const int kvlen_lo = (q_lo < hist) ? hist : S_;
    const int kvlen_hi = (q_lo + 8 < hist) ? hist : S_;
    const int kv_end = (q0 + AQ <= hist) ? hist : S_;
    const int ntiles = (kv_end + AK - 1) / AK;

    // ldmatrix lane offsets (halves)
    const int qrow_off = (wm + (g & 1) * 8 + sub) * KSH + (g >> 1) * 8;
    const int krow_off = ((g >> 1) * 8 + sub) * KSH + (g & 1) * 8;

    // ---- stage Q (hi+lo planes) ----
    const size_t qoff = ((size_t)(b * S_ + q0)) * D_ + h * HD_;
    #pragma unroll
    for (int i = 0; i < 16; i++) {
        int idx = i * 256 + tid;
        int pl = idx >> 11, w = idx & 2047, r = w >> 4, c = w & 15;
        uint32_t dst = sb + (pl * QPH + r * KSH + c * 8) * 2;
        const __half* src = (pl ? Ql : Qh) + qoff + (size_t)r * D_ + c * 8;
        CP_ASYNC16(dst, src);
    }
    CP_COMMIT();

    const size_t kvo = ((size_t)(b * S_)) * D_ + h * HD_;
    const __half* Khp = Kh + kvo;
    const __half* Vhp = Vh + kvo;

    auto load_kv = [&](int kt, int bi) {
        const uint32_t baseh = 2 * QPH + bi * 2 * KVPH;
        #pragma unroll
        for (int i = 0; i < 8; i++) {
            int idx = i * 256 + tid;
            int pl = idx >> 10, w = idx & 1023, r = w >> 4, c = w & 15;
            const __half* s = pl ? Vhp : Khp;
            uint32_t dst = sb + (baseh + pl * KVPH + r * KSH + c * 8) * 2;
            CP_ASYNC16(dst, s + (size_t)(kt + r) * D_ + c * 8);
        }
        CP_COMMIT();
    };

    load_kv(0, 0);
    load_kv(AK, 1);

    float oc[16][4];
    #pragma unroll
    for (int f = 0; f < 16; f++)
        #pragma unroll
        for (int e = 0; e < 4; e++) oc[f][e] = 0.0f;
    float m_lo = -1e30f, m_hi = -1e30f, l_lo = 0.0f, l_hi = 0.0f;

    for (int t = 0; t < ntiles; t++) {
        const int kt = t * AK;
        if (t + 1 < ntiles) { CP_WAIT(1); } else { CP_WAIT(0); }
        __syncthreads();

        const uint32_t kbaseH = 2 * QPH + (t & 1) * 2 * KVPH;  // halves

        // ---- S = Q K^T (2 terms) ----
        float sc[8][4];
        #pragma unroll
        for (int j = 0; j < 8; j++)
            #pragma unroll
            for (int e = 0; e < 4; e++) sc[j][e] = 0.0f;

        #pragma unroll
        for (int kd = 0; kd < 8; kd++) {
            uint32_t a_h[4], a_l[4];
            ldsm_x4(a_h[0], a_h[1], a_h[2], a_h[3],
                    sb + (qrow_off + kd * 16) * 2);
            ldsm_x4(a_l[0], a_l[1], a_l[2], a_l[3],
                    sb + (QPH + qrow_off + kd * 16) * 2);
            #pragma unroll
            for (int jp = 0; jp < 4; jp++) {
                uint32_t kb[4];
                ldsm_x4(kb[0], kb[1], kb[2], kb[3],
                        sb + (kbaseH + jp * 16 * KSH + krow_off + kd * 16) * 2);
                uint32_t b01[2] = {kb[0], kb[1]}, b23[2] = {kb[2], kb[3]};
                mma_f16(sc[2 * jp],     a_h, b01);
                mma_f16(sc[2 * jp],     a_l, b01);
                mma_f16(sc[2 * jp + 1], a_h, b23);
                mma_f16(sc[2 * jp + 1], a_l, b23);
            }
        }

        // ---- mask ----
        if (kt + AK > kvlen_lo || kt + AK > kvlen_hi) {
            #pragma unroll
            for (int j = 0; j < 8; j++) {
                const int c0 = kt + j * 8 + 2 * lc;
                if (c0     >= kvlen_lo) sc[j][0] = -1e30f;
                if (c0 + 1 >= kvlen_lo) sc[j][1] = -1e30f;
                if (c0     >= kvlen_hi) sc[j][2] = -1e30f;
                if (c0 + 1 >= kvlen_hi) sc[j][3] = -1e30f;
            }
        }

        // ---- online softmax (warp-local rows) ----
        float mx_lo = -1e30f, mx_hi = -1e30f;
        #pragma unroll
        for (int j = 0; j < 8; j++) {
            mx_lo = fmaxf(mx_lo, fmaxf(sc[j][0], sc[j][1]));
            mx_hi = fmaxf(mx_hi, fmaxf(sc[j][2], sc[j][3]));
        }
        mx_lo = fmaxf(mx_lo, __shfl_xor_sync(0xffffffffu, mx_lo, 1));
        mx_lo = fmaxf(mx_lo, __shfl_xor_sync(0xffffffffu, mx_lo, 2));
        mx_hi = fmaxf(mx_hi, __shfl_xor_sync(0xffffffffu, mx_hi, 1));
        mx_hi = fmaxf(mx_hi, __shfl_xor_sync(0xffffffffu, mx_hi, 2));
        const float mn_lo = fmaxf(m_lo, mx_lo);
        const float mn_hi = fmaxf(m_hi, mx_hi);
        const float corr_lo = __expf(m_lo - mn_lo);
        const float corr_hi = __expf(m_hi - mn_hi);
        m_lo = mn_lo; m_hi = mn_hi;

        uint32_t ph01[8], ph23[8], pl01[8], pl23[8];
        float s_lo = 0.0f, s_hi = 0.0f;
        #pragma unroll
        for (int j = 0; j < 8; j++) {
            float p0 = __expf(sc[j][0] - mn_lo);
            float p1 = __expf(sc[j][1] - mn_lo);
            float p2 = __expf(sc[j][2] - mn_hi);
            float p3 = __expf(sc[j][3] - mn_hi);
            s_lo += p0 + p1; s_hi += p2 + p3;
            __half2 h01 = __floats2half2_rn(p0, p1);
            __half2 h23 = __floats2half2_rn(p2, p3);
            ph01[j] = *reinterpret_cast<uint32_t*>(&h01);
            ph23[j] = *reinterpret_cast<uint32_t*>(&h23);
            pl01[j] = pack_f2(p0 - __low2float(h01), p1 - __high2float(h01));
            pl23[j] = pack_f2(p2 - __low2float(h23), p3 - __high2float(h23));
        }
        s_lo += __shfl_xor_sync(0xffffffffu, s_lo, 1);
        s_lo += __shfl_xor_sync(0xffffffffu, s_lo, 2);
        s_hi += __shfl_xor_sync(0xffffffffu, s_hi, 1);
        s_hi += __shfl_xor_sync(0xffffffffu, s_hi, 2);
        l_lo = l_lo * corr_lo + s_lo;
        l_hi = l_hi * corr_hi + s_hi;
        #pragma unroll
        for (int f = 0; f < 16; f++) {
            oc[f][0] *= corr_lo; oc[f][1] *= corr_lo;
            oc[f][2] *= corr_hi; oc[f][3] *= corr_hi;
        }

        // ---- O += P V (2 terms) ----
        const uint32_t vh_h = 2 * QPH + (t & 1) * 2 * KVPH + KVPH;   // halves
        const int vrow = lane & 15;
        const int vcol = (lane >> 4) * 8;
        #pragma unroll
        for (int ks = 0; ks < 4; ks++) {
            uint32_t a_h[4] = {ph01[2 * ks], ph23[2 * ks],
                               ph01[2 * ks + 1], ph23[2 * ks + 1]};
            uint32_t a_l[4] = {pl01[2 * ks], pl23[2 * ks],
                               pl01[2 * ks + 1], pl23[2 * ks + 1]};
            const int vr = ks * 16 + vrow;
            #pragma unroll
            for (int jp = 0; jp < 8; jp++) {
                uint32_t r0, r1, r2, r3;
                uint32_t vaddr = sb + (vh_h + vr * KSH + jp * 16 + vcol) * 2;
                ldsm_x4_t(r0, r1, r2, r3, vaddr);
                uint32_t bh0[2] = {r0, r1}, bh1[2] = {r2, r3};
                mma_f16(oc[2 * jp],     a_h, bh0);
                mma_f16(oc[2 * jp + 1], a_h, bh1);
                mma_f16(oc[2 * jp],     a_l, bh0);
                mma_f16(oc[2 * jp + 1], a_l, bh1);
            }
        }

        __syncthreads();
        if (t + 2 < ntiles) load_kv((t + 2) * AK, t & 1);
    }
    CP_WAIT(0);

    // ---- epilogue: write fp16 hi/lo planes directly ----
    const float inv_lo = 1.0f / l_lo;
    const float inv_hi = 1.0f / l_hi;
    const size_t orow = ((size_t)(b * S_ + q0 + wm + lr)) * D_ + h * HD_;
    #pragma unroll
    for (int f = 0; f < 16; f++) {
        const int hd = f * 8 + 2 * lc;
        float v0 = oc[f][0] * inv_lo, v1 = oc[f][1] * inv_lo;
        float v2 = oc[f][2] * inv_hi, v3 = oc[f][3] * inv_hi;
        __half2 h01 = __floats2half2_rn(v0, v1);
        __half2 h23 = __floats2half2_rn(v2, v3);
        *(uint32_t*)(Oah + orow + hd)                  = *reinterpret_cast<uint32_t*>(&h01);
        *(uint32_t*)(Oah + orow + (size_t)8 * D_ + hd) = *reinterpret_cast<uint32_t*>(&h23);
        *(uint32_t*)(Oal + orow + hd) =
            pack_f2(v0 - __low2float(h01), v1 - __high2float(h01));
        *(uint32_t*)(Oal + orow + (size_t)8 * D_ + hd) =
            pack_f2(v2 - __low2float(h23), v3 - __high2float(h23));
    }
}

// ---------------- kernel_launch ---------------------------------------------
extern "C" void kernel_launch(void* const* d_in, const int* in_sizes, int n_in,
                              void* d_out, int out_size)
{
    const float* hidden = (const float*)d_in[0];
    const float* rot    = (const float*)d_in[1];
    const float* Wq = (const float*)d_in[2];
    const float* bq = (const float*)d_in[3];
    const float* Wk = (const float*)d_in[4];
    const float* bk = (const float*)d_in[5];
    const float* Wv = (const float*)d_in[6];
    const float* bv = (const float*)d_in[7];
    const float* gq = (const float*)d_in[8];
    const float* gk = (const float*)d_in[9];
    const float* Wo = (const float*)d_in[10];
    const float* bo = (const float*)d_in[11];
    const int*   ctx  = (const int*)d_in[12];
    const int*   nseq = (const int*)d_in[13];
    float* out = (float*)d_out;

    float *q, *k;
    __half *xh, *xl, *ah, *al, *wh, *qh, *ql, *kh, *vh;
    cudaGetSymbolAddress((void**)&q, g_q);
    cudaGetSymbolAddress((void**)&k, g_k);
    cudaGetSymbolAddress((void**)&xh, g_xh);
    cudaGetSymbolAddress((void**)&xl, g_xl);
    cudaGetSymbolAddress((void**)&ah, g_ah);
    cudaGetSymbolAddress((void**)&al, g_al);
    cudaGetSymbolAddress((void**)&wh, g_wh);
    cudaGetSymbolAddress((void**)&qh, g_qh);
    cudaGetSymbolAddress((void**)&ql, g_ql);
    cudaGetSymbolAddress((void**)&kh, g_kh);
    cudaGetSymbolAddress((void**)&vh, g_vh);

    const int nX = M_ * D_, nW = D_ * D_;

    split_fp16<<<nX / 1024, 256>>>(hidden, xh, xl, nX);
    cvt_f16<<<nW / 1024, 256>>>(Wq, wh + 0 * (size_t)nW, nW);
    cvt_f16<<<nW / 1024, 256>>>(Wk, wh + 1 * (size_t)nW, nW);
    cvt_f16<<<nW / 1024, 256>>>(Wv, wh + 2 * (size_t)nW, nW);
    cvt_f16<<<nW / 1024, 256>>>(Wo, wh + 3 * (size_t)nW, nW);

    cudaFuncSetAttribute(gemm_f16_n256, cudaFuncAttributeMaxDynamicSharedMemorySize,
                         GEMM2_SMEM);

    // Fused QKV projections: z = 0 -> q (f32), 1 -> k (f32), 2 -> v (fp16)
    gemm_f16_n256<<<dim3(D_ / 256, M_ / 128, 3), 256, GEMM2_SMEM>>>(
        xh, xl, wh, bq, bk, bv, q, k, vh);

    rms_rope_split<<<dim3(M_, 2), 256>>>(q, k, gq, gk, rot, qh, ql, kh);

    cudaFuncSetAttribute(attn_f16, cudaFuncAttributeMaxDynamicSharedMemorySize,
                         ATT_SMEM);
    attn_f16<<<dim3(S_ / AQ, H_, B_), 256, ATT_SMEM>>>(qh, ql, kh, vh,
                                                       ah, al, ctx, nseq);

    // Output projection (z = 0 path -> float out)
    gemm_f16_n256<<<dim3(D_ / 256, M_ / 128, 1), 256, GEMM2_SMEM>>>(
        ah, al, wh + 3 * (size_t)nW, bo, bo, bo, out, nullptr, nullptr);
}

// round 10
// speedup vs baseline: 4.2712x; 1.0069x over previous
#include <cuda_runtime.h>
#include <cuda_fp16.h>
#include <cstdint>

#define B_   2
#define S_   3072
#define D_   2048
#define H_   16
#define HD_  128
#define M_   (B_ * S_)     // 6144 tokens

// ---------------- scratch (no allocation anywhere) -------------------------
__device__ float  g_q[M_ * D_];
__device__ float  g_k[M_ * D_];
__device__ __half g_xh[M_ * D_], g_xl[M_ * D_];         // hidden hi/lo
__device__ __half g_ah[M_ * D_], g_al[M_ * D_];         // attn-out hi/lo
__device__ __half g_wh[4 * D_ * D_];                    // Wq,Wk,Wv,Wo fp16
__device__ __half g_qh[M_ * D_], g_ql[M_ * D_];
__device__ __half g_kh[M_ * D_];
__device__ __half g_vh[M_ * D_];

// ---------------- helpers ----------------------------------------------------
__device__ __forceinline__ uint32_t smem_u32(const void* p) {
    uint32_t a;
    asm("{ .reg .u64 t; cvta.to.shared.u64 t, %1; cvt.u32.u64 %0, t; }"
        : "=r"(a) : "l"(p));
    return a;
}
__device__ __forceinline__ void mma_f16(float c[4], const uint32_t a[4],
                                        const uint32_t b[2]) {
    asm volatile(
        "mma.sync.aligned.m16n8k16.row.col.f32.f16.f16.f32 "
        "{%0,%1,%2,%3}, {%4,%5,%6,%7}, {%8,%9}, {%0,%1,%2,%3};"
        : "+f"(c[0]), "+f"(c[1]), "+f"(c[2]), "+f"(c[3])
        : "r"(a[0]), "r"(a[1]), "r"(a[2]), "r"(a[3]), "r"(b[0]), "r"(b[1]));
}
__device__ __forceinline__ void ldsm_x4(uint32_t& r0, uint32_t& r1,
                                        uint32_t& r2, uint32_t& r3, uint32_t a) {
    asm volatile("ldmatrix.sync.aligned.m8n8.x4.shared.b16 {%0,%1,%2,%3}, [%4];"
                 : "=r"(r0), "=r"(r1), "=r"(r2), "=r"(r3) : "r"(a));
}
__device__ __forceinline__ void ldsm_x4_t(uint32_t& r0, uint32_t& r1,
                                          uint32_t& r2, uint32_t& r3, uint32_t a) {
    asm volatile("ldmatrix.sync.aligned.m8n8.x4.trans.shared.b16 "
                 "{%0,%1,%2,%3}, [%4];"
                 : "=r"(r0), "=r"(r1), "=r"(r2), "=r"(r3) : "r"(a));
}
__device__ __forceinline__ uint32_t pack_h2(__half a, __half b) {
    __half2 t = __halves2half2(a, b);
    return *reinterpret_cast<uint32_t*>(&t);
}
__device__ __forceinline__ uint32_t pack_f2(float a, float b) {
    __half2 t = __floats2half2_rn(a, b);
    return *reinterpret_cast<uint32_t*>(&t);
}
#define CP_ASYNC16(s, g) \
    asm volatile("cp.async.cg.shared.global [%0], [%1], 16;" :: "r"(s), "l"(g))
#define CP_COMMIT()  asm volatile("cp.async.commit_group;" ::: "memory")
#define CP_WAIT(n)   asm volatile("cp.async.wait_group %0;" :: "n"(n) : "memory")

// ---------------- split fp32 -> fp16 hi/lo -----------------------------------
__global__ void __launch_bounds__(256) split_fp16(
    const float* __restrict__ in, __half* __restrict__ hp, __half* __restrict__ lp,
    int n)
{
    int i = (blockIdx.x * 256 + threadIdx.x) * 4;
    if (i >= n) return;
    float4 v = *(const float4*)(in + i);
    float x[4] = {v.x, v.y, v.z, v.w};
    __half h[4];
    float  r[4];
    #pragma unroll
    for (int j = 0; j < 4; j++) {
        h[j] = __float2half_rn(x[j]);
        r[j] = x[j] - __half2float(h[j]);
    }
    *(uint32_t*)(hp + i)     = pack_h2(h[0], h[1]);
    *(uint32_t*)(hp + i + 2) = pack_h2(h[2], h[3]);
    *(uint32_t*)(lp + i)     = pack_f2(r[0], r[1]);
    *(uint32_t*)(lp + i + 2) = pack_f2(r[2], r[3]);
}

// ---------------- convert 4 weight matrices fp32 -> fp16 (one launch) -------
__global__ void __launch_bounds__(256) cvt_f16_4(
    const float* __restrict__ w0, const float* __restrict__ w1,
    const float* __restrict__ w2, const float* __restrict__ w3,
    __half* __restrict__ out, int n)
{
    const int z = blockIdx.y;
    const float* in = (z == 0) ? w0 : (z == 1) ? w1 : (z == 2) ? w2 : w3;
    __half* o = out + (size_t)z * n;
    int i = (blockIdx.x * 256 + threadIdx.x) * 4;
    if (i >= n) return;
    float4 v = *(const float4*)(in + i);
    *(uint32_t*)(o + i)     = pack_f2(v.x, v.y);
    *(uint32_t*)(o + i + 2) = pack_f2(v.z, v.w);
}

// ---------------------------------------------------------------------------
// fp16 2-term tensor GEMM: O[m,n] = sum_k (Ah+Al)[m,k] * W16[n,k] + bias[n]
// A split hi/lo fp16; W single fp16 plane.  128x256 CTA tile, ldmatrix frags,
// cp.async 3-stage.  blockIdx.z selects weight/bias/output (fused QKV);
// z=2 writes fp16.  8 warps (2m x 4n), warp tile 64x64.
// ---------------------------------------------------------------------------
#define G2_STR  40                        // halves per smem row (80 B)
#define G2_APLH (128 * G2_STR)            // 5120 halves
#define G2_BPLH (256 * G2_STR)            // 10240 halves
#define G2_STGH (2 * G2_APLH + G2_BPLH)   // 20480 halves / stage
#define GEMM2_SMEM (3 * G2_STGH * 2)      // 122880 bytes

__global__ void __launch_bounds__(256, 1) gemm_f16_n256(
    const __half* __restrict__ Ahg, const __half* __restrict__ Alg,
    const __half* __restrict__ WhB,
    const float* __restrict__ b0p, const float* __restrict__ b1p,
    const float* __restrict__ b2p,
    float* __restrict__ o0, float* __restrict__ o1, __half* __restrict__ o2)
{
    extern __shared__ __align__(16) __half g2sm[];
    const uint32_t sb = smem_u32(g2sm);

    const int z    = blockIdx.z;
    const __half* Bhg = WhB + (size_t)z * D_ * D_;
    const float* bias = (z == 0) ? b0p : (z == 1) ? b1p : b2p;

    const int bm   = blockIdx.y * 128;
    const int bn   = blockIdx.x * 256;
    const int tid  = threadIdx.x;
    const int warp = tid >> 5;
    const int lane = tid & 31;
    const int lr   = lane >> 2;
    const int lc   = lane & 3;
    const int g    = lane >> 3;
    const int sub  = lane & 7;
    const int wm   = (warp & 1) * 64;
    const int wn   = (warp >> 1) * 64;

    int aoff[4], boff[4];
    #pragma unroll
    for (int mi = 0; mi < 4; mi++)
        aoff[mi] = (wm + mi * 16 + (g & 1) * 8 + sub) * G2_STR + (g >> 1) * 8;
    #pragma unroll
    for (int nip = 0; nip < 4; nip++)
        boff[nip] = (wn + nip * 16 + (g >> 1) * 8 + sub) * G2_STR + (g & 1) * 8;

    auto load_stage = [&](int s, int buf) {
        const int kt = s * 32;
        const uint32_t stg = buf * G2_STGH;
        #pragma unroll
        for (int i = 0; i < 8; i++) {
            const int idx = i * 256 + tid;        // 0..2047
            uint32_t dsth;
            const __half* src;
            if (idx < 1024) {                     // A planes (hi, lo)
                const int pl = idx >> 9, w = idx & 511;
                const int row = w >> 2, c = w & 3;
                dsth = stg + pl * G2_APLH + row * G2_STR + c * 8;
                src = (pl ? Alg : Ahg) + (size_t)(bm + row) * D_ + kt + c * 8;
            } else {                               // W plane
                const int j = idx - 1024;
                const int row = j >> 2, c = j & 3;
                dsth = stg + 2 * G2_APLH + row * G2_STR + c * 8;
                src = Bhg + (size_t)(bn + row) * D_ + kt + c * 8;
            }
            CP_ASYNC16(sb + dsth * 2, src);
        }
        CP_COMMIT();
    };

    float acc[4][8][4];
    #pragma unroll
    for (int mi = 0; mi < 4; mi++)
        #pragma unroll
        for (int ni = 0; ni < 8; ni++)
            #pragma unroll
            for (int r = 0; r < 4; r++) acc[mi][ni][r] = 0.0f;

    load_stage(0, 0);
    load_stage(1, 1);

    for (int s = 0; s < 64; s++) {
        CP_WAIT(1);
        __syncthreads();
        if (s + 2 < 64) load_stage(s + 2, (s + 2) % 3);

        const uint32_t stg = (s % 3) * G2_STGH;
        #pragma unroll
        for (int kk = 0; kk < 2; kk++) {
            const int kh = kk * 16;
            uint32_t ah[4][4], al[4][4];
            #pragma unroll
            for (int mi = 0; mi < 4; mi++) {
                ldsm_x4(ah[mi][0], ah[mi][1], ah[mi][2], ah[mi][3],
                        sb + (stg + aoff[mi] + kh) * 2);
                ldsm_x4(al[mi][0], al[mi][1], al[mi][2], al[mi][3],
                        sb + (stg + G2_APLH + aoff[mi] + kh) * 2);
            }
            #pragma unroll
            for (int nip = 0; nip < 4; nip++) {
                uint32_t bh[4];
                ldsm_x4(bh[0], bh[1], bh[2], bh[3],
                        sb + (stg + 2 * G2_APLH + boff[nip] + kh) * 2);
                uint32_t bh01[2] = {bh[0], bh[1]}, bh23[2] = {bh[2], bh[3]};
                #pragma unroll
                for (int mi = 0; mi < 4; mi++) {
                    mma_f16(acc[mi][2 * nip],     ah[mi], bh01);
                    mma_f16(acc[mi][2 * nip],     al[mi], bh01);
                    mma_f16(acc[mi][2 * nip + 1], ah[mi], bh23);
                    mma_f16(acc[mi][2 * nip + 1], al[mi], bh23);
                }
            }
        }
    }

    // epilogue
    #pragma unroll
    for (int ni = 0; ni < 8; ni++) {
        const int c = bn + wn + ni * 8 + 2 * lc;
        const float bb0 = __ldg(bias + c);
        const float bb1 = __ldg(bias + c + 1);
        #pragma unroll
        for (int mi = 0; mi < 4; mi++) {
            const int r = bm + wm + mi * 16 + lr;
            const float v00 = acc[mi][ni][0] + bb0;
            const float v01 = acc[mi][ni][1] + bb1;
            const float v10 = acc[mi][ni][2] + bb0;
            const float v11 = acc[mi][ni][3] + bb1;
            if (z == 2) {
                *(uint32_t*)(o2 + (size_t)r * D_ + c)       = pack_f2(v00, v01);
                *(uint32_t*)(o2 + (size_t)(r + 8) * D_ + c) = pack_f2(v10, v11);
            } else {
                float* Of = (z == 0) ? o0 : o1;
                *(float2*)(Of + (size_t)r * D_ + c)       = float2{v00, v01};
                *(float2*)(Of + (size_t)(r + 8) * D_ + c) = float2{v10, v11};
            }
        }
    }
}

// ---------------------------------------------------------------------------
// RMSNorm + interleaved RoPE -> fp16 planes: qh+ql (q scaled 1/sqrt(HD)), kh.
// ---------------------------------------------------------------------------
__global__ void __launch_bounds__(256) rms_rope_split(
    const float* __restrict__ Tq, const float* __restrict__ Tk,
    const float* __restrict__ gq, const float* __restrict__ gk,
    const float* __restrict__ rot,
    __half* __restrict__ qh, __half* __restrict__ ql,
    __half* __restrict__ kh)
{
    const int token = blockIdx.x;
    const int s     = token % S_;
    const bool isq  = (blockIdx.y == 0);
    const float* T  = isq ? Tq : Tk;
    const float* g  = isq ? gq : gk;
    const float post = isq ? 0.08838834764831845f : 1.0f;
    const int t = threadIdx.x;

    const float* row = T + (size_t)token * D_;
    float4 v0 = *(const float4*)(row + t * 8);
    float4 v1 = *(const float4*)(row + t * 8 + 4);
    float x[8] = {v0.x, v0.y, v0.z, v0.w, v1.x, v1.y, v1.z, v1.w};

    float ss = 0.0f;
    #pragma unroll
    for (int i = 0; i < 8; i++) ss += x[i] * x[i];
    #pragma unroll
    for (int o = 16; o; o >>= 1) ss += __shfl_xor_sync(0xffffffffu, ss, o);

    __shared__ float red[8];
    __shared__ float rs_s;
    if ((t & 31) == 0) red[t >> 5] = ss;
    __syncthreads();
    if (t == 0) {
        float tot = 0.0f;
        #pragma unroll
        for (int i = 0; i < 8; i++) tot += red[i];
        rs_s = rsqrtf(tot * (1.0f / (float)D_) + 1e-6f);
    }
    __syncthreads();
    const float rs = rs_s;

    const float* rc = rot + (size_t)s * (2 * HD_);
    float out[8];
    #pragma unroll
    for (int j = 0; j < 4; j++) {
        const int d0 = t * 8 + 2 * j;
        const int i2 = d0 & (HD_ - 1);
        const float c  = rc[i2];
        const float sn = rc[HD_ + i2 + 1];
        const float x1 = x[2 * j]     * rs * g[d0];
        const float x2 = x[2 * j + 1] * rs * g[d0 + 1];
        out[2 * j]     = (x1 * c - x2 * sn) * post;
        out[2 * j + 1] = (x1 * sn + x2 * c) * post;
    }

    if (isq) {
        uint32_t* hd = (uint32_t*)(qh + (size_t)token * D_ + t * 8);
        uint32_t* ld = (uint32_t*)(ql + (size_t)token * D_ + t * 8);
        #pragma unroll
        for (int j = 0; j < 4; j++) {
            __half h0 = __float2half_rn(out[2 * j]);
            __half h1 = __float2half_rn(out[2 * j + 1]);
            hd[j] = pack_h2(h0, h1);
            ld[j] = pack_f2(out[2 * j]     - __half2float(h0),
                            out[2 * j + 1] - __half2float(h1));
        }
    } else {
        uint32_t* hd = (uint32_t*)(kh + (size_t)token * D_ + t * 8);
        #pragma unroll
        for (int j = 0; j < 4; j++)
            hd[j] = pack_f2(out[2 * j], out[2 * j + 1]);
    }
}

// ---------------------------------------------------------------------------
// fp16 tensor flash attention, 2-term QK + 2-term PV, ldmatrix frag loads.
// Heavy-first q-tile ordering + 3-stage KV pipeline with early issue.
// ---------------------------------------------------------------------------
#define AQ 128
#define AK 64
#define NQT (S_ / AQ)                  // 24 q-tiles
#define KSH 136                        // halves per smem row (272 B)
#define QPH (128 * KSH)                // halves per Q plane
#define KVPH (64 * KSH)                // halves per KV plane
#define ATT_SMEM ((2 * QPH + 6 * KVPH) * 2)   // 174080 bytes

__global__ void __launch_bounds__(256, 1) attn_f16(
    const __half* __restrict__ Qh, const __half* __restrict__ Ql,
    const __half* __restrict__ Kh, const __half* __restrict__ Vh,
    __half* __restrict__ Oah, __half* __restrict__ Oal,
    const int* __restrict__ ctxp, const int* __restrict__ nseqp)
{
    extern __shared__ __align__(16) __half smh[];
    const uint32_t sb = smem_u32(smh);

    const int tid  = threadIdx.x;
    const int warp = tid >> 5;
    const int lane = tid & 31;
    const int lr   = lane >> 2;
    const int lc   = lane & 3;
    const int g    = lane >> 3;
    const int sub  = lane & 7;
    const int h    = blockIdx.y;
    const int b    = blockIdx.z;
    const int hist = (S_ - ctxp[0]) / nseqp[0];

    // heavy-first q-tile ordering: current-segment tiles (long kv) first
    const int qt   = (blockIdx.x + (hist / AQ)) % NQT;
    const int q0   = qt * AQ;

    const int wm = warp * 16;
    const int q_lo = q0 + wm + lr;
    const int kvlen_lo = (q_lo < hist) ? hist : S_;
    const int kvlen_hi = (q_lo + 8 < hist) ? hist : S_;
    const int kv_end = (q0 + AQ <= hist) ? hist : S_;
    const int ntiles = (kv_end + AK - 1) / AK;

    const int qrow_off = (wm + (g & 1) * 8 + sub) * KSH + (g >> 1) * 8;
    const int krow_off = ((g >> 1) * 8 + sub) * KSH + (g & 1) * 8;

    // ---- stage Q (hi+lo planes) ----
    const size_t qoff = ((size_t)(b * S_ + q0)) * D_ + h * HD_;
    #pragma unroll
    for (int i = 0; i < 16; i++) {
        int idx = i * 256 + tid;
        int pl = idx >> 11, w = idx & 2047, r = w >> 4, c = w & 15;
        uint32_t dst = sb + (pl * QPH + r * KSH + c * 8) * 2;
        const __half* src = (pl ? Ql : Qh) + qoff + (size_t)r * D_ + c * 8;
        CP_ASYNC16(dst, src);
    }
    CP_COMMIT();

    const size_t kvo = ((size_t)(b * S_)) * D_ + h * HD_;
    const __half* Khp = Kh + kvo;
    const __half* Vhp = Vh + kvo;

    auto load_kv = [&](int kt, int bi) {
        const uint32_t baseh = 2 * QPH + bi * 2 * KVPH;
        #pragma unroll
        for (int i = 0; i < 8; i++) {
            int idx = i * 256 + tid;
            int pl = idx >> 10, w = idx & 1023, r = w >> 4, c = w & 15;
            const __half* s = pl ? Vhp : Khp;
            uint32_t dst = sb + (baseh + pl * KVPH + r * KSH + c * 8) * 2;
            CP_ASYNC16(dst, s + (size_t)(kt + r) * D_ + c * 8);
        }
        CP_COMMIT();
    };

    load_kv(0, 0);
    load_kv(AK, 1);

    float oc[16][4];
    #pragma unroll
    for (int f = 0; f < 16; f++)
        #pragma unroll
        for (int e = 0; e < 4; e++) oc[f][e] = 0.0f;
    float m_lo = -1e30f, m_hi = -1e30f, l_lo = 0.0f, l_hi = 0.0f;

    for (int t = 0; t < ntiles; t++) {
        const int kt = t * AK;
        if (t + 1 < ntiles) { CP_WAIT(1); } else { CP_WAIT(0); }
        __syncthreads();
        if (t + 2 < ntiles) load_kv((t + 2) * AK, (t + 2) % 3);

        const uint32_t kbaseH = 2 * QPH + (t % 3) * 2 * KVPH;  // halves

        // ---- S = Q K^T (2 terms) ----
        float sc[8][4];
        #pragma unroll
        for (int j = 0; j < 8; j++)
            #pragma unroll
            for (int e = 0; e < 4; e++) sc[j][e] = 0.0f;

        #pragma unroll
        for (int kd = 0; kd < 8; kd++) {
            uint32_t a_h[4], a_l[4];
            ldsm_x4(a_h[0], a_h[1], a_h[2], a_h[3],
                    sb + (qrow_off + kd * 16) * 2);
            ldsm_x4(a_l[0], a_l[1], a_l[2], a_l[3],
                    sb + (QPH + qrow_off + kd * 16) * 2);
            #pragma unroll
            for (int jp = 0; jp < 4; jp++) {
                uint32_t kb[4];
                ldsm_x4(kb[0], kb[1], kb[2], kb[3],
                        sb + (kbaseH + jp * 16 * KSH + krow_off + kd * 16) * 2);
                uint32_t b01[2] = {kb[0], kb[1]}, b23[2] = {kb[2], kb[3]};
                mma_f16(sc[2 * jp],     a_h, b01);
                mma_f16(sc[2 * jp],     a_l, b01);
                mma_f16(sc[2 * jp + 1], a_h, b23);
                mma_f16(sc[2 * jp + 1], a_l, b23);
            }
        }

        // ---- mask ----
        if (kt + AK > kvlen_lo || kt + AK > kvlen_hi) {
            #pragma unroll
            for (int j = 0; j < 8; j++) {
                const int c0 = kt + j * 8 + 2 * lc;
                if (c0     >= kvlen_lo) sc[j][0] = -1e30f;
                if (c0 + 1 >= kvlen_lo) sc[j][1] = -1e30f;
                if (c0     >= kvlen_hi) sc[j][2] = -1e30f;
                if (c0 + 1 >= kvlen_hi) sc[j][3] = -1e30f;
            }
        }

        // ---- online softmax (warp-local rows) ----
        float mx_lo = -1e30f, mx_hi = -1e30f;
        #pragma unroll
        for (int j = 0; j < 8; j++) {
            mx_lo = fmaxf(mx_lo, fmaxf(sc[j][0], sc[j][1]));
            mx_hi = fmaxf(mx_hi, fmaxf(sc[j][2], sc[j][3]));
        }
        mx_lo = fmaxf(mx_lo, __shfl_xor_sync(0xffffffffu, mx_lo, 1));
        mx_lo = fmaxf(mx_lo, __shfl_xor_sync(0xffffffffu, mx_lo, 2));
        mx_hi = fmaxf(mx_hi, __shfl_xor_sync(0xffffffffu, mx_hi, 1));
        mx_hi = fmaxf(mx_hi, __shfl_xor_sync(0xffffffffu, mx_hi, 2));
        const float mn_lo = fmaxf(m_lo, mx_lo);
        const float mn_hi = fmaxf(m_hi, mx_hi);
        const float corr_lo = __expf(m_lo - mn_lo);
        const float corr_hi = __expf(m_hi - mn_hi);
        m_lo = mn_lo; m_hi = mn_hi;

        uint32_t ph01[8], ph23[8], pl01[8], pl23[8];
        float s_lo = 0.0f, s_hi = 0.0f;
        #pragma unroll
        for (int j = 0; j < 8; j++) {
            float p0 = __expf(sc[j][0] - mn_lo);
            float p1 = __expf(sc[j][1] - mn_lo);
            float p2 = __expf(sc[j][2] - mn_hi);
            float p3 = __expf(sc[j][3] - mn_hi);
            s_lo += p0 + p1; s_hi += p2 + p3;
            __half2 h01 = __floats2half2_rn(p0, p1);
            __half2 h23 = __floats2half2_rn(p2, p3);
            ph01[j] = *reinterpret_cast<uint32_t*>(&h01);
            ph23[j] = *reinterpret_cast<uint32_t*>(&h23);
            pl01[j] = pack_f2(p0 - __low2float(h01), p1 - __high2float(h01));
            pl23[j] = pack_f2(p2 - __low2float(h23), p3 - __high2float(h23));
        }
        s_lo += __shfl_xor_sync(0xffffffffu, s_lo, 1);
        s_lo += __shfl_xor_sync(0xffffffffu, s_lo, 2);
        s_hi += __shfl_xor_sync(0xffffffffu, s_hi, 1);
        s_hi += __shfl_xor_sync(0xffffffffu, s_hi, 2);
        l_lo = l_lo * corr_lo + s_lo;
        l_hi = l_hi * corr_hi + s_hi;
        #pragma unroll
        for (int f = 0; f < 16; f++) {
            oc[f][0] *= corr_lo; oc[f][1] *= corr_lo;
            oc[f][2] *= corr_hi; oc[f][3] *= corr_hi;
        }

        // ---- O += P V (2 terms) ----
        const uint32_t vh_h = 2 * QPH + (t % 3) * 2 * KVPH + KVPH;   // halves
        const int vrow = lane & 15;
        const int vcol = (lane >> 4) * 8;
        #pragma unroll
        for (int ks = 0; ks < 4; ks++) {
            uint32_t a_h[4] = {ph01[2 * ks], ph23[2 * ks],
                               ph01[2 * ks + 1], ph23[2 * ks + 1]};
            uint32_t a_l[4] = {pl01[2 * ks], pl23[2 * ks],
                               pl01[2 * ks + 1], pl23[2 * ks + 1]};
            const int vr = ks * 16 + vrow;
            #pragma unroll
            for (int jp = 0; jp < 8; jp++) {
                uint32_t r0, r1, r2, r3;
                uint32_t vaddr = sb + (vh_h + vr * KSH + jp * 16 + vcol) * 2;
                ldsm_x4_t(r0, r1, r2, r3, vaddr);
                uint32_t bh0[2] = {r0, r1}, bh1[2] = {r2, r3};
                mma_f16(oc[2 * jp],     a_h, bh0);
                mma_f16(oc[2 * jp + 1], a_h, bh1);
                mma_f16(oc[2 * jp],     a_l, bh0);
                mma_f16(oc[2 * jp + 1], a_l, bh1);
            }
        }
    }
    CP_WAIT(0);

    // ---- epilogue: write fp16 hi/lo planes directly ----
    const float inv_lo = 1.0f / l_lo;
    const float inv_hi = 1.0f / l_hi;
    const size_t orow = ((size_t)(b * S_ + q0 + wm + lr)) * D_ + h * HD_;
    #pragma unroll
    for (int f = 0; f < 16; f++) {
        const int hd = f * 8 + 2 * lc;
        float v0 = oc[f][0] * inv_lo, v1 = oc[f][1] * inv_lo;
        float v2 = oc[f][2] * inv_hi, v3 = oc[f][3] * inv_hi;
        __half2 h01 = __floats2half2_rn(v0, v1);
        __half2 h23 = __floats2half2_rn(v2, v3);
        *(uint32_t*)(Oah + orow + hd)                  = *reinterpret_cast<uint32_t*>(&h01);
        *(uint32_t*)(Oah + orow + (size_t)8 * D_ + hd) = *reinterpret_cast<uint32_t*>(&h23);
        *(uint32_t*)(Oal + orow + hd) =
            pack_f2(v0 - __low2float(h01), v1 - __high2float(h01));
        *(uint32_t*)(Oal + orow + (size_t)8 * D_ + hd) =
            pack_f2(v2 - __low2float(h23), v3 - __high2float(h23));
    }
}

// ---------------- kernel_launch ---------------------------------------------
extern "C" void kernel_launch(void* const* d_in, const int* in_sizes, int n_in,
                              void* d_out, int out_size)
{
    const float* hidden = (const float*)d_in[0];
    const float* rot    = (const float*)d_in[1];
    const float* Wq = (const float*)d_in[2];
    const float* bq = (const float*)d_in[3];
    const float* Wk = (const float*)d_in[4];
    const float* bk = (const float*)d_in[5];
    const float* Wv = (const float*)d_in[6];
    const float* bv = (const float*)d_in[7];
    const float* gq = (const float*)d_in[8];
    const float* gk = (const float*)d_in[9];
    const float* Wo = (const float*)d_in[10];
    const float* bo = (const float*)d_in[11];
    const int*   ctx  = (const int*)d_in[12];
    const int*   nseq = (const int*)d_in[13];
    float* out = (float*)d_out;

    float *q, *k;
    __half *xh, *xl, *ah, *al, *wh, *qh, *ql, *kh, *vh;
    cudaGetSymbolAddress((void**)&q, g_q);
    cudaGetSymbolAddress((void**)&k, g_k);
    cudaGetSymbolAddress((void**)&xh, g_xh);
    cudaGetSymbolAddress((void**)&xl, g_xl);
    cudaGetSymbolAddress((void**)&ah, g_ah);
    cudaGetSymbolAddress((void**)&al, g_al);
    cudaGetSymbolAddress((void**)&wh, g_wh);
    cudaGetSymbolAddress((void**)&qh, g_qh);
    cudaGetSymbolAddress((void**)&ql, g_ql);
    cudaGetSymbolAddress((void**)&kh, g_kh);
    cudaGetSymbolAddress((void**)&vh, g_vh);

    const int nX = M_ * D_, nW = D_ * D_;

    split_fp16<<<nX / 1024, 256>>>(hidden, xh, xl, nX);
    cvt_f16_4<<<dim3(nW / 1024, 4), 256>>>(Wq, Wk, Wv, Wo, wh, nW);

    cudaFuncSetAttribute(gemm_f16_n256, cudaFuncAttributeMaxDynamicSharedMemorySize,
                         GEMM2_SMEM);

    // Fused QKV projections: z = 0 -> q (f32), 1 -> k (f32), 2 -> v (fp16)
    gemm_f16_n256<<<dim3(D_ / 256, M_ / 128, 3), 256, GEMM2_SMEM>>>(
        xh, xl, wh, bq, bk, bv, q, k, vh);

    rms_rope_split<<<dim3(M_, 2), 256>>>(q, k, gq, gk, rot, qh, ql, kh);

    cudaFuncSetAttribute(attn_f16, cudaFuncAttributeMaxDynamicSharedMemorySize,
                         ATT_SMEM);
    attn_f16<<<dim3(NQT, H_, B_), 256, ATT_SMEM>>>(qh, ql, kh, vh,
                                                   ah, al, ctx, nseq);

    // Output projection (z = 0 path -> float out)
    gemm_f16_n256<<<dim3(D_ / 256, M_ / 128, 1), 256, GEMM2_SMEM>>>(
        ah, al, wh + 3 * (size_t)nW, bo, bo, bo, out, nullptr, nullptr);
}

// round 11
// speedup vs baseline: 4.6105x; 1.0794x over previous
#include <cuda_runtime.h>
#include <cuda_fp16.h>
#include <cstdint>

#define B_   2
#define S_   3072
#define D_   2048
#define H_   16
#define HD_  128
#define M_   (B_ * S_)     // 6144 tokens

// ---------------- scratch (no allocation anywhere) -------------------------
__device__ float  g_q[M_ * D_];
__device__ float  g_k[M_ * D_];
__device__ __half g_xh[M_ * D_], g_xl[M_ * D_];         // hidden hi/lo
__device__ __half g_ah[M_ * D_], g_al[M_ * D_];         // attn-out hi/lo
__device__ __half g_wh[4 * D_ * D_];                    // Wq,Wk,Wv,Wo fp16
__device__ __half g_qh[M_ * D_], g_ql[M_ * D_];
__device__ __half g_kh[M_ * D_];
__device__ __half g_vh[M_ * D_];

// ---------------- helpers ----------------------------------------------------
__device__ __forceinline__ uint32_t smem_u32(const void* p) {
    uint32_t a;
    asm("{ .reg .u64 t; cvta.to.shared.u64 t, %1; cvt.u32.u64 %0, t; }"
        : "=r"(a) : "l"(p));
    return a;
}
__device__ __forceinline__ void mma_f16(float c[4], const uint32_t a[4],
                                        const uint32_t b[2]) {
    asm volatile(
        "mma.sync.aligned.m16n8k16.row.col.f32.f16.f16.f32 "
        "{%0,%1,%2,%3}, {%4,%5,%6,%7}, {%8,%9}, {%0,%1,%2,%3};"
        : "+f"(c[0]), "+f"(c[1]), "+f"(c[2]), "+f"(c[3])
        : "r"(a[0]), "r"(a[1]), "r"(a[2]), "r"(a[3]), "r"(b[0]), "r"(b[1]));
}
__device__ __forceinline__ void ldsm_x4(uint32_t& r0, uint32_t& r1,
                                        uint32_t& r2, uint32_t& r3, uint32_t a) {
    asm volatile("ldmatrix.sync.aligned.m8n8.x4.shared.b16 {%0,%1,%2,%3}, [%4];"
                 : "=r"(r0), "=r"(r1), "=r"(r2), "=r"(r3) : "r"(a));
}
__device__ __forceinline__ void ldsm_x4_t(uint32_t& r0, uint32_t& r1,
                                          uint32_t& r2, uint32_t& r3, uint32_t a) {
    asm volatile("ldmatrix.sync.aligned.m8n8.x4.trans.shared.b16 "
                 "{%0,%1,%2,%3}, [%4];"
                 : "=r"(r0), "=r"(r1), "=r"(r2), "=r"(r3) : "r"(a));
}
__device__ __forceinline__ uint32_t pack_h2(__half a, __half b) {
    __half2 t = __halves2half2(a, b);
    return *reinterpret_cast<uint32_t*>(&t);
}
__device__ __forceinline__ uint32_t pack_f2(float a, float b) {
    __half2 t = __floats2half2_rn(a, b);
    return *reinterpret_cast<uint32_t*>(&t);
}
#define CP_ASYNC16(s, g) \
    asm volatile("cp.async.cg.shared.global [%0], [%1], 16;" :: "r"(s), "l"(g))
#define CP_COMMIT()  asm volatile("cp.async.commit_group;" ::: "memory")
#define CP_WAIT(n)   asm volatile("cp.async.wait_group %0;" :: "n"(n) : "memory")

// ---------------- split fp32 -> fp16 hi/lo -----------------------------------
__global__ void __launch_bounds__(256) split_fp16(
    const float* __restrict__ in, __half* __restrict__ hp, __half* __restrict__ lp,
    int n)
{
    int i = (blockIdx.x * 256 + threadIdx.x) * 4;
    if (i >= n) return;
    float4 v = *(const float4*)(in + i);
    float x[4] = {v.x, v.y, v.z, v.w};
    __half h[4];
    float  r[4];
    #pragma unroll
    for (int j = 0; j < 4; j++) {
        h[j] = __float2half_rn(x[j]);
        r[j] = x[j] - __half2float(h[j]);
    }
    *(uint32_t*)(hp + i)     = pack_h2(h[0], h[1]);
    *(uint32_t*)(hp + i + 2) = pack_h2(h[2], h[3]);
    *(uint32_t*)(lp + i)     = pack_f2(r[0], r[1]);
    *(uint32_t*)(lp + i + 2) = pack_f2(r[2], r[3]);
}

// ---------------- convert 4 weight matrices fp32 -> fp16 (one launch) -------
__global__ void __launch_bounds__(256) cvt_f16_4(
    const float* __restrict__ w0, const float* __restrict__ w1,
    const float* __restrict__ w2, const float* __restrict__ w3,
    __half* __restrict__ out, int n)
{
    const int z = blockIdx.y;
    const float* in = (z == 0) ? w0 : (z == 1) ? w1 : (z == 2) ? w2 : w3;
    __half* o = out + (size_t)z * n;
    int i = (blockIdx.x * 256 + threadIdx.x) * 4;
    if (i >= n) return;
    float4 v = *(const float4*)(in + i);
    *(uint32_t*)(o + i)     = pack_f2(v.x, v.y);
    *(uint32_t*)(o + i + 2) = pack_f2(v.z, v.w);
}

// ---------------------------------------------------------------------------
// fp16 2-term tensor GEMM: O[m,n] = sum_k (Ah+Al)[m,k] * W16[n,k] + bias[n]
// A split hi/lo fp16; W single fp16 plane.  128x256 CTA tile, ldmatrix frags,
// cp.async 3-stage with BK=64 (32 stages, sync overhead halved vs BK=32).
// blockIdx.z selects weight/bias/output (fused QKV); z=2 writes fp16.
// 8 warps (2m x 4n), warp tile 64x64.
// Row stride 72 halves = 144 B: 16B-aligned; ldmatrix conflict-free
// (36r mod 32 covers all banks per 8-row group).
// ---------------------------------------------------------------------------
#define G2_BK   64
#define G2_STR  72                        // halves per smem row (144 B)
#define G2_APLH (128 * G2_STR)            // 9216 halves
#define G2_BPLH (256 * G2_STR)            // 18432 halves
#define G2_STGH (2 * G2_APLH + G2_BPLH)   // 36864 halves / stage
#define GEMM2_SMEM (3 * G2_STGH * 2)      // 221184 bytes
#define G2_NS   (D_ / G2_BK)              // 32 stages

__global__ void __launch_bounds__(256, 1) gemm_f16_n256(
    const __half* __restrict__ Ahg, const __half* __restrict__ Alg,
    const __half* __restrict__ WhB,
    const float* __restrict__ b0p, const float* __restrict__ b1p,
    const float* __restrict__ b2p,
    float* __restrict__ o0, float* __restrict__ o1, __half* __restrict__ o2)
{
    extern __shared__ __align__(16) __half g2sm[];
    const uint32_t sb = smem_u32(g2sm);

    const int z    = blockIdx.z;
    const __half* Bhg = WhB + (size_t)z * D_ * D_;
    const float* bias = (z == 0) ? b0p : (z == 1) ? b1p : b2p;

    const int bm   = blockIdx.y * 128;
    const int bn   = blockIdx.x * 256;
    const int tid  = threadIdx.x;
    const int warp = tid >> 5;
    const int lane = tid & 31;
    const int lr   = lane >> 2;
    const int lc   = lane & 3;
    const int g    = lane >> 3;
    const int sub  = lane & 7;
    const int wm   = (warp & 1) * 64;
    const int wn   = (warp >> 1) * 64;

    int aoff[4], boff[4];
    #pragma unroll
    for (int mi = 0; mi < 4; mi++)
        aoff[mi] = (wm + mi * 16 + (g & 1) * 8 + sub) * G2_STR + (g >> 1) * 8;
    #pragma unroll
    for (int nip = 0; nip < 4; nip++)
        boff[nip] = (wn + nip * 16 + (g >> 1) * 8 + sub) * G2_STR + (g & 1) * 8;

    auto load_stage = [&](int s, int buf) {
        const int kt = s * G2_BK;
        const uint32_t stg = buf * G2_STGH;
        #pragma unroll
        for (int i = 0; i < 16; i++) {
            const int idx = i * 256 + tid;        // 0..4095
            uint32_t dsth;
            const __half* src;
            if (idx < 2048) {                     // A planes (hi, lo)
                const int pl = idx >> 10, w = idx & 1023;
                const int row = w >> 3, c = w & 7;
                dsth = stg + pl * G2_APLH + row * G2_STR + c * 8;
                src = (pl ? Alg : Ahg) + (size_t)(bm + row) * D_ + kt + c * 8;
            } else {                               // W plane
                const int j = idx - 2048;
                const int row = j >> 3, c = j & 7;
                dsth = stg + 2 * G2_APLH + row * G2_STR + c * 8;
                src = Bhg + (size_t)(bn + row) * D_ + kt + c * 8;
            }
            CP_ASYNC16(sb + dsth * 2, src);
        }
        CP_COMMIT();
    };

    float acc[4][8][4];
    #pragma unroll
    for (int mi = 0; mi < 4; mi++)
        #pragma unroll
        for (int ni = 0; ni < 8; ni++)
            #pragma unroll
            for (int r = 0; r < 4; r++) acc[mi][ni][r] = 0.0f;

    load_stage(0, 0);
    load_stage(1, 1);

    for (int s = 0; s < G2_NS; s++) {
        if (s + 1 < G2_NS) { CP_WAIT(1); } else { CP_WAIT(0); }
        __syncthreads();
        if (s + 2 < G2_NS) load_stage(s + 2, (s + 2) % 3);

        const uint32_t stg = (s % 3) * G2_STGH;
        #pragma unroll
        for (int kk = 0; kk < 4; kk++) {
            const int kh = kk * 16;
            uint32_t ah[4][4], al[4][4];
            #pragma unroll
            for (int mi = 0; mi < 4; mi++) {
                ldsm_x4(ah[mi][0], ah[mi][1], ah[mi][2], ah[mi][3],
                        sb + (stg + aoff[mi] + kh) * 2);
                ldsm_x4(al[mi][0], al[mi][1], al[mi][2], al[mi][3],
                        sb + (stg + G2_APLH + aoff[mi] + kh) * 2);
            }
            #pragma unroll
            for (int nip = 0; nip < 4; nip++) {
                uint32_t bh[4];
                ldsm_x4(bh[0], bh[1], bh[2], bh[3],
                        sb + (stg + 2 * G2_APLH + boff[nip] + kh) * 2);
                uint32_t bh01[2] = {bh[0], bh[1]}, bh23[2] = {bh[2], bh[3]};
                #pragma unroll
                for (int mi = 0; mi < 4; mi++) {
                    mma_f16(acc[mi][2 * nip],     ah[mi], bh01);
                    mma_f16(acc[mi][2 * nip],     al[mi], bh01);
                    mma_f16(acc[mi][2 * nip + 1], ah[mi], bh23);
                    mma_f16(acc[mi][2 * nip + 1], al[mi], bh23);
                }
            }
        }
    }

    // epilogue
    #pragma unroll
    for (int ni = 0; ni < 8; ni++) {
        const int c = bn + wn + ni * 8 + 2 * lc;
        const float bb0 = __ldg(bias + c);
        const float bb1 = __ldg(bias + c + 1);
        #pragma unroll
        for (int mi = 0; mi < 4; mi++) {
            const int r = bm + wm + mi * 16 + lr;
            const float v00 = acc[mi][ni][0] + bb0;
            const float v01 = acc[mi][ni][1] + bb1;
            const float v10 = acc[mi][ni][2] + bb0;
            const float v11 = acc[mi][ni][3] + bb1;
            if (z == 2) {
                *(uint32_t*)(o2 + (size_t)r * D_ + c)       = pack_f2(v00, v01);
                *(uint32_t*)(o2 + (size_t)(r + 8) * D_ + c) = pack_f2(v10, v11);
            } else {
                float* Of = (z == 0) ? o0 : o1;
                *(float2*)(Of + (size_t)r * D_ + c)       = float2{v00, v01};
                *(float2*)(Of + (size_t)(r + 8) * D_ + c) = float2{v10, v11};
            }
        }
    }
}

// ---------------------------------------------------------------------------
// RMSNorm + interleaved RoPE -> fp16 planes: qh+ql (q scaled 1/sqrt(HD)), kh.
// ---------------------------------------------------------------------------
__global__ void __launch_bounds__(256) rms_rope_split(
    const float* __restrict__ Tq, const float* __restrict__ Tk,
    const float* __restrict__ gq, const float* __restrict__ gk,
    const float* __restrict__ rot,
    __half* __restrict__ qh, __half* __restrict__ ql,
    __half* __restrict__ kh)
{
    const int token = blockIdx.x;
    const int s     = token % S_;
    const bool isq  = (blockIdx.y == 0);
    const float* T  = isq ? Tq : Tk;
    const float* g  = isq ? gq : gk;
    const float post = isq ? 0.08838834764831845f : 1.0f;
    const int t = threadIdx.x;

    const float* row = T + (size_t)token * D_;
    float4 v0 = *(const float4*)(row + t * 8);
    float4 v1 = *(const float4*)(row + t * 8 + 4);
    float x[8] = {v0.x, v0.y, v0.z, v0.w, v1.x, v1.y, v1.z, v1.w};

    float ss = 0.0f;
    #pragma unroll
    for (int i = 0; i < 8; i++) ss += x[i] * x[i];
    #pragma unroll
    for (int o = 16; o; o >>= 1) ss += __shfl_xor_sync(0xffffffffu, ss, o);

    __shared__ float red[8];
    __shared__ float rs_s;
    if ((t & 31) == 0) red[t >> 5] = ss;
    __syncthreads();
    if (t == 0) {
        float tot = 0.0f;
        #pragma unroll
        for (int i = 0; i < 8; i++) tot += red[i];
        rs_s = rsqrtf(tot * (1.0f / (float)D_) + 1e-6f);
    }
    __syncthreads();
    const float rs = rs_s;

    const float* rc = rot + (size_t)s * (2 * HD_);
    float out[8];
    #pragma unroll
    for (int j = 0; j < 4; j++) {
        const int d0 = t * 8 + 2 * j;
        const int i2 = d0 & (HD_ - 1);
        const float c  = rc[i2];
        const float sn = rc[HD_ + i2 + 1];
        const float x1 = x[2 * j]     * rs * g[d0];
        const float x2 = x[2 * j + 1] * rs * g[d0 + 1];
        out[2 * j]     = (x1 * c - x2 * sn) * post;
        out[2 * j + 1] = (x1 * sn + x2 * c) * post;
    }

    if (isq) {
        uint32_t* hd = (uint32_t*)(qh + (size_t)token * D_ + t * 8);
        uint32_t* ld = (uint32_t*)(ql + (size_t)token * D_ + t * 8);
        #pragma unroll
        for (int j = 0; j < 4; j++) {
            __half h0 = __float2half_rn(out[2 * j]);
            __half h1 = __float2half_rn(out[2 * j + 1]);
            hd[j] = pack_h2(h0, h1);
            ld[j] = pack_f2(out[2 * j]     - __half2float(h0),
                            out[2 * j + 1] - __half2float(h1));
        }
    } else {
        uint32_t* hd = (uint32_t*)(kh + (size_t)token * D_ + t * 8);
        #pragma unroll
        for (int j = 0; j < 4; j++)
            hd[j] = pack_f2(out[2 * j], out[2 * j + 1]);
    }
}

// ---------------------------------------------------------------------------
// fp16 tensor flash attention, 2-term QK + 2-term PV, ldmatrix frag loads.
// Heavy-first q-tile ordering + 3-stage KV pipeline with early issue.
// ---------------------------------------------------------------------------
#define AQ 128
#define AK 64
#define NQT (S_ / AQ)                  // 24 q-tiles
#define KSH 136                        // halves per smem row (272 B)
#define QPH (128 * KSH)                // halves per Q plane
#define KVPH (64 * KSH)                // halves per KV plane
#define ATT_SMEM ((2 * QPH + 6 * KVPH) * 2)   // 174080 bytes

__global__ void __launch_bounds__(256, 1) attn_f16(
    const __half* __restrict__ Qh, const __half* __restrict__ Ql,
    const __half* __restrict__ Kh, const __half* __restrict__ Vh,
    __half* __restrict__ Oah, __half* __restrict__ Oal,
    const int* __restrict__ ctxp, const int* __restrict__ nseqp)
{
    extern __shared__ __align__(16) __half smh[];
    const uint32_t sb = smem_u32(smh);

    const int tid  = threadIdx.x;
    const int warp = tid >> 5;
    const int lane = tid & 31;
    const int lr   = lane >> 2;
    const int lc   = lane & 3;
    const int g    = lane >> 3;
    const int sub  = lane & 7;
    const int h    = blockIdx.y;
    const int b    = blockIdx.z;
    const int hist = (S_ - ctxp[0]) / nseqp[0];

    // heavy-first q-tile ordering: current-segment tiles (long kv) first
    const int qt   = (blockIdx.x + (hist / AQ)) % NQT;
    const int q0   = qt * AQ;

    const int wm = warp * 16;
    const int q_lo = q0 + wm + lr;
    const int kvlen_lo = (q_lo < hist) ? hist : S_;
    const int kvlen_hi = (q_lo + 8 < hist) ? hist : S_;
    const int kv_end = (q0 + AQ <= hist) ? hist : S_;
    const int ntiles = (kv_end + AK - 1) / AK;

    const int qrow_off = (wm + (g & 1) * 8 + sub) * KSH + (g >> 1) * 8;
    const int krow_off = ((g >> 1) * 8 + sub) * KSH + (g & 1) * 8;

    // ---- stage Q (hi+lo planes) ----
    const size_t qoff = ((size_t)(b * S_ + q0)) * D_ + h * HD_;
    #pragma unroll
    for (int i = 0; i < 16; i++) {
        int idx = i * 256 + tid;
        int pl = idx >> 11, w = idx & 2047, r = w >> 4, c = w & 15;
        uint32_t dst = sb + (pl * QPH + r * KSH + c * 8) * 2;
        const __half* src = (pl ? Ql : Qh) + qoff + (size_t)r * D_ + c * 8;
        CP_ASYNC16(dst, src);
    }
    CP_COMMIT();

    const size_t kvo = ((size_t)(b * S_)) * D_ + h * HD_;
    const __half* Khp = Kh + kvo;
    const __half* Vhp = Vh + kvo;

    auto load_kv = [&](int kt, int bi) {
        const uint32_t baseh = 2 * QPH + bi * 2 * KVPH;
        #pragma unroll
        for (int i = 0; i < 8; i++) {
            int idx = i * 256 + tid;
            int pl = idx >> 10, w = idx & 1023, r = w >> 4, c = w & 15;
            const __half* s = pl ? Vhp : Khp;
            uint32_t dst = sb + (baseh + pl * KVPH + r * KSH + c * 8) * 2;
            CP_ASYNC16(dst, s + (size_t)(kt + r) * D_ + c * 8);
        }
        CP_COMMIT();
    };

    load_kv(0, 0);
    load_kv(AK, 1);

    float oc[16][4];
    #pragma unroll
    for (int f = 0; f < 16; f++)
        #pragma unroll
        for (int e = 0; e < 4; e++) oc[f][e] = 0.0f;
    float m_lo = -1e30f, m_hi = -1e30f, l_lo = 0.0f, l_hi = 0.0f;

    for (int t = 0; t < ntiles; t++) {
        const int kt = t * AK;
        if (t + 1 < ntiles) { CP_WAIT(1); } else { CP_WAIT(0); }
        __syncthreads();
        if (t + 2 < ntiles) load_kv((t + 2) * AK, (t + 2) % 3);

        const uint32_t kbaseH = 2 * QPH + (t % 3) * 2 * KVPH;  // halves

        // ---- S = Q K^T (2 terms) ----
        float sc[8][4];
        #pragma unroll
        for (int j = 0; j < 8; j++)
            #pragma unroll
            for (int e = 0; e < 4; e++) sc[j][e] = 0.0f;

        #pragma unroll
        for (int kd = 0; kd < 8; kd++) {
            uint32_t a_h[4], a_l[4];
            ldsm_x4(a_h[0], a_h[1], a_h[2], a_h[3],
                    sb + (qrow_off + kd * 16) * 2);
            ldsm_x4(a_l[0], a_l[1], a_l[2], a_l[3],
                    sb + (QPH + qrow_off + kd * 16) * 2);
            #pragma unroll
            for (int jp = 0; jp < 4; jp++) {
                uint32_t kb[4];
                ldsm_x4(kb[0], kb[1], kb[2], kb[3],
                        sb + (kbaseH + jp * 16 * KSH + krow_off + kd * 16) * 2);
                uint32_t b01[2] = {kb[0], kb[1]}, b23[2] = {kb[2], kb[3]};
                mma_f16(sc[2 * jp],     a_h, b01);
                mma_f16(sc[2 * jp],     a_l, b01);
                mma_f16(sc[2 * jp + 1], a_h, b23);
                mma_f16(sc[2 * jp + 1], a_l, b23);
            }
        }

        // ---- mask ----
        if (kt + AK > kvlen_lo || kt + AK > kvlen_hi) {
            #pragma unroll
            for (int j = 0; j < 8; j++) {
                const int c0 = kt + j * 8 + 2 * lc;
                if (c0     >= kvlen_lo) sc[j][0] = -1e30f;
                if (c0 + 1 >= kvlen_lo) sc[j][1] = -1e30f;
                if (c0     >= kvlen_hi) sc[j][2] = -1e30f;
                if (c0 + 1 >= kvlen_hi) sc[j][3] = -1e30f;
            }
        }

        // ---- online softmax (warp-local rows) ----
        float mx_lo = -1e30f, mx_hi = -1e30f;
        #pragma unroll
        for (int j = 0; j < 8; j++) {
            mx_lo = fmaxf(mx_lo, fmaxf(sc[j][0], sc[j][1]));
            mx_hi = fmaxf(mx_hi, fmaxf(sc[j][2], sc[j][3]));
        }
        mx_lo = fmaxf(mx_lo, __shfl_xor_sync(0xffffffffu, mx_lo, 1));
        mx_lo = fmaxf(mx_lo, __shfl_xor_sync(0xffffffffu, mx_lo, 2));
        mx_hi = fmaxf(mx_hi, __shfl_xor_sync(0xffffffffu, mx_hi, 1));
        mx_hi = fmaxf(mx_hi, __shfl_xor_sync(0xffffffffu, mx_hi, 2));
        const float mn_lo = fmaxf(m_lo, mx_lo);
        const float mn_hi = fmaxf(m_hi, mx_hi);
        const float corr_lo = __expf(m_lo - mn_lo);
        const float corr_hi = __expf(m_hi - mn_hi);
        m_lo = mn_lo; m_hi = mn_hi;

        uint32_t ph01[8], ph23[8], pl01[8], pl23[8];
        float s_lo = 0.0f, s_hi = 0.0f;
        #pragma unroll
        for (int j = 0; j < 8; j++) {
            float p0 = __expf(sc[j][0] - mn_lo);
            float p1 = __expf(sc[j][1] - mn_lo);
            float p2 = __expf(sc[j][2] - mn_hi);
            float p3 = __expf(sc[j][3] - mn_hi);
            s_lo += p0 + p1; s_hi += p2 + p3;
            __half2 h01 = __floats2half2_rn(p0, p1);
            __half2 h23 = __floats2half2_rn(p2, p3);
            ph01[j] = *reinterpret_cast<uint32_t*>(&h01);
            ph23[j] = *reinterpret_cast<uint32_t*>(&h23);
            pl01[j] = pack_f2(p0 - __low2float(h01), p1 - __high2float(h01));
            pl23[j] = pack_f2(p2 - __low2float(h23), p3 - __high2float(h23));
        }
        s_lo += __shfl_xor_sync(0xffffffffu, s_lo, 1);
        s_lo += __shfl_xor_sync(0xffffffffu, s_lo, 2);
        s_hi += __shfl_xor_sync(0xffffffffu, s_hi, 1);
        s_hi += __shfl_xor_sync(0xffffffffu, s_hi, 2);
        l_lo = l_lo * corr_lo + s_lo;
        l_hi = l_hi * corr_hi + s_hi;
        #pragma unroll
        for (int f = 0; f < 16; f++) {
            oc[f][0] *= corr_lo; oc[f][1] *= corr_lo;
            oc[f][2] *= corr_hi; oc[f][3] *= corr_hi;
        }

        // ---- O += P V (2 terms) ----
        const uint32_t vh_h = 2 * QPH + (t % 3) * 2 * KVPH + KVPH;   // halves
        const int vrow = lane & 15;
        const int vcol = (lane >> 4) * 8;
        #pragma unroll
        for (int ks = 0; ks < 4; ks++) {
            uint32_t a_h[4] = {ph01[2 * ks], ph23[2 * ks],
                               ph01[2 * ks + 1], ph23[2 * ks + 1]};
            uint32_t a_l[4] = {pl01[2 * ks], pl23[2 * ks],
                               pl01[2 * ks + 1], pl23[2 * ks + 1]};
            const int vr = ks * 16 + vrow;
            #pragma unroll
            for (int jp = 0; jp < 8; jp++) {
                uint32_t r0, r1, r2, r3;
                uint32_t vaddr = sb + (vh_h + vr * KSH + jp * 16 + vcol) * 2;
                ldsm_x4_t(r0, r1, r2, r3, vaddr);
                uint32_t bh0[2] = {r0, r1}, bh1[2] = {r2, r3};
                mma_f16(oc[2 * jp],     a_h, bh0);
                mma_f16(oc[2 * jp + 1], a_h, bh1);
                mma_f16(oc[2 * jp],     a_l, bh0);
                mma_f16(oc[2 * jp + 1], a_l, bh1);
            }
        }
    }
    CP_WAIT(0);

    // ---- epilogue: write fp16 hi/lo planes directly ----
    const float inv_lo = 1.0f / l_lo;
    const float inv_hi = 1.0f / l_hi;
    const size_t orow = ((size_t)(b * S_ + q0 + wm + lr)) * D_ + h * HD_;
    #pragma unroll
    for (int f = 0; f < 16; f++) {
        const int hd = f * 8 + 2 * lc;
        float v0 = oc[f][0] * inv_lo, v1 = oc[f][1] * inv_lo;
        float v2 = oc[f][2] * inv_hi, v3 = oc[f][3] * inv_hi;
        __half2 h01 = __floats2half2_rn(v0, v1);
        __half2 h23 = __floats2half2_rn(v2, v3);
        *(uint32_t*)(Oah + orow + hd)                  = *reinterpret_cast<uint32_t*>(&h01);
        *(uint32_t*)(Oah + orow + (size_t)8 * D_ + hd) = *reinterpret_cast<uint32_t*>(&h23);
        *(uint32_t*)(Oal + orow + hd) =
            pack_f2(v0 - __low2float(h01), v1 - __high2float(h01));
        *(uint32_t*)(Oal + orow + (size_t)8 * D_ + hd) =
            pack_f2(v2 - __low2float(h23), v3 - __high2float(h23));
    }
}

// ---------------- kernel_launch ---------------------------------------------
extern "C" void kernel_launch(void* const* d_in, const int* in_sizes, int n_in,
                              void* d_out, int out_size)
{
    const float* hidden = (const float*)d_in[0];
    const float* rot    = (const float*)d_in[1];
    const float* Wq = (const float*)d_in[2];
    const float* bq = (const float*)d_in[3];
    const float* Wk = (const float*)d_in[4];
    const float* bk = (const float*)d_in[5];
    const float* Wv = (const float*)d_in[6];
    const float* bv = (const float*)d_in[7];
    const float* gq = (const float*)d_in[8];
    const float* gk = (const float*)d_in[9];
    const float* Wo = (const float*)d_in[10];
    const float* bo = (const float*)d_in[11];
    const int*   ctx  = (const int*)d_in[12];
    const int*   nseq = (const int*)d_in[13];
    float* out = (float*)d_out;

    float *q, *k;
    __half *xh, *xl, *ah, *al, *wh, *qh, *ql, *kh, *vh;
    cudaGetSymbolAddress((void**)&q, g_q);
    cudaGetSymbolAddress((void**)&k, g_k);
    cudaGetSymbolAddress((void**)&xh, g_xh);
    cudaGetSymbolAddress((void**)&xl, g_xl);
    cudaGetSymbolAddress((void**)&ah, g_ah);
    cudaGetSymbolAddress((void**)&al, g_al);
    cudaGetSymbolAddress((void**)&wh, g_wh);
    cudaGetSymbolAddress((void**)&qh, g_qh);
    cudaGetSymbolAddress((void**)&ql, g_ql);
    cudaGetSymbolAddress((void**)&kh, g_kh);
    cudaGetSymbolAddress((void**)&vh, g_vh);

    const int nX = M_ * D_, nW = D_ * D_;

    split_fp16<<<nX / 1024, 256>>>(hidden, xh, xl, nX);
    cvt_f16_4<<<dim3(nW / 1024, 4), 256>>>(Wq, Wk, Wv, Wo, wh, nW);

    cudaFuncSetAttribute(gemm_f16_n256, cudaFuncAttributeMaxDynamicSharedMemorySize,
                         GEMM2_SMEM);

    // Fused QKV projections: z = 0 -> q (f32), 1 -> k (f32), 2 -> v (fp16)
    gemm_f16_n256<<<dim3(D_ / 256, M_ / 128, 3), 256, GEMM2_SMEM>>>(
        xh, xl, wh, bq, bk, bv, q, k, vh);

    rms_rope_split<<<dim3(M_, 2), 256>>>(q, k, gq, gk, rot, qh, ql, kh);

    cudaFuncSetAttribute(attn_f16, cudaFuncAttributeMaxDynamicSharedMemorySize,
                         ATT_SMEM);
    attn_f16<<<dim3(NQT, H_, B_), 256, ATT_SMEM>>>(qh, ql, kh, vh,
                                                   ah, al, ctx, nseq);

    // Output projection (z = 0 path -> float out)
    gemm_f16_n256<<<dim3(D_ / 256, M_ / 128, 1), 256, GEMM2_SMEM>>>(
        ah, al, wh + 3 * (size_t)nW, bo, bo, bo, out, nullptr, nullptr);
}

// round 12
// speedup vs baseline: 4.6176x; 1.0015x over previous
#include <cuda_runtime.h>
#include <cuda_fp16.h>
#include <cstdint>

#define B_   2
#define S_   3072
#define D_   2048
#define H_   16
#define HD_  128
#define M_   (B_ * S_)     // 6144 tokens

// ---------------- scratch (no allocation anywhere) -------------------------
__device__ float  g_q[M_ * D_];
__device__ float  g_k[M_ * D_];
__device__ __half g_xh[M_ * D_], g_xl[M_ * D_];         // hidden hi/lo
__device__ __half g_ah[M_ * D_], g_al[M_ * D_];         // attn-out hi/lo
__device__ __half g_wh[4 * D_ * D_];                    // Wq,Wk,Wv,Wo fp16
__device__ __half g_qh[M_ * D_], g_ql[M_ * D_];
__device__ __half g_kh[M_ * D_];
__device__ __half g_vh[M_ * D_];

// ---------------- helpers ----------------------------------------------------
__device__ __forceinline__ uint32_t smem_u32(const void* p) {
    uint32_t a;
    asm("{ .reg .u64 t; cvta.to.shared.u64 t, %1; cvt.u32.u64 %0, t; }"
        : "=r"(a) : "l"(p));
    return a;
}
__device__ __forceinline__ void mma_f16(float c[4], const uint32_t a[4],
                                        const uint32_t b[2]) {
    asm volatile(
        "mma.sync.aligned.m16n8k16.row.col.f32.f16.f16.f32 "
        "{%0,%1,%2,%3}, {%4,%5,%6,%7}, {%8,%9}, {%0,%1,%2,%3};"
        : "+f"(c[0]), "+f"(c[1]), "+f"(c[2]), "+f"(c[3])
        : "r"(a[0]), "r"(a[1]), "r"(a[2]), "r"(a[3]), "r"(b[0]), "r"(b[1]));
}
__device__ __forceinline__ void ldsm_x4(uint32_t& r0, uint32_t& r1,
                                        uint32_t& r2, uint32_t& r3, uint32_t a) {
    asm volatile("ldmatrix.sync.aligned.m8n8.x4.shared.b16 {%0,%1,%2,%3}, [%4];"
                 : "=r"(r0), "=r"(r1), "=r"(r2), "=r"(r3) : "r"(a));
}
__device__ __forceinline__ void ldsm_x4_t(uint32_t& r0, uint32_t& r1,
                                          uint32_t& r2, uint32_t& r3, uint32_t a) {
    asm volatile("ldmatrix.sync.aligned.m8n8.x4.trans.shared.b16 "
                 "{%0,%1,%2,%3}, [%4];"
                 : "=r"(r0), "=r"(r1), "=r"(r2), "=r"(r3) : "r"(a));
}
__device__ __forceinline__ uint32_t pack_h2(__half a, __half b) {
    __half2 t = __halves2half2(a, b);
    return *reinterpret_cast<uint32_t*>(&t);
}
__device__ __forceinline__ uint32_t pack_f2(float a, float b) {
    __half2 t = __floats2half2_rn(a, b);
    return *reinterpret_cast<uint32_t*>(&t);
}
#define CP_ASYNC16(s, g) \
    asm volatile("cp.async.cg.shared.global [%0], [%1], 16;" :: "r"(s), "l"(g))
#define CP_COMMIT()  asm volatile("cp.async.commit_group;" ::: "memory")
#define CP_WAIT(n)   asm volatile("cp.async.wait_group %0;" :: "n"(n) : "memory")

// ---------------- split fp32 -> fp16 hi/lo -----------------------------------
__global__ void __launch_bounds__(256) split_fp16(
    const float* __restrict__ in, __half* __restrict__ hp, __half* __restrict__ lp,
    int n)
{
    int i = (blockIdx.x * 256 + threadIdx.x) * 4;
    if (i >= n) return;
    float4 v = *(const float4*)(in + i);
    float x[4] = {v.x, v.y, v.z, v.w};
    __half h[4];
    float  r[4];
    #pragma unroll
    for (int j = 0; j < 4; j++) {
        h[j] = __float2half_rn(x[j]);
        r[j] = x[j] - __half2float(h[j]);
    }
    *(uint32_t*)(hp + i)     = pack_h2(h[0], h[1]);
    *(uint32_t*)(hp + i + 2) = pack_h2(h[2], h[3]);
    *(uint32_t*)(lp + i)     = pack_f2(r[0], r[1]);
    *(uint32_t*)(lp + i + 2) = pack_f2(r[2], r[3]);
}

// ---------------- convert 4 weight matrices fp32 -> fp16 (one launch) -------
__global__ void __launch_bounds__(256) cvt_f16_4(
    const float* __restrict__ w0, const float* __restrict__ w1,
    const float* __restrict__ w2, const float* __restrict__ w3,
    __half* __restrict__ out, int n)
{
    const int z = blockIdx.y;
    const float* in = (z == 0) ? w0 : (z == 1) ? w1 : (z == 2) ? w2 : w3;
    __half* o = out + (size_t)z * n;
    int i = (blockIdx.x * 256 + threadIdx.x) * 4;
    if (i >= n) return;
    float4 v = *(const float4*)(in + i);
    *(uint32_t*)(o + i)     = pack_f2(v.x, v.y);
    *(uint32_t*)(o + i + 2) = pack_f2(v.z, v.w);
}

// ---------------------------------------------------------------------------
// fp16 2-term tensor GEMM: O[m,n] = sum_k (Ah+Al)[m,k] * W16[n,k] + bias[n]
// A split hi/lo fp16; W single fp16 plane.  128x256 CTA tile, ldmatrix frags,
// cp.async 3-stage with BK=64.  Inner loop split into hi-pass / lo-pass so
// consecutive mmas on the same accumulator are >=4 apart (same per-acc order).
// ---------------------------------------------------------------------------
#define G2_BK   64
#define G2_STR  72                        // halves per smem row (144 B)
#define G2_APLH (128 * G2_STR)            // 9216 halves
#define G2_BPLH (256 * G2_STR)            // 18432 halves
#define G2_STGH (2 * G2_APLH + G2_BPLH)   // 36864 halves / stage
#define GEMM2_SMEM (3 * G2_STGH * 2)      // 221184 bytes
#define G2_NS   (D_ / G2_BK)              // 32 stages

__global__ void __launch_bounds__(256, 1) gemm_f16_n256(
    const __half* __restrict__ Ahg, const __half* __restrict__ Alg,
    const __half* __restrict__ WhB,
    const float* __restrict__ b0p, const float* __restrict__ b1p,
    const float* __restrict__ b2p,
    float* __restrict__ o0, float* __restrict__ o1, __half* __restrict__ o2)
{
    extern __shared__ __align__(16) __half g2sm[];
    const uint32_t sb = smem_u32(g2sm);

    const int z    = blockIdx.z;
    const __half* Bhg = WhB + (size_t)z * D_ * D_;
    const float* bias = (z == 0) ? b0p : (z == 1) ? b1p : b2p;

    const int bm   = blockIdx.y * 128;
    const int bn   = blockIdx.x * 256;
    const int tid  = threadIdx.x;
    const int warp = tid >> 5;
    const int lane = tid & 31;
    const int lr   = lane >> 2;
    const int lc   = lane & 3;
    const int g    = lane >> 3;
    const int sub  = lane & 7;
    const int wm   = (warp & 1) * 64;
    const int wn   = (warp >> 1) * 64;

    int aoff[4], boff[4];
    #pragma unroll
    for (int mi = 0; mi < 4; mi++)
        aoff[mi] = (wm + mi * 16 + (g & 1) * 8 + sub) * G2_STR + (g >> 1) * 8;
    #pragma unroll
    for (int nip = 0; nip < 4; nip++)
        boff[nip] = (wn + nip * 16 + (g >> 1) * 8 + sub) * G2_STR + (g & 1) * 8;

    auto load_stage = [&](int s, int buf) {
        const int kt = s * G2_BK;
        const uint32_t stg = buf * G2_STGH;
        #pragma unroll
        for (int i = 0; i < 16; i++) {
            const int idx = i * 256 + tid;        // 0..4095
            uint32_t dsth;
            const __half* src;
            if (idx < 2048) {                     // A planes (hi, lo)
                const int pl = idx >> 10, w = idx & 1023;
                const int row = w >> 3, c = w & 7;
                dsth = stg + pl * G2_APLH + row * G2_STR + c * 8;
                src = (pl ? Alg : Ahg) + (size_t)(bm + row) * D_ + kt + c * 8;
            } else {                               // W plane
                const int j = idx - 2048;
                const int row = j >> 3, c = j & 7;
                dsth = stg + 2 * G2_APLH + row * G2_STR + c * 8;
                src = Bhg + (size_t)(bn + row) * D_ + kt + c * 8;
            }
            CP_ASYNC16(sb + dsth * 2, src);
        }
        CP_COMMIT();
    };

    float acc[4][8][4];
    #pragma unroll
    for (int mi = 0; mi < 4; mi++)
        #pragma unroll
        for (int ni = 0; ni < 8; ni++)
            #pragma unroll
            for (int r = 0; r < 4; r++) acc[mi][ni][r] = 0.0f;

    load_stage(0, 0);
    load_stage(1, 1);

    for (int s = 0; s < G2_NS; s++) {
        if (s + 1 < G2_NS) { CP_WAIT(1); } else { CP_WAIT(0); }
        __syncthreads();
        if (s + 2 < G2_NS) load_stage(s + 2, (s + 2) % 3);

        const uint32_t stg = (s % 3) * G2_STGH;
        #pragma unroll
        for (int kk = 0; kk < 4; kk++) {
            const int kh = kk * 16;
            uint32_t ah[4][4], al[4][4];
            #pragma unroll
            for (int mi = 0; mi < 4; mi++) {
                ldsm_x4(ah[mi][0], ah[mi][1], ah[mi][2], ah[mi][3],
                        sb + (stg + aoff[mi] + kh) * 2);
                ldsm_x4(al[mi][0], al[mi][1], al[mi][2], al[mi][3],
                        sb + (stg + G2_APLH + aoff[mi] + kh) * 2);
            }
            #pragma unroll
            for (int nip = 0; nip < 4; nip++) {
                uint32_t bh[4];
                ldsm_x4(bh[0], bh[1], bh[2], bh[3],
                        sb + (stg + 2 * G2_APLH + boff[nip] + kh) * 2);
                uint32_t bh01[2] = {bh[0], bh[1]}, bh23[2] = {bh[2], bh[3]};
                // hi pass (distance-4 between dependent mmas)
                #pragma unroll
                for (int mi = 0; mi < 4; mi++)
                    mma_f16(acc[mi][2 * nip],     ah[mi], bh01);
                #pragma unroll
                for (int mi = 0; mi < 4; mi++)
                    mma_f16(acc[mi][2 * nip + 1], ah[mi], bh23);
                // lo pass (same per-acc order: ah before al)
                #pragma unroll
                for (int mi = 0; mi < 4; mi++)
                    mma_f16(acc[mi][2 * nip],     al[mi], bh01);
                #pragma unroll
                for (int mi = 0; mi < 4; mi++)
                    mma_f16(acc[mi][2 * nip + 1], al[mi], bh23);
            }
        }
    }

    // epilogue
    #pragma unroll
    for (int ni = 0; ni < 8; ni++) {
        const int c = bn + wn + ni * 8 + 2 * lc;
        const float bb0 = __ldg(bias + c);
        const float bb1 = __ldg(bias + c + 1);
        #pragma unroll
        for (int mi = 0; mi < 4; mi++) {
            const int r = bm + wm + mi * 16 + lr;
            const float v00 = acc[mi][ni][0] + bb0;
            const float v01 = acc[mi][ni][1] + bb1;
            const float v10 = acc[mi][ni][2] + bb0;
            const float v11 = acc[mi][ni][3] + bb1;
            if (z == 2) {
                *(uint32_t*)(o2 + (size_t)r * D_ + c)       = pack_f2(v00, v01);
                *(uint32_t*)(o2 + (size_t)(r + 8) * D_ + c) = pack_f2(v10, v11);
            } else {
                float* Of = (z == 0) ? o0 : o1;
                *(float2*)(Of + (size_t)r * D_ + c)       = float2{v00, v01};
                *(float2*)(Of + (size_t)(r + 8) * D_ + c) = float2{v10, v11};
            }
        }
    }
}

// ---------------------------------------------------------------------------
// RMSNorm + interleaved RoPE -> fp16 planes: qh+ql (q scaled 1/sqrt(HD)), kh.
// ---------------------------------------------------------------------------
__global__ void __launch_bounds__(256) rms_rope_split(
    const float* __restrict__ Tq, const float* __restrict__ Tk,
    const float* __restrict__ gq, const float* __restrict__ gk,
    const float* __restrict__ rot,
    __half* __restrict__ qh, __half* __restrict__ ql,
    __half* __restrict__ kh)
{
    const int token = blockIdx.x;
    const int s     = token % S_;
    const bool isq  = (blockIdx.y == 0);
    const float* T  = isq ? Tq : Tk;
    const float* g  = isq ? gq : gk;
    const float post = isq ? 0.08838834764831845f : 1.0f;
    const int t = threadIdx.x;

    const float* row = T + (size_t)token * D_;
    float4 v0 = *(const float4*)(row + t * 8);
    float4 v1 = *(const float4*)(row + t * 8 + 4);
    float x[8] = {v0.x, v0.y, v0.z, v0.w, v1.x, v1.y, v1.z, v1.w};

    float ss = 0.0f;
    #pragma unroll
    for (int i = 0; i < 8; i++) ss += x[i] * x[i];
    #pragma unroll
    for (int o = 16; o; o >>= 1) ss += __shfl_xor_sync(0xffffffffu, ss, o);

    __shared__ float red[8];
    __shared__ float rs_s;
    if ((t & 31) == 0) red[t >> 5] = ss;
    __syncthreads();
    if (t == 0) {
        float tot = 0.0f;
        #pragma unroll
        for (int i = 0; i < 8; i++) tot += red[i];
        rs_s = rsqrtf(tot * (1.0f / (float)D_) + 1e-6f);
    }
    __syncthreads();
    const float rs = rs_s;

    const float* rc = rot + (size_t)s * (2 * HD_);
    float out[8];
    #pragma unroll
    for (int j = 0; j < 4; j++) {
        const int d0 = t * 8 + 2 * j;
        const int i2 = d0 & (HD_ - 1);
        const float c  = rc[i2];
        const float sn = rc[HD_ + i2 + 1];
        const float x1 = x[2 * j]     * rs * g[d0];
        const float x2 = x[2 * j + 1] * rs * g[d0 + 1];
        out[2 * j]     = (x1 * c - x2 * sn) * post;
        out[2 * j + 1] = (x1 * sn + x2 * c) * post;
    }

    if (isq) {
        uint32_t* hd = (uint32_t*)(qh + (size_t)token * D_ + t * 8);
        uint32_t* ld = (uint32_t*)(ql + (size_t)token * D_ + t * 8);
        #pragma unroll
        for (int j = 0; j < 4; j++) {
            __half h0 = __float2half_rn(out[2 * j]);
            __half h1 = __float2half_rn(out[2 * j + 1]);
            hd[j] = pack_h2(h0, h1);
            ld[j] = pack_f2(out[2 * j]     - __half2float(h0),
                            out[2 * j + 1] - __half2float(h1));
        }
    } else {
        uint32_t* hd = (uint32_t*)(kh + (size_t)token * D_ + t * 8);
        #pragma unroll
        for (int j = 0; j < 4; j++)
            hd[j] = pack_f2(out[2 * j], out[2 * j + 1]);
    }
}

// ---------------------------------------------------------------------------
// fp16 tensor flash attention, 2-term QK + 2-term PV, ldmatrix frag loads.
// Static-shift softmax: scores are bounded (RMS-normed q/k, |s| <~ 12), so
// p = exp(s - 5) with a clamp at +11 (p <= 6e4 < fp16 max; clamp never fires
// for real data => exact softmax).  No online max, no corr rescale.
// ---------------------------------------------------------------------------
#define AQ 128
#define AK 64
#define NQT (S_ / AQ)                  // 24 q-tiles
#define KSH 136                        // halves per smem row (272 B)
#define QPH (128 * KSH)                // halves per Q plane
#define KVPH (64 * KSH)                // halves per KV plane
#define ATT_SMEM ((2 * QPH + 6 * KVPH) * 2)   // 174080 bytes
#define MAXS 5.0f

__global__ void __launch_bounds__(256, 1) attn_f16(
    const __half* __restrict__ Qh, const __half* __restrict__ Ql,
    const __half* __restrict__ Kh, const __half* __restrict__ Vh,
    __half* __restrict__ Oah, __half* __restrict__ Oal,
    const int* __restrict__ ctxp, const int* __restrict__ nseqp)
{
    extern __shared__ __align__(16) __half smh[];
    const uint32_t sb = smem_u32(smh);

    const int tid  = threadIdx.x;
    const int warp = tid >> 5;
    const int lane = tid & 31;
    const int lr   = lane >> 2;
    const int lc   = lane & 3;
    const int g    = lane >> 3;
    const int sub  = lane & 7;
    const int h    = blockIdx.y;
    const int b    = blockIdx.z;
    const int hist = (S_ - ctxp[0]) / nseqp[0];

    // heavy-first q-tile ordering
    const int qt   = (blockIdx.x + (hist / AQ)) % NQT;
    const int q0   = qt * AQ;

    const int wm = warp * 16;
    const int q_lo = q0 + wm + lr;
    const int kvlen_lo = (q_lo < hist) ? hist : S_;
    const int kvlen_hi = (q_lo + 8 < hist) ? hist : S_;
    const int kv_end = (q0 + AQ <= hist) ? hist : S_;
    const int ntiles = (kv_end + AK - 1) / AK;

    const int qrow_off = (wm + (g & 1) * 8 + sub) * KSH + (g >> 1) * 8;
    const int krow_off = ((g >> 1) * 8 + sub) * KSH + (g & 1) * 8;

    // ---- stage Q (hi+lo planes) ----
    const size_t qoff = ((size_t)(b * S_ + q0)) * D_ + h * HD_;
    #pragma unroll
    for (int i = 0; i < 16; i++) {
        int idx = i * 256 + tid;
        int pl = idx >> 11, w = idx & 2047, r = w >> 4, c = w & 15;
        uint32_t dst = sb + (pl * QPH + r * KSH + c * 8) * 2;
        const __half* src = (pl ? Ql : Qh) + qoff + (size_t)r * D_ + c * 8;
        CP_ASYNC16(dst, src);
    }
    CP_COMMIT();

    const size_t kvo = ((size_t)(b * S_)) * D_ + h * HD_;
    const __half* Khp = Kh + kvo;
    const __half* Vhp = Vh + kvo;

    auto load_kv = [&](int kt, int bi) {
        const uint32_t baseh = 2 * QPH + bi * 2 * KVPH;
        #pragma unroll
        for (int i = 0; i < 8; i++) {
            int idx = i * 256 + tid;
            int pl = idx >> 10, w = idx & 1023, r = w >> 4, c = w & 15;
            const __half* s = pl ? Vhp : Khp;
            uint32_t dst = sb + (baseh + pl * KVPH + r * KSH + c * 8) * 2;
            CP_ASYNC16(dst, s + (size_t)(kt + r) * D_ + c * 8);
        }
        CP_COMMIT();
    };

    load_kv(0, 0);
    load_kv(AK, 1);

    float oc[16][4];
    #pragma unroll
    for (int f = 0; f < 16; f++)
        #pragma unroll
        for (int e = 0; e < 4; e++) oc[f][e] = 0.0f;
    float l_lo = 0.0f, l_hi = 0.0f;

    for (int t = 0; t < ntiles; t++) {
        const int kt = t * AK;
        if (t + 1 < ntiles) { CP_WAIT(1); } else { CP_WAIT(0); }
        __syncthreads();
        if (t + 2 < ntiles) load_kv((t + 2) * AK, (t + 2) % 3);

        const uint32_t kbaseH = 2 * QPH + (t % 3) * 2 * KVPH;  // halves

        // ---- S = Q K^T (2 terms, dependent mmas spaced) ----
        float sc[8][4];
        #pragma unroll
        for (int j = 0; j < 8; j++)
            #pragma unroll
            for (int e = 0; e < 4; e++) sc[j][e] = 0.0f;

        #pragma unroll
        for (int kd = 0; kd < 8; kd++) {
            uint32_t a_h[4], a_l[4];
            ldsm_x4(a_h[0], a_h[1], a_h[2], a_h[3],
                    sb + (qrow_off + kd * 16) * 2);
            ldsm_x4(a_l[0], a_l[1], a_l[2], a_l[3],
                    sb + (QPH + qrow_off + kd * 16) * 2);
            #pragma unroll
            for (int jp = 0; jp < 4; jp++) {
                uint32_t kb[4];
                ldsm_x4(kb[0], kb[1], kb[2], kb[3],
                        sb + (kbaseH + jp * 16 * KSH + krow_off + kd * 16) * 2);
                uint32_t b01[2] = {kb[0], kb[1]}, b23[2] = {kb[2], kb[3]};
                mma_f16(sc[2 * jp],     a_h, b01);
                mma_f16(sc[2 * jp + 1], a_h, b23);
                mma_f16(sc[2 * jp],     a_l, b01);
                mma_f16(sc[2 * jp + 1], a_l, b23);
            }
        }

        // ---- mask ----
        if (kt + AK > kvlen_lo || kt + AK > kvlen_hi) {
            #pragma unroll
            for (int j = 0; j < 8; j++) {
                const int c0 = kt + j * 8 + 2 * lc;
                if (c0     >= kvlen_lo) sc[j][0] = -1e30f;
                if (c0 + 1 >= kvlen_lo) sc[j][1] = -1e30f;
                if (c0     >= kvlen_hi) sc[j][2] = -1e30f;
                if (c0 + 1 >= kvlen_hi) sc[j][3] = -1e30f;
            }
        }

        // ---- static-shift softmax: p = exp(s - MAXS), clamp guard ----
        uint32_t ph01[8], ph23[8], pl01[8], pl23[8];
        float s_lo = 0.0f, s_hi = 0.0f;
        #pragma unroll
        for (int j = 0; j < 8; j++) {
            float p0 = __expf(fminf(sc[j][0] - MAXS, 11.0f));
            float p1 = __expf(fminf(sc[j][1] - MAXS, 11.0f));
            float p2 = __expf(fminf(sc[j][2] - MAXS, 11.0f));
            float p3 = __expf(fminf(sc[j][3] - MAXS, 11.0f));
            s_lo += p0 + p1; s_hi += p2 + p3;
            __half2 h01 = __floats2half2_rn(p0, p1);
            __half2 h23 = __floats2half2_rn(p2, p3);
            ph01[j] = *reinterpret_cast<uint32_t*>(&h01);
            ph23[j] = *reinterpret_cast<uint32_t*>(&h23);
            pl01[j] = pack_f2(p0 - __low2float(h01), p1 - __high2float(h01));
            pl23[j] = pack_f2(p2 - __low2float(h23), p3 - __high2float(h23));
        }
        s_lo += __shfl_xor_sync(0xffffffffu, s_lo, 1);
        s_lo += __shfl_xor_sync(0xffffffffu, s_lo, 2);
        s_hi += __shfl_xor_sync(0xffffffffu, s_hi, 1);
        s_hi += __shfl_xor_sync(0xffffffffu, s_hi, 2);
        l_lo += s_lo;
        l_hi += s_hi;

        // ---- O += P V (2 terms) ----
        const uint32_t vh_h = 2 * QPH + (t % 3) * 2 * KVPH + KVPH;   // halves
        const int vrow = lane & 15;
        const int vcol = (lane >> 4) * 8;
        #pragma unroll
        for (int ks = 0; ks < 4; ks++) {
            uint32_t a_h[4] = {ph01[2 * ks], ph23[2 * ks],
                               ph01[2 * ks + 1], ph23[2 * ks + 1]};
            uint32_t a_l[4] = {pl01[2 * ks], pl23[2 * ks],
                               pl01[2 * ks + 1], pl23[2 * ks + 1]};
            const int vr = ks * 16 + vrow;
            #pragma unroll
            for (int jp = 0; jp < 8; jp++) {
                uint32_t r0, r1, r2, r3;
                uint32_t vaddr = sb + (vh_h + vr * KSH + jp * 16 + vcol) * 2;
                ldsm_x4_t(r0, r1, r2, r3, vaddr);
                uint32_t bh0[2] = {r0, r1}, bh1[2] = {r2, r3};
                mma_f16(oc[2 * jp],     a_h, bh0);
                mma_f16(oc[2 * jp + 1], a_h, bh1);
                mma_f16(oc[2 * jp],     a_l, bh0);
                mma_f16(oc[2 * jp + 1], a_l, bh1);
            }
        }
    }
    CP_WAIT(0);

    // ---- epilogue: write fp16 hi/lo planes directly ----
    const float inv_lo = 1.0f / l_lo;
    const float inv_hi = 1.0f / l_hi;
    const size_t orow = ((size_t)(b * S_ + q0 + wm + lr)) * D_ + h * HD_;
    #pragma unroll
    for (int f = 0; f < 16; f++) {
        const int hd = f * 8 + 2 * lc;
        float v0 = oc[f][0] * inv_lo, v1 = oc[f][1] * inv_lo;
        float v2 = oc[f][2] * inv_hi, v3 = oc[f][3] * inv_hi;
        __half2 h01 = __floats2half2_rn(v0, v1);
        __half2 h23 = __floats2half2_rn(v2, v3);
        *(uint32_t*)(Oah + orow + hd)                  = *reinterpret_cast<uint32_t*>(&h01);
        *(uint32_t*)(Oah + orow + (size_t)8 * D_ + hd) = *reinterpret_cast<uint32_t*>(&h23);
        *(uint32_t*)(Oal + orow + hd) =
            pack_f2(v0 - __low2float(h01), v1 - __high2float(h01));
        *(uint32_t*)(Oal + orow + (size_t)8 * D_ + hd) =
            pack_f2(v2 - __low2float(h23), v3 - __high2float(h23));
    }
}

// ---------------- kernel_launch ---------------------------------------------
extern "C" void kernel_launch(void* const* d_in, const int* in_sizes, int n_in,
                              void* d_out, int out_size)
{
    const float* hidden = (const float*)d_in[0];
    const float* rot    = (const float*)d_in[1];
    const float* Wq = (const float*)d_in[2];
    const float* bq = (const float*)d_in[3];
    const float* Wk = (const float*)d_in[4];
    const float* bk = (const float*)d_in[5];
    const float* Wv = (const float*)d_in[6];
    const float* bv = (const float*)d_in[7];
    const float* gq = (const float*)d_in[8];
    const float* gk = (const float*)d_in[9];
    const float* Wo = (const float*)d_in[10];
    const float* bo = (const float*)d_in[11];
    const int*   ctx  = (const int*)d_in[12];
    const int*   nseq = (const int*)d_in[13];
    float* out = (float*)d_out;

    float *q, *k;
    __half *xh, *xl, *ah, *al, *wh, *qh, *ql, *kh, *vh;
    cudaGetSymbolAddress((void**)&q, g_q);
    cudaGetSymbolAddress((void**)&k, g_k);
    cudaGetSymbolAddress((void**)&xh, g_xh);
    cudaGetSymbolAddress((void**)&xl, g_xl);
    cudaGetSymbolAddress((void**)&ah, g_ah);
    cudaGetSymbolAddress((void**)&al, g_al);
    cudaGetSymbolAddress((void**)&wh, g_wh);
    cudaGetSymbolAddress((void**)&qh, g_qh);
    cudaGetSymbolAddress((void**)&ql, g_ql);
    cudaGetSymbolAddress((void**)&kh, g_kh);
    cudaGetSymbolAddress((void**)&vh, g_vh);

    const int nX = M_ * D_, nW = D_ * D_;

    split_fp16<<<nX / 1024, 256>>>(hidden, xh, xl, nX);
    cvt_f16_4<<<dim3(nW / 1024, 4), 256>>>(Wq, Wk, Wv, Wo, wh, nW);

    cudaFuncSetAttribute(gemm_f16_n256, cudaFuncAttributeMaxDynamicSharedMemorySize,
                         GEMM2_SMEM);

    // Fused QKV projections: z = 0 -> q (f32), 1 -> k (f32), 2 -> v (fp16)
    gemm_f16_n256<<<dim3(D_ / 256, M_ / 128, 3), 256, GEMM2_SMEM>>>(
        xh, xl, wh, bq, bk, bv, q, k, vh);

    rms_rope_split<<<dim3(M_, 2), 256>>>(q, k, gq, gk, rot, qh, ql, kh);

    cudaFuncSetAttribute(attn_f16, cudaFuncAttributeMaxDynamicSharedMemorySize,
                         ATT_SMEM);
    attn_f16<<<dim3(NQT, H_, B_), 256, ATT_SMEM>>>(qh, ql, kh, vh,
                                                   ah, al, ctx, nseq);

    // Output projection (z = 0 path -> float out)
    gemm_f16_n256<<<dim3(D_ / 256, M_ / 128, 1), 256, GEMM2_SMEM>>>(
        ah, al, wh + 3 * (size_t)nW, bo, bo, bo, out, nullptr, nullptr);
}

// round 13
// speedup vs baseline: 4.9358x; 1.0689x over previous
#include <cuda_runtime.h>
#include <cuda_fp16.h>
#include <cstdint>

#define B_   2
#define S_   3072
#define D_   2048
#define H_   16
#define HD_  128
#define M_   (B_ * S_)     // 6144 tokens

// ---------------- scratch (no allocation anywhere) -------------------------
__device__ float  g_q[M_ * D_];
__device__ float  g_k[M_ * D_];
__device__ __half g_xh[M_ * D_], g_xl[M_ * D_];         // hidden hi/lo
__device__ __half g_ah[M_ * D_], g_al[M_ * D_];         // attn-out hi/lo
__device__ __half g_wh[4 * D_ * D_];                    // Wq,Wk,Wv,Wo fp16
__device__ __half g_qh[M_ * D_], g_ql[M_ * D_];
__device__ __half g_kh[M_ * D_];
__device__ __half g_vh[M_ * D_];

// ---------------- helpers ----------------------------------------------------
__device__ __forceinline__ uint32_t smem_u32(const void* p) {
    uint32_t a;
    asm("{ .reg .u64 t; cvta.to.shared.u64 t, %1; cvt.u32.u64 %0, t; }"
        : "=r"(a) : "l"(p));
    return a;
}
__device__ __forceinline__ void mma_f16(float c[4], const uint32_t a[4],
                                        const uint32_t b[2]) {
    asm volatile(
        "mma.sync.aligned.m16n8k16.row.col.f32.f16.f16.f32 "
        "{%0,%1,%2,%3}, {%4,%5,%6,%7}, {%8,%9}, {%0,%1,%2,%3};"
        : "+f"(c[0]), "+f"(c[1]), "+f"(c[2]), "+f"(c[3])
        : "r"(a[0]), "r"(a[1]), "r"(a[2]), "r"(a[3]), "r"(b[0]), "r"(b[1]));
}
__device__ __forceinline__ void ldsm_x4(uint32_t& r0, uint32_t& r1,
                                        uint32_t& r2, uint32_t& r3, uint32_t a) {
    asm volatile("ldmatrix.sync.aligned.m8n8.x4.shared.b16 {%0,%1,%2,%3}, [%4];"
                 : "=r"(r0), "=r"(r1), "=r"(r2), "=r"(r3) : "r"(a));
}
__device__ __forceinline__ void ldsm_x4_t(uint32_t& r0, uint32_t& r1,
                                          uint32_t& r2, uint32_t& r3, uint32_t a) {
    asm volatile("ldmatrix.sync.aligned.m8n8.x4.trans.shared.b16 "
                 "{%0,%1,%2,%3}, [%4];"
                 : "=r"(r0), "=r"(r1), "=r"(r2), "=r"(r3) : "r"(a));
}
__device__ __forceinline__ uint32_t pack_h2(__half a, __half b) {
    __half2 t = __halves2half2(a, b);
    return *reinterpret_cast<uint32_t*>(&t);
}
__device__ __forceinline__ uint32_t pack_f2(float a, float b) {
    __half2 t = __floats2half2_rn(a, b);
    return *reinterpret_cast<uint32_t*>(&t);
}
#define CP_ASYNC16(s, g) \
    asm volatile("cp.async.cg.shared.global [%0], [%1], 16;" :: "r"(s), "l"(g))
#define CP_COMMIT()  asm volatile("cp.async.commit_group;" ::: "memory")
#define CP_WAIT(n)   asm volatile("cp.async.wait_group %0;" :: "n"(n) : "memory")

// ---------------- split fp32 -> fp16 hi/lo -----------------------------------
__global__ void __launch_bounds__(256) split_fp16(
    const float* __restrict__ in, __half* __restrict__ hp, __half* __restrict__ lp,
    int n)
{
    int i = (blockIdx.x * 256 + threadIdx.x) * 4;
    if (i >= n) return;
    float4 v = *(const float4*)(in + i);
    float x[4] = {v.x, v.y, v.z, v.w};
    __half h[4];
    float  r[4];
    #pragma unroll
    for (int j = 0; j < 4; j++) {
        h[j] = __float2half_rn(x[j]);
        r[j] = x[j] - __half2float(h[j]);
    }
    *(uint32_t*)(hp + i)     = pack_h2(h[0], h[1]);
    *(uint32_t*)(hp + i + 2) = pack_h2(h[2], h[3]);
    *(uint32_t*)(lp + i)     = pack_f2(r[0], r[1]);
    *(uint32_t*)(lp + i + 2) = pack_f2(r[2], r[3]);
}

// ---------------- convert 4 weight matrices fp32 -> fp16 (one launch) -------
__global__ void __launch_bounds__(256) cvt_f16_4(
    const float* __restrict__ w0, const float* __restrict__ w1,
    const float* __restrict__ w2, const float* __restrict__ w3,
    __half* __restrict__ out, int n)
{
    const int z = blockIdx.y;
    const float* in = (z == 0) ? w0 : (z == 1) ? w1 : (z == 2) ? w2 : w3;
    __half* o = out + (size_t)z * n;
    int i = (blockIdx.x * 256 + threadIdx.x) * 4;
    if (i >= n) return;
    float4 v = *(const float4*)(in + i);
    *(uint32_t*)(o + i)     = pack_f2(v.x, v.y);
    *(uint32_t*)(o + i + 2) = pack_f2(v.z, v.w);
}

// ---------------------------------------------------------------------------
// fp16 2-term tensor GEMM: O[m,n] = sum_k (Ah+Al)[m,k] * W16[n,k] + bias[n]
// A split hi/lo fp16; W single fp16 plane.  128x256 CTA tile, ldmatrix frags,
// cp.async 3-stage with BK=64.
// ---------------------------------------------------------------------------
#define G2_BK   64
#define G2_STR  72                        // halves per smem row (144 B)
#define G2_APLH (128 * G2_STR)            // 9216 halves
#define G2_BPLH (256 * G2_STR)            // 18432 halves
#define G2_STGH (2 * G2_APLH + G2_BPLH)   // 36864 halves / stage
#define GEMM2_SMEM (3 * G2_STGH * 2)      // 221184 bytes
#define G2_NS   (D_ / G2_BK)              // 32 stages

__global__ void __launch_bounds__(256, 1) gemm_f16_n256(
    const __half* __restrict__ Ahg, const __half* __restrict__ Alg,
    const __half* __restrict__ WhB,
    const float* __restrict__ b0p, const float* __restrict__ b1p,
    const float* __restrict__ b2p,
    float* __restrict__ o0, float* __restrict__ o1, __half* __restrict__ o2)
{
    extern __shared__ __align__(16) __half g2sm[];
    const uint32_t sb = smem_u32(g2sm);

    const int z    = blockIdx.z;
    const __half* Bhg = WhB + (size_t)z * D_ * D_;
    const float* bias = (z == 0) ? b0p : (z == 1) ? b1p : b2p;

    const int bm   = blockIdx.y * 128;
    const int bn   = blockIdx.x * 256;
    const int tid  = threadIdx.x;
    const int warp = tid >> 5;
    const int lane = tid & 31;
    const int lr   = lane >> 2;
    const int lc   = lane & 3;
    const int g    = lane >> 3;
    const int sub  = lane & 7;
    const int wm   = (warp & 1) * 64;
    const int wn   = (warp >> 1) * 64;

    int aoff[4], boff[4];
    #pragma unroll
    for (int mi = 0; mi < 4; mi++)
        aoff[mi] = (wm + mi * 16 + (g & 1) * 8 + sub) * G2_STR + (g >> 1) * 8;
    #pragma unroll
    for (int nip = 0; nip < 4; nip++)
        boff[nip] = (wn + nip * 16 + (g >> 1) * 8 + sub) * G2_STR + (g & 1) * 8;

    auto load_stage = [&](int s, int buf) {
        const int kt = s * G2_BK;
        const uint32_t stg = buf * G2_STGH;
        #pragma unroll
        for (int i = 0; i < 16; i++) {
            const int idx = i * 256 + tid;        // 0..4095
            uint32_t dsth;
            const __half* src;
            if (idx < 2048) {                     // A planes (hi, lo)
                const int pl = idx >> 10, w = idx & 1023;
                const int row = w >> 3, c = w & 7;
                dsth = stg + pl * G2_APLH + row * G2_STR + c * 8;
                src = (pl ? Alg : Ahg) + (size_t)(bm + row) * D_ + kt + c * 8;
            } else {                               // W plane
                const int j = idx - 2048;
                const int row = j >> 3, c = j & 7;
                dsth = stg + 2 * G2_APLH + row * G2_STR + c * 8;
                src = Bhg + (size_t)(bn + row) * D_ + kt + c * 8;
            }
            CP_ASYNC16(sb + dsth * 2, src);
        }
        CP_COMMIT();
    };

    float acc[4][8][4];
    #pragma unroll
    for (int mi = 0; mi < 4; mi++)
        #pragma unroll
        for (int ni = 0; ni < 8; ni++)
            #pragma unroll
            for (int r = 0; r < 4; r++) acc[mi][ni][r] = 0.0f;

    load_stage(0, 0);
    load_stage(1, 1);

    for (int s = 0; s < G2_NS; s++) {
        if (s + 1 < G2_NS) { CP_WAIT(1); } else { CP_WAIT(0); }
        __syncthreads();
        if (s + 2 < G2_NS) load_stage(s + 2, (s + 2) % 3);

        const uint32_t stg = (s % 3) * G2_STGH;
        #pragma unroll
        for (int kk = 0; kk < 4; kk++) {
            const int kh = kk * 16;
            uint32_t ah[4][4], al[4][4];
            #pragma unroll
            for (int mi = 0; mi < 4; mi++) {
                ldsm_x4(ah[mi][0], ah[mi][1], ah[mi][2], ah[mi][3],
                        sb + (stg + aoff[mi] + kh) * 2);
                ldsm_x4(al[mi][0], al[mi][1], al[mi][2], al[mi][3],
                        sb + (stg + G2_APLH + aoff[mi] + kh) * 2);
            }
            #pragma unroll
            for (int nip = 0; nip < 4; nip++) {
                uint32_t bh[4];
                ldsm_x4(bh[0], bh[1], bh[2], bh[3],
                        sb + (stg + 2 * G2_APLH + boff[nip] + kh) * 2);
                uint32_t bh01[2] = {bh[0], bh[1]}, bh23[2] = {bh[2], bh[3]};
                #pragma unroll
                for (int mi = 0; mi < 4; mi++)
                    mma_f16(acc[mi][2 * nip],     ah[mi], bh01);
                #pragma unroll
                for (int mi = 0; mi < 4; mi++)
                    mma_f16(acc[mi][2 * nip + 1], ah[mi], bh23);
                #pragma unroll
                for (int mi = 0; mi < 4; mi++)
                    mma_f16(acc[mi][2 * nip],     al[mi], bh01);
                #pragma unroll
                for (int mi = 0; mi < 4; mi++)
                    mma_f16(acc[mi][2 * nip + 1], al[mi], bh23);
            }
        }
    }

    // epilogue
    #pragma unroll
    for (int ni = 0; ni < 8; ni++) {
        const int c = bn + wn + ni * 8 + 2 * lc;
        const float bb0 = __ldg(bias + c);
        const float bb1 = __ldg(bias + c + 1);
        #pragma unroll
        for (int mi = 0; mi < 4; mi++) {
            const int r = bm + wm + mi * 16 + lr;
            const float v00 = acc[mi][ni][0] + bb0;
            const float v01 = acc[mi][ni][1] + bb1;
            const float v10 = acc[mi][ni][2] + bb0;
            const float v11 = acc[mi][ni][3] + bb1;
            if (z == 2) {
                *(uint32_t*)(o2 + (size_t)r * D_ + c)       = pack_f2(v00, v01);
                *(uint32_t*)(o2 + (size_t)(r + 8) * D_ + c) = pack_f2(v10, v11);
            } else {
                float* Of = (z == 0) ? o0 : o1;
                *(float2*)(Of + (size_t)r * D_ + c)       = float2{v00, v01};
                *(float2*)(Of + (size_t)(r + 8) * D_ + c) = float2{v10, v11};
            }
        }
    }
}

// ---------------------------------------------------------------------------
// RMSNorm + interleaved RoPE -> fp16 planes: qh+ql (q scaled 1/sqrt(HD)), kh.
// ---------------------------------------------------------------------------
__global__ void __launch_bounds__(256) rms_rope_split(
    const float* __restrict__ Tq, const float* __restrict__ Tk,
    const float* __restrict__ gq, const float* __restrict__ gk,
    const float* __restrict__ rot,
    __half* __restrict__ qh, __half* __restrict__ ql,
    __half* __restrict__ kh)
{
    const int token = blockIdx.x;
    const int s     = token % S_;
    const bool isq  = (blockIdx.y == 0);
    const float* T  = isq ? Tq : Tk;
    const float* g  = isq ? gq : gk;
    const float post = isq ? 0.08838834764831845f : 1.0f;
    const int t = threadIdx.x;

    const float* row = T + (size_t)token * D_;
    float4 v0 = *(const float4*)(row + t * 8);
    float4 v1 = *(const float4*)(row + t * 8 + 4);
    float x[8] = {v0.x, v0.y, v0.z, v0.w, v1.x, v1.y, v1.z, v1.w};

    float ss = 0.0f;
    #pragma unroll
    for (int i = 0; i < 8; i++) ss += x[i] * x[i];
    #pragma unroll
    for (int o = 16; o; o >>= 1) ss += __shfl_xor_sync(0xffffffffu, ss, o);

    __shared__ float red[8];
    __shared__ float rs_s;
    if ((t & 31) == 0) red[t >> 5] = ss;
    __syncthreads();
    if (t == 0) {
        float tot = 0.0f;
        #pragma unroll
        for (int i = 0; i < 8; i++) tot += red[i];
        rs_s = rsqrtf(tot * (1.0f / (float)D_) + 1e-6f);
    }
    __syncthreads();
    const float rs = rs_s;

    const float* rc = rot + (size_t)s * (2 * HD_);
    float out[8];
    #pragma unroll
    for (int j = 0; j < 4; j++) {
        const int d0 = t * 8 + 2 * j;
        const int i2 = d0 & (HD_ - 1);
        const float c  = rc[i2];
        const float sn = rc[HD_ + i2 + 1];
        const float x1 = x[2 * j]     * rs * g[d0];
        const float x2 = x[2 * j + 1] * rs * g[d0 + 1];
        out[2 * j]     = (x1 * c - x2 * sn) * post;
        out[2 * j + 1] = (x1 * sn + x2 * c) * post;
    }

    if (isq) {
        uint32_t* hd = (uint32_t*)(qh + (size_t)token * D_ + t * 8);
        uint32_t* ld = (uint32_t*)(ql + (size_t)token * D_ + t * 8);
        #pragma unroll
        for (int j = 0; j < 4; j++) {
            __half h0 = __float2half_rn(out[2 * j]);
            __half h1 = __float2half_rn(out[2 * j + 1]);
            hd[j] = pack_h2(h0, h1);
            ld[j] = pack_f2(out[2 * j]     - __half2float(h0),
                            out[2 * j + 1] - __half2float(h1));
        }
    } else {
        uint32_t* hd = (uint32_t*)(kh + (size_t)token * D_ + t * 8);
        #pragma unroll
        for (int j = 0; j < 4; j++)
            hd[j] = pack_f2(out[2 * j], out[2 * j + 1]);
    }
}

// ---------------------------------------------------------------------------
// fp16 tensor flash attention: 2-term QK (qh*kh + ql*kh), SINGLE-term PV
// (ph*vh; l summed in fp32 so the denominator stays exact).  Static-shift
// softmax: p = exp(s - 5), clamp at +11 (never fires for real data).
// ---------------------------------------------------------------------------
#define AQ 128
#define AK 64
#define NQT (S_ / AQ)                  // 24 q-tiles
#define KSH 136                        // halves per smem row (272 B)
#define QPH (128 * KSH)                // halves per Q plane
#define KVPH (64 * KSH)                // halves per KV plane
#define ATT_SMEM ((2 * QPH + 6 * KVPH) * 2)   // 174080 bytes
#define MAXS 5.0f

__global__ void __launch_bounds__(256, 1) attn_f16(
    const __half* __restrict__ Qh, const __half* __restrict__ Ql,
    const __half* __restrict__ Kh, const __half* __restrict__ Vh,
    __half* __restrict__ Oah, __half* __restrict__ Oal,
    const int* __restrict__ ctxp, const int* __restrict__ nseqp)
{
    extern __shared__ __align__(16) __half smh[];
    const uint32_t sb = smem_u32(smh);

    const int tid  = threadIdx.x;
    const int warp = tid >> 5;
    const int lane = tid & 31;
    const int lr   = lane >> 2;
    const int lc   = lane & 3;
    const int g    = lane >> 3;
    const int sub  = lane & 7;
    const int h    = blockIdx.y;
    const int b    = blockIdx.z;
    const int hist = (S_ - ctxp[0]) / nseqp[0];

    // heavy-first q-tile ordering
    const int qt   = (blockIdx.x + (hist / AQ)) % NQT;
    const int q0   = qt * AQ;

    const int wm = warp * 16;
    const int q_lo = q0 + wm + lr;
    const int kvlen_lo = (q_lo < hist) ? hist : S_;
    const int kvlen_hi = (q_lo + 8 < hist) ? hist : S_;
    const int kv_end = (q0 + AQ <= hist) ? hist : S_;
    const int ntiles = (kv_end + AK - 1) / AK;

    const int qrow_off = (wm + (g & 1) * 8 + sub) * KSH + (g >> 1) * 8;
    const int krow_off = ((g >> 1) * 8 + sub) * KSH + (g & 1) * 8;

    // ---- stage Q (hi+lo planes) ----
    const size_t qoff = ((size_t)(b * S_ + q0)) * D_ + h * HD_;
    #pragma unroll
    for (int i = 0; i < 16; i++) {
        int idx = i * 256 + tid;
        int pl = idx >> 11, w = idx & 2047, r = w >> 4, c = w & 15;
        uint32_t dst = sb + (pl * QPH + r * KSH + c * 8) * 2;
        const __half* src = (pl ? Ql : Qh) + qoff + (size_t)r * D_ + c * 8;
        CP_ASYNC16(dst, src);
    }
    CP_COMMIT();

    const size_t kvo = ((size_t)(b * S_)) * D_ + h * HD_;
    const __half* Khp = Kh + kvo;
    const __half* Vhp = Vh + kvo;

    auto load_kv = [&](int kt, int bi) {
        const uint32_t baseh = 2 * QPH + bi * 2 * KVPH;
        #pragma unroll
        for (int i = 0; i < 8; i++) {
            int idx = i * 256 + tid;
            int pl = idx >> 10, w = idx & 1023, r = w >> 4, c = w & 15;
            const __half* s = pl ? Vhp : Khp;
            uint32_t dst = sb + (baseh + pl * KVPH + r * KSH + c * 8) * 2;
            CP_ASYNC16(dst, s + (size_t)(kt + r) * D_ + c * 8);
        }
        CP_COMMIT();
    };

    load_kv(0, 0);
    load_kv(AK, 1);

    float oc[16][4];
    #pragma unroll
    for (int f = 0; f < 16; f++)
        #pragma unroll
        for (int e = 0; e < 4; e++) oc[f][e] = 0.0f;
    float l_lo = 0.0f, l_hi = 0.0f;

    for (int t = 0; t < ntiles; t++) {
        const int kt = t * AK;
        if (t + 1 < ntiles) { CP_WAIT(1); } else { CP_WAIT(0); }
        __syncthreads();
        if (t + 2 < ntiles) load_kv((t + 2) * AK, (t + 2) % 3);

        const uint32_t kbaseH = 2 * QPH + (t % 3) * 2 * KVPH;  // halves

        // ---- S = Q K^T (2 terms) ----
        float sc[8][4];
        #pragma unroll
        for (int j = 0; j < 8; j++)
            #pragma unroll
            for (int e = 0; e < 4; e++) sc[j][e] = 0.0f;

        #pragma unroll
        for (int kd = 0; kd < 8; kd++) {
            uint32_t a_h[4], a_l[4];
            ldsm_x4(a_h[0], a_h[1], a_h[2], a_h[3],
                    sb + (qrow_off + kd * 16) * 2);
            ldsm_x4(a_l[0], a_l[1], a_l[2], a_l[3],
                    sb + (QPH + qrow_off + kd * 16) * 2);
            #pragma unroll
            for (int jp = 0; jp < 4; jp++) {
                uint32_t kb[4];
                ldsm_x4(kb[0], kb[1], kb[2], kb[3],
                        sb + (kbaseH + jp * 16 * KSH + krow_off + kd * 16) * 2);
                uint32_t b01[2] = {kb[0], kb[1]}, b23[2] = {kb[2], kb[3]};
                mma_f16(sc[2 * jp],     a_h, b01);
                mma_f16(sc[2 * jp + 1], a_h, b23);
                mma_f16(sc[2 * jp],     a_l, b01);
                mma_f16(sc[2 * jp + 1], a_l, b23);
            }
        }

        // ---- mask ----
        if (kt + AK > kvlen_lo || kt + AK > kvlen_hi) {
            #pragma unroll
            for (int j = 0; j < 8; j++) {
                const int c0 = kt + j * 8 + 2 * lc;
                if (c0     >= kvlen_lo) sc[j][0] = -1e30f;
                if (c0 + 1 >= kvlen_lo) sc[j][1] = -1e30f;
                if (c0     >= kvlen_hi) sc[j][2] = -1e30f;
                if (c0 + 1 >= kvlen_hi) sc[j][3] = -1e30f;
            }
        }

        // ---- static-shift softmax: p = exp(s - MAXS), clamp guard ----
        uint32_t ph01[8], ph23[8];
        float s_lo = 0.0f, s_hi = 0.0f;
        #pragma unroll
        for (int j = 0; j < 8; j++) {
            float p0 = __expf(fminf(sc[j][0] - MAXS, 11.0f));
            float p1 = __expf(fminf(sc[j][1] - MAXS, 11.0f));
            float p2 = __expf(fminf(sc[j][2] - MAXS, 11.0f));
            float p3 = __expf(fminf(sc[j][3] - MAXS, 11.0f));
            s_lo += p0 + p1; s_hi += p2 + p3;
            __half2 h01 = __floats2half2_rn(p0, p1);
            __half2 h23 = __floats2half2_rn(p2, p3);
            ph01[j] = *reinterpret_cast<uint32_t*>(&h01);
            ph23[j] = *reinterpret_cast<uint32_t*>(&h23);
        }
        s_lo += __shfl_xor_sync(0xffffffffu, s_lo, 1);
        s_lo += __shfl_xor_sync(0xffffffffu, s_lo, 2);
        s_hi += __shfl_xor_sync(0xffffffffu, s_hi, 1);
        s_hi += __shfl_xor_sync(0xffffffffu, s_hi, 2);
        l_lo += s_lo;
        l_hi += s_hi;

        // ---- O += P V (single term, fp32 acc) ----
        const uint32_t vh_h = 2 * QPH + (t % 3) * 2 * KVPH + KVPH;   // halves
        const int vrow = lane & 15;
        const int vcol = (lane >> 4) * 8;
        #pragma unroll
        for (int ks = 0; ks < 4; ks++) {
            uint32_t a_h[4] = {ph01[2 * ks], ph23[2 * ks],
                               ph01[2 * ks + 1], ph23[2 * ks + 1]};
            const int vr = ks * 16 + vrow;
            #pragma unroll
            for (int jp = 0; jp < 8; jp++) {
                uint32_t r0, r1, r2, r3;
                uint32_t vaddr = sb + (vh_h + vr * KSH + jp * 16 + vcol) * 2;
                ldsm_x4_t(r0, r1, r2, r3, vaddr);
                uint32_t bh0[2] = {r0, r1}, bh1[2] = {r2, r3};
                mma_f16(oc[2 * jp],     a_h, bh0);
                mma_f16(oc[2 * jp + 1], a_h, bh1);
            }
        }
    }
    CP_WAIT(0);

    // ---- epilogue: write fp16 hi/lo planes directly ----
    const float inv_lo = 1.0f / l_lo;
    const float inv_hi = 1.0f / l_hi;
    const size_t orow = ((size_t)(b * S_ + q0 + wm + lr)) * D_ + h * HD_;
    #pragma unroll
    for (int f = 0; f < 16; f++) {
        const int hd = f * 8 + 2 * lc;
        float v0 = oc[f][0] * inv_lo, v1 = oc[f][1] * inv_lo;
        float v2 = oc[f][2] * inv_hi, v3 = oc[f][3] * inv_hi;
        __half2 h01 = __floats2half2_rn(v0, v1);
        __half2 h23 = __floats2half2_rn(v2, v3);
        *(uint32_t*)(Oah + orow + hd)                  = *reinterpret_cast<uint32_t*>(&h01);
        *(uint32_t*)(Oah + orow + (size_t)8 * D_ + hd) = *reinterpret_cast<uint32_t*>(&h23);
        *(uint32_t*)(Oal + orow + hd) =
            pack_f2(v0 - __low2float(h01), v1 - __high2float(h01));
        *(uint32_t*)(Oal + orow + (size_t)8 * D_ + hd) =
            pack_f2(v2 - __low2float(h23), v3 - __high2float(h23));
    }
}

// ---------------- kernel_launch ---------------------------------------------
extern "C" void kernel_launch(void* const* d_in, const int* in_sizes, int n_in,
                              void* d_out, int out_size)
{
    const float* hidden = (const float*)d_in[0];
    const float* rot    = (const float*)d_in[1];
    const float* Wq = (const float*)d_in[2];
    const float* bq = (const float*)d_in[3];
    const float* Wk = (const float*)d_in[4];
    const float* bk = (const float*)d_in[5];
    const float* Wv = (const float*)d_in[6];
    const float* bv = (const float*)d_in[7];
    const float* gq = (const float*)d_in[8];
    const float* gk = (const float*)d_in[9];
    const float* Wo = (const float*)d_in[10];
    const float* bo = (const float*)d_in[11];
    const int*   ctx  = (const int*)d_in[12];
    const int*   nseq = (const int*)d_in[13];
    float* out = (float*)d_out;

    float *q, *k;
    __half *xh, *xl, *ah, *al, *wh, *qh, *ql, *kh, *vh;
    cudaGetSymbolAddress((void**)&q, g_q);
    cudaGetSymbolAddress((void**)&k, g_k);
    cudaGetSymbolAddress((void**)&xh, g_xh);
    cudaGetSymbolAddress((void**)&xl, g_xl);
    cudaGetSymbolAddress((void**)&ah, g_ah);
    cudaGetSymbolAddress((void**)&al, g_al);
    cudaGetSymbolAddress((void**)&wh, g_wh);
    cudaGetSymbolAddress((void**)&qh, g_qh);
    cudaGetSymbolAddress((void**)&ql, g_ql);
    cudaGetSymbolAddress((void**)&kh, g_kh);
    cudaGetSymbolAddress((void**)&vh, g_vh);

    const int nX = M_ * D_, nW = D_ * D_;

    split_fp16<<<nX / 1024, 256>>>(hidden, xh, xl, nX);
    cvt_f16_4<<<dim3(nW / 1024, 4), 256>>>(Wq, Wk, Wv, Wo, wh, nW);

    cudaFuncSetAttribute(gemm_f16_n256, cudaFuncAttributeMaxDynamicSharedMemorySize,
                         GEMM2_SMEM);

    // Fused QKV projections: z = 0 -> q (f32), 1 -> k (f32), 2 -> v (fp16)
    gemm_f16_n256<<<dim3(D_ / 256, M_ / 128, 3), 256, GEMM2_SMEM>>>(
        xh, xl, wh, bq, bk, bv, q, k, vh);

    rms_rope_split<<<dim3(M_, 2), 256>>>(q, k, gq, gk, rot, qh, ql, kh);

    cudaFuncSetAttribute(attn_f16, cudaFuncAttributeMaxDynamicSharedMemorySize,
                         ATT_SMEM);
    attn_f16<<<dim3(NQT, H_, B_), 256, ATT_SMEM>>>(qh, ql, kh, vh,
                                                   ah, al, ctx, nseq);

    // Output projection (z = 0 path -> float out)
    gemm_f16_n256<<<dim3(D_ / 256, M_ / 128, 1), 256, GEMM2_SMEM>>>(
        ah, al, wh + 3 * (size_t)nW, bo, bo, bo, out, nullptr, nullptr);
}

// round 14
// speedup vs baseline: 5.0749x; 1.0282x over previous
#include <cuda_runtime.h>
#include <cuda_fp16.h>
#include <cstdint>

#define B_   2
#define S_   3072
#define D_   2048
#define H_   16
#define HD_  128
#define M_   (B_ * S_)     // 6144 tokens

// ---------------- scratch (no allocation anywhere) -------------------------
__device__ float  g_q[M_ * D_];
__device__ float  g_k[M_ * D_];
__device__ __half g_xh[M_ * D_], g_xl[M_ * D_];         // hidden hi/lo
__device__ __half g_ah[M_ * D_], g_al[M_ * D_];         // attn-out hi/lo
__device__ __half g_wh[4 * D_ * D_];                    // Wq,Wk,Wv,Wo fp16
__device__ __half g_qh[M_ * D_], g_ql[M_ * D_];
__device__ __half g_kh[M_ * D_];
__device__ __half g_vh[M_ * D_];

// ---------------- helpers ----------------------------------------------------
__device__ __forceinline__ uint32_t smem_u32(const void* p) {
    uint32_t a;
    asm("{ .reg .u64 t; cvta.to.shared.u64 t, %1; cvt.u32.u64 %0, t; }"
        : "=r"(a) : "l"(p));
    return a;
}
__device__ __forceinline__ void mma_f16(float c[4], const uint32_t a[4],
                                        const uint32_t b[2]) {
    asm volatile(
        "mma.sync.aligned.m16n8k16.row.col.f32.f16.f16.f32 "
        "{%0,%1,%2,%3}, {%4,%5,%6,%7}, {%8,%9}, {%0,%1,%2,%3};"
        : "+f"(c[0]), "+f"(c[1]), "+f"(c[2]), "+f"(c[3])
        : "r"(a[0]), "r"(a[1]), "r"(a[2]), "r"(a[3]), "r"(b[0]), "r"(b[1]));
}
__device__ __forceinline__ void ldsm_x4(uint32_t& r0, uint32_t& r1,
                                        uint32_t& r2, uint32_t& r3, uint32_t a) {
    asm volatile("ldmatrix.sync.aligned.m8n8.x4.shared.b16 {%0,%1,%2,%3}, [%4];"
                 : "=r"(r0), "=r"(r1), "=r"(r2), "=r"(r3) : "r"(a));
}
__device__ __forceinline__ void ldsm_x4_t(uint32_t& r0, uint32_t& r1,
                                          uint32_t& r2, uint32_t& r3, uint32_t a) {
    asm volatile("ldmatrix.sync.aligned.m8n8.x4.trans.shared.b16 "
                 "{%0,%1,%2,%3}, [%4];"
                 : "=r"(r0), "=r"(r1), "=r"(r2), "=r"(r3) : "r"(a));
}
__device__ __forceinline__ uint32_t pack_h2(__half a, __half b) {
    __half2 t = __halves2half2(a, b);
    return *reinterpret_cast<uint32_t*>(&t);
}
__device__ __forceinline__ uint32_t pack_f2(float a, float b) {
    __half2 t = __floats2half2_rn(a, b);
    return *reinterpret_cast<uint32_t*>(&t);
}
#define CP_ASYNC16(s, g) \
    asm volatile("cp.async.cg.shared.global [%0], [%1], 16;" :: "r"(s), "l"(g))
#define CP_COMMIT()  asm volatile("cp.async.commit_group;" ::: "memory")
#define CP_WAIT(n)   asm volatile("cp.async.wait_group %0;" :: "n"(n) : "memory")

// ---------------- split fp32 -> fp16 hi/lo -----------------------------------
__global__ void __launch_bounds__(256) split_fp16(
    const float* __restrict__ in, __half* __restrict__ hp, __half* __restrict__ lp,
    int n)
{
    int i = (blockIdx.x * 256 + threadIdx.x) * 4;
    if (i >= n) return;
    float4 v = *(const float4*)(in + i);
    float x[4] = {v.x, v.y, v.z, v.w};
    __half h[4];
    float  r[4];
    #pragma unroll
    for (int j = 0; j < 4; j++) {
        h[j] = __float2half_rn(x[j]);
        r[j] = x[j] - __half2float(h[j]);
    }
    *(uint32_t*)(hp + i)     = pack_h2(h[0], h[1]);
    *(uint32_t*)(hp + i + 2) = pack_h2(h[2], h[3]);
    *(uint32_t*)(lp + i)     = pack_f2(r[0], r[1]);
    *(uint32_t*)(lp + i + 2) = pack_f2(r[2], r[3]);
}

// ---------------- convert 4 weight matrices fp32 -> fp16 (one launch) -------
__global__ void __launch_bounds__(256) cvt_f16_4(
    const float* __restrict__ w0, const float* __restrict__ w1,
    const float* __restrict__ w2, const float* __restrict__ w3,
    __half* __restrict__ out, int n)
{
    const int z = blockIdx.y;
    const float* in = (z == 0) ? w0 : (z == 1) ? w1 : (z == 2) ? w2 : w3;
    __half* o = out + (size_t)z * n;
    int i = (blockIdx.x * 256 + threadIdx.x) * 4;
    if (i >= n) return;
    float4 v = *(const float4*)(in + i);
    *(uint32_t*)(o + i)     = pack_f2(v.x, v.y);
    *(uint32_t*)(o + i + 2) = pack_f2(v.z, v.w);
}

// ---------------------------------------------------------------------------
// fp16 2-term tensor GEMM: O[m,n] = sum_k (Ah+Al)[m,k] * W16[n,k] + bias[n]
// 128x128 CTA tile, BK=64, 2-stage double buffer, 110.6 KB smem ->
// 2 CTAs/SM (cross-CTA overlap hides barrier/cp-wait stalls).
// 8 warps (2m x 4n), warp tile 64x32.  Accumulation order per output is
// identical to the previous N=256 version (same stage/kk/hi-lo sequence).
// ---------------------------------------------------------------------------
#define G2_BK   64
#define G2_STR  72                        // halves per smem row (144 B)
#define G2_APLH (128 * G2_STR)            // 9216 halves per A plane
#define G2_BPLH (128 * G2_STR)            // 9216 halves per B plane
#define G2_STGH (2 * G2_APLH + G2_BPLH)   // 27648 halves / stage
#define GEMM2_SMEM (2 * G2_STGH * 2)      // 110592 bytes (2 stages)
#define G2_NS   (D_ / G2_BK)              // 32 stages

__global__ void __launch_bounds__(256, 2) gemm_f16_n128(
    const __half* __restrict__ Ahg, const __half* __restrict__ Alg,
    const __half* __restrict__ WhB,
    const float* __restrict__ b0p, const float* __restrict__ b1p,
    const float* __restrict__ b2p,
    float* __restrict__ o0, float* __restrict__ o1, __half* __restrict__ o2)
{
    extern __shared__ __align__(16) __half g2sm[];
    const uint32_t sb = smem_u32(g2sm);

    const int z    = blockIdx.z;
    const __half* Bhg = WhB + (size_t)z * D_ * D_;
    const float* bias = (z == 0) ? b0p : (z == 1) ? b1p : b2p;

    const int bm   = blockIdx.y * 128;
    const int bn   = blockIdx.x * 128;
    const int tid  = threadIdx.x;
    const int warp = tid >> 5;
    const int lane = tid & 31;
    const int lr   = lane >> 2;
    const int lc   = lane & 3;
    const int g    = lane >> 3;
    const int sub  = lane & 7;
    const int wm   = (warp & 1) * 64;
    const int wn   = (warp >> 1) * 32;

    int aoff[4], boff[2];
    #pragma unroll
    for (int mi = 0; mi < 4; mi++)
        aoff[mi] = (wm + mi * 16 + (g & 1) * 8 + sub) * G2_STR + (g >> 1) * 8;
    #pragma unroll
    for (int nip = 0; nip < 2; nip++)
        boff[nip] = (wn + nip * 16 + (g >> 1) * 8 + sub) * G2_STR + (g & 1) * 8;

    auto load_stage = [&](int s, int buf) {
        const int kt = s * G2_BK;
        const uint32_t stg = buf * G2_STGH;
        #pragma unroll
        for (int i = 0; i < 12; i++) {
            const int idx = i * 256 + tid;        // 0..3071
            uint32_t dsth;
            const __half* src;
            if (idx < 2048) {                     // A planes (hi, lo)
                const int pl = idx >> 10, w = idx & 1023;
                const int row = w >> 3, c = w & 7;
                dsth = stg + pl * G2_APLH + row * G2_STR + c * 8;
                src = (pl ? Alg : Ahg) + (size_t)(bm + row) * D_ + kt + c * 8;
            } else {                               // W plane
                const int j = idx - 2048;          // 0..1023
                const int row = j >> 3, c = j & 7;
                dsth = stg + 2 * G2_APLH + row * G2_STR + c * 8;
                src = Bhg + (size_t)(bn + row) * D_ + kt + c * 8;
            }
            CP_ASYNC16(sb + dsth * 2, src);
        }
        CP_COMMIT();
    };

    float acc[4][4][4];
    #pragma unroll
    for (int mi = 0; mi < 4; mi++)
        #pragma unroll
        for (int ni = 0; ni < 4; ni++)
            #pragma unroll
            for (int r = 0; r < 4; r++) acc[mi][ni][r] = 0.0f;

    load_stage(0, 0);
    load_stage(1, 1);

    for (int s = 0; s < G2_NS; s++) {
        if (s + 1 < G2_NS) { CP_WAIT(1); } else { CP_WAIT(0); }
        __syncthreads();

        const uint32_t stg = (s & 1) * G2_STGH;
        #pragma unroll
        for (int kk = 0; kk < 4; kk++) {
            const int kh = kk * 16;
            uint32_t ah[4][4], al[4][4];
            #pragma unroll
            for (int mi = 0; mi < 4; mi++) {
                ldsm_x4(ah[mi][0], ah[mi][1], ah[mi][2], ah[mi][3],
                        sb + (stg + aoff[mi] + kh) * 2);
                ldsm_x4(al[mi][0], al[mi][1], al[mi][2], al[mi][3],
                        sb + (stg + G2_APLH + aoff[mi] + kh) * 2);
            }
            #pragma unroll
            for (int nip = 0; nip < 2; nip++) {
                uint32_t bh[4];
                ldsm_x4(bh[0], bh[1], bh[2], bh[3],
                        sb + (stg + 2 * G2_APLH + boff[nip] + kh) * 2);
                uint32_t bh01[2] = {bh[0], bh[1]}, bh23[2] = {bh[2], bh[3]};
                #pragma unroll
                for (int mi = 0; mi < 4; mi++)
                    mma_f16(acc[mi][2 * nip],     ah[mi], bh01);
                #pragma unroll
                for (int mi = 0; mi < 4; mi++)
                    mma_f16(acc[mi][2 * nip + 1], ah[mi], bh23);
                #pragma unroll
                for (int mi = 0; mi < 4; mi++)
                    mma_f16(acc[mi][2 * nip],     al[mi], bh01);
                #pragma unroll
                for (int mi = 0; mi < 4; mi++)
                    mma_f16(acc[mi][2 * nip + 1], al[mi], bh23);
            }
        }

        __syncthreads();           // all warps done reading this buffer
        if (s + 2 < G2_NS) load_stage(s + 2, s & 1);
    }

    // epilogue
    #pragma unroll
    for (int ni = 0; ni < 4; ni++) {
        const int c = bn + wn + ni * 8 + 2 * lc;
        const float bb0 = __ldg(bias + c);
        const float bb1 = __ldg(bias + c + 1);
        #pragma unroll
        for (int mi = 0; mi < 4; mi++) {
            const int r = bm + wm + mi * 16 + lr;
            const float v00 = acc[mi][ni][0] + bb0;
            const float v01 = acc[mi][ni][1] + bb1;
            const float v10 = acc[mi][ni][2] + bb0;
            const float v11 = acc[mi][ni][3] + bb1;
            if (z == 2) {
                *(uint32_t*)(o2 + (size_t)r * D_ + c)       = pack_f2(v00, v01);
                *(uint32_t*)(o2 + (size_t)(r + 8) * D_ + c) = pack_f2(v10, v11);
            } else {
                float* Of = (z == 0) ? o0 : o1;
                *(float2*)(Of + (size_t)r * D_ + c)       = float2{v00, v01};
                *(float2*)(Of + (size_t)(r + 8) * D_ + c) = float2{v10, v11};
            }
        }
    }
}

// ---------------------------------------------------------------------------
// RMSNorm + interleaved RoPE -> fp16 planes: qh+ql (q scaled 1/sqrt(HD)), kh.
// ---------------------------------------------------------------------------
__global__ void __launch_bounds__(256) rms_rope_split(
    const float* __restrict__ Tq, const float* __restrict__ Tk,
    const float* __restrict__ gq, const float* __restrict__ gk,
    const float* __restrict__ rot,
    __half* __restrict__ qh, __half* __restrict__ ql,
    __half* __restrict__ kh)
{
    const int token = blockIdx.x;
    const int s     = token % S_;
    const bool isq  = (blockIdx.y == 0);
    const float* T  = isq ? Tq : Tk;
    const float* g  = isq ? gq : gk;
    const float post = isq ? 0.08838834764831845f : 1.0f;
    const int t = threadIdx.x;

    const float* row = T + (size_t)token * D_;
    float4 v0 = *(const float4*)(row + t * 8);
    float4 v1 = *(const float4*)(row + t * 8 + 4);
    float x[8] = {v0.x, v0.y, v0.z, v0.w, v1.x, v1.y, v1.z, v1.w};

    float ss = 0.0f;
    #pragma unroll
    for (int i = 0; i < 8; i++) ss += x[i] * x[i];
    #pragma unroll
    for (int o = 16; o; o >>= 1) ss += __shfl_xor_sync(0xffffffffu, ss, o);

    __shared__ float red[8];
    __shared__ float rs_s;
    if ((t & 31) == 0) red[t >> 5] = ss;
    __syncthreads();
    if (t == 0) {
        float tot = 0.0f;
        #pragma unroll
        for (int i = 0; i < 8; i++) tot += red[i];
        rs_s = rsqrtf(tot * (1.0f / (float)D_) + 1e-6f);
    }
    __syncthreads();
    const float rs = rs_s;

    const float* rc = rot + (size_t)s * (2 * HD_);
    float out[8];
    #pragma unroll
    for (int j = 0; j < 4; j++) {
        const int d0 = t * 8 + 2 * j;
        const int i2 = d0 & (HD_ - 1);
        const float c  = rc[i2];
        const float sn = rc[HD_ + i2 + 1];
        const float x1 = x[2 * j]     * rs * g[d0];
        const float x2 = x[2 * j + 1] * rs * g[d0 + 1];
        out[2 * j]     = (x1 * c - x2 * sn) * post;
        out[2 * j + 1] = (x1 * sn + x2 * c) * post;
    }

    if (isq) {
        uint32_t* hd = (uint32_t*)(qh + (size_t)token * D_ + t * 8);
        uint32_t* ld = (uint32_t*)(ql + (size_t)token * D_ + t * 8);
        #pragma unroll
        for (int j = 0; j < 4; j++) {
            __half h0 = __float2half_rn(out[2 * j]);
            __half h1 = __float2half_rn(out[2 * j + 1]);
            hd[j] = pack_h2(h0, h1);
            ld[j] = pack_f2(out[2 * j]     - __half2float(h0),
                            out[2 * j + 1] - __half2float(h1));
        }
    } else {
        uint32_t* hd = (uint32_t*)(kh + (size_t)token * D_ + t * 8);
        #pragma unroll
        for (int j = 0; j < 4; j++)
            hd[j] = pack_f2(out[2 * j], out[2 * j + 1]);
    }
}

// ---------------------------------------------------------------------------
// fp16 tensor flash attention: 2-term QK, single-term PV (fp32 l).
// Static-shift softmax p = exp(s - 5), clamp +11 (guard only).
// ---------------------------------------------------------------------------
#define AQ 128
#define AK 64
#define NQT (S_ / AQ)                  // 24 q-tiles
#define KSH 136                        // halves per smem row (272 B)
#define QPH (128 * KSH)                // halves per Q plane
#define KVPH (64 * KSH)                // halves per KV plane
#define ATT_SMEM ((2 * QPH + 6 * KVPH) * 2)   // 174080 bytes
#define MAXS 5.0f

__global__ void __launch_bounds__(256, 1) attn_f16(
    const __half* __restrict__ Qh, const __half* __restrict__ Ql,
    const __half* __restrict__ Kh, const __half* __restrict__ Vh,
    __half* __restrict__ Oah, __half* __restrict__ Oal,
    const int* __restrict__ ctxp, const int* __restrict__ nseqp)
{
    extern __shared__ __align__(16) __half smh[];
    const uint32_t sb = smem_u32(smh);

    const int tid  = threadIdx.x;
    const int warp = tid >> 5;
    const int lane = tid & 31;
    const int lr   = lane >> 2;
    const int lc   = lane & 3;
    const int g    = lane >> 3;
    const int sub  = lane & 7;
    const int h    = blockIdx.y;
    const int b    = blockIdx.z;
    const int hist = (S_ - ctxp[0]) / nseqp[0];

    const int qt   = (blockIdx.x + (hist / AQ)) % NQT;
    const int q0   = qt * AQ;

    const int wm = warp * 16;
    const int q_lo = q0 + wm + lr;
    const int kvlen_lo = (q_lo < hist) ? hist : S_;
    const int kvlen_hi = (q_lo + 8 < hist) ? hist : S_;
    const int kv_end = (q0 + AQ <= hist) ? hist : S_;
    const int ntiles = (kv_end + AK - 1) / AK;

    const int qrow_off = (wm + (g & 1) * 8 + sub) * KSH + (g >> 1) * 8;
    const int krow_off = ((g >> 1) * 8 + sub) * KSH + (g & 1) * 8;

    const size_t qoff = ((size_t)(b * S_ + q0)) * D_ + h * HD_;
    #pragma unroll
    for (int i = 0; i < 16; i++) {
        int idx = i * 256 + tid;
        int pl = idx >> 11, w = idx & 2047, r = w >> 4, c = w & 15;
        uint32_t dst = sb + (pl * QPH + r * KSH + c * 8) * 2;
        const __half* src = (pl ? Ql : Qh) + qoff + (size_t)r * D_ + c * 8;
        CP_ASYNC16(dst, src);
    }
    CP_COMMIT();

    const size_t kvo = ((size_t)(b * S_)) * D_ + h * HD_;
    const __half* Khp = Kh + kvo;
    const __half* Vhp = Vh + kvo;

    auto load_kv = [&](int kt, int bi) {
        const uint32_t baseh = 2 * QPH + bi * 2 * KVPH;
        #pragma unroll
        for (int i = 0; i < 8; i++) {
            int idx = i * 256 + tid;
            int pl = idx >> 10, w = idx & 1023, r = w >> 4, c = w & 15;
            const __half* s = pl ? Vhp : Khp;
            uint32_t dst = sb + (baseh + pl * KVPH + r * KSH + c * 8) * 2;
            CP_ASYNC16(dst, s + (size_t)(kt + r) * D_ + c * 8);
        }
        CP_COMMIT();
    };

    load_kv(0, 0);
    load_kv(AK, 1);

    float oc[16][4];
    #pragma unroll
    for (int f = 0; f < 16; f++)
        #pragma unroll
        for (int e = 0; e < 4; e++) oc[f][e] = 0.0f;
    float l_lo = 0.0f, l_hi = 0.0f;

    for (int t = 0; t < ntiles; t++) {
        const int kt = t * AK;
        if (t + 1 < ntiles) { CP_WAIT(1); } else { CP_WAIT(0); }
        __syncthreads();
        if (t + 2 < ntiles) load_kv((t + 2) * AK, (t + 2) % 3);

        const uint32_t kbaseH = 2 * QPH + (t % 3) * 2 * KVPH;

        float sc[8][4];
        #pragma unroll
        for (int j = 0; j < 8; j++)
            #pragma unroll
            for (int e = 0; e < 4; e++) sc[j][e] = 0.0f;

        #pragma unroll
        for (int kd = 0; kd < 8; kd++) {
            uint32_t a_h[4], a_l[4];
            ldsm_x4(a_h[0], a_h[1], a_h[2], a_h[3],
                    sb + (qrow_off + kd * 16) * 2);
            ldsm_x4(a_l[0], a_l[1], a_l[2], a_l[3],
                    sb + (QPH + qrow_off + kd * 16) * 2);
            #pragma unroll
            for (int jp = 0; jp < 4; jp++) {
                uint32_t kb[4];
                ldsm_x4(kb[0], kb[1], kb[2], kb[3],
                        sb + (kbaseH + jp * 16 * KSH + krow_off + kd * 16) * 2);
                uint32_t b01[2] = {kb[0], kb[1]}, b23[2] = {kb[2], kb[3]};
                mma_f16(sc[2 * jp],     a_h, b01);
                mma_f16(sc[2 * jp + 1], a_h, b23);
                mma_f16(sc[2 * jp],     a_l, b01);
                mma_f16(sc[2 * jp + 1], a_l, b23);
            }
        }

        if (kt + AK > kvlen_lo || kt + AK > kvlen_hi) {
            #pragma unroll
            for (int j = 0; j < 8; j++) {
                const int c0 = kt + j * 8 + 2 * lc;
                if (c0     >= kvlen_lo) sc[j][0] = -1e30f;
                if (c0 + 1 >= kvlen_lo) sc[j][1] = -1e30f;
                if (c0     >= kvlen_hi) sc[j][2] = -1e30f;
                if (c0 + 1 >= kvlen_hi) sc[j][3] = -1e30f;
            }
        }

        uint32_t ph01[8], ph23[8];
        float s_lo = 0.0f, s_hi = 0.0f;
        #pragma unroll
        for (int j = 0; j < 8; j++) {
            float p0 = __expf(fminf(sc[j][0] - MAXS, 11.0f));
            float p1 = __expf(fminf(sc[j][1] - MAXS, 11.0f));
            float p2 = __expf(fminf(sc[j][2] - MAXS, 11.0f));
            float p3 = __expf(fminf(sc[j][3] - MAXS, 11.0f));
            s_lo += p0 + p1; s_hi += p2 + p3;
            __half2 h01 = __floats2half2_rn(p0, p1);
            __half2 h23 = __floats2half2_rn(p2, p3);
            ph01[j] = *reinterpret_cast<uint32_t*>(&h01);
            ph23[j] = *reinterpret_cast<uint32_t*>(&h23);
        }
        s_lo += __shfl_xor_sync(0xffffffffu, s_lo, 1);
        s_lo += __shfl_xor_sync(0xffffffffu, s_lo, 2);
        s_hi += __shfl_xor_sync(0xffffffffu, s_hi, 1);
        s_hi += __shfl_xor_sync(0xffffffffu, s_hi, 2);
        l_lo += s_lo;
        l_hi += s_hi;

        const uint32_t vh_h = 2 * QPH + (t % 3) * 2 * KVPH + KVPH;
        const int vrow = lane & 15;
        const int vcol = (lane >> 4) * 8;
        #pragma unroll
        for (int ks = 0; ks < 4; ks++) {
            uint32_t a_h[4] = {ph01[2 * ks], ph23[2 * ks],
                               ph01[2 * ks + 1], ph23[2 * ks + 1]};
            const int vr = ks * 16 + vrow;
            #pragma unroll
            for (int jp = 0; jp < 8; jp++) {
                uint32_t r0, r1, r2, r3;
                uint32_t vaddr = sb + (vh_h + vr * KSH + jp * 16 + vcol) * 2;
                ldsm_x4_t(r0, r1, r2, r3, vaddr);
                uint32_t bh0[2] = {r0, r1}, bh1[2] = {r2, r3};
                mma_f16(oc[2 * jp],     a_h, bh0);
                mma_f16(oc[2 * jp + 1], a_h, bh1);
            }
        }
    }
    CP_WAIT(0);

    const float inv_lo = 1.0f / l_lo;
    const float inv_hi = 1.0f / l_hi;
    const size_t orow = ((size_t)(b * S_ + q0 + wm + lr)) * D_ + h * HD_;
    #pragma unroll
    for (int f = 0; f < 16; f++) {
        const int hd = f * 8 + 2 * lc;
        float v0 = oc[f][0] * inv_lo, v1 = oc[f][1] * inv_lo;
        float v2 = oc[f][2] * inv_hi, v3 = oc[f][3] * inv_hi;
        __half2 h01 = __floats2half2_rn(v0, v1);
        __half2 h23 = __floats2half2_rn(v2, v3);
        *(uint32_t*)(Oah + orow + hd)                  = *reinterpret_cast<uint32_t*>(&h01);
        *(uint32_t*)(Oah + orow + (size_t)8 * D_ + hd) = *reinterpret_cast<uint32_t*>(&h23);
        *(uint32_t*)(Oal + orow + hd) =
            pack_f2(v0 - __low2float(h01), v1 - __high2float(h01));
        *(uint32_t*)(Oal + orow + (size_t)8 * D_ + hd) =
            pack_f2(v2 - __low2float(h23), v3 - __high2float(h23));
    }
}

// ---------------- kernel_launch ---------------------------------------------
extern "C" void kernel_launch(void* const* d_in, const int* in_sizes, int n_in,
                              void* d_out, int out_size)
{
    const float* hidden = (const float*)d_in[0];
    const float* rot    = (const float*)d_in[1];
    const float* Wq = (const float*)d_in[2];
    const float* bq = (const float*)d_in[3];
    const float* Wk = (const float*)d_in[4];
    const float* bk = (const float*)d_in[5];
    const float* Wv = (const float*)d_in[6];
    const float* bv = (const float*)d_in[7];
    const float* gq = (const float*)d_in[8];
    const float* gk = (const float*)d_in[9];
    const float* Wo = (const float*)d_in[10];
    const float* bo = (const float*)d_in[11];
    const int*   ctx  = (const int*)d_in[12];
    const int*   nseq = (const int*)d_in[13];
    float* out = (float*)d_out;

    float *q, *k;
    __half *xh, *xl, *ah, *al, *wh, *qh, *ql, *kh, *vh;
    cudaGetSymbolAddress((void**)&q, g_q);
    cudaGetSymbolAddress((void**)&k, g_k);
    cudaGetSymbolAddress((void**)&xh, g_xh);
    cudaGetSymbolAddress((void**)&xl, g_xl);
    cudaGetSymbolAddress((void**)&ah, g_ah);
    cudaGetSymbolAddress((void**)&al, g_al);
    cudaGetSymbolAddress((void**)&wh, g_wh);
    cudaGetSymbolAddress((void**)&qh, g_qh);
    cudaGetSymbolAddress((void**)&ql, g_ql);
    cudaGetSymbolAddress((void**)&kh, g_kh);
    cudaGetSymbolAddress((void**)&vh, g_vh);

    const int nX = M_ * D_, nW = D_ * D_;

    split_fp16<<<nX / 1024, 256>>>(hidden, xh, xl, nX);
    cvt_f16_4<<<dim3(nW / 1024, 4), 256>>>(Wq, Wk, Wv, Wo, wh, nW);

    cudaFuncSetAttribute(gemm_f16_n128, cudaFuncAttributeMaxDynamicSharedMemorySize,
                         GEMM2_SMEM);

    // Fused QKV projections: z = 0 -> q (f32), 1 -> k (f32), 2 -> v (fp16)
    gemm_f16_n128<<<dim3(D_ / 128, M_ / 128, 3), 256, GEMM2_SMEM>>>(
        xh, xl, wh, bq, bk, bv, q, k, vh);

    rms_rope_split<<<dim3(M_, 2), 256>>>(q, k, gq, gk, rot, qh, ql, kh);

    cudaFuncSetAttribute(attn_f16, cudaFuncAttributeMaxDynamicSharedMemorySize,
                         ATT_SMEM);
    attn_f16<<<dim3(NQT, H_, B_), 256, ATT_SMEM>>>(qh, ql, kh, vh,
                                                   ah, al, ctx, nseq);

    // Output projection (z = 0 path -> float out)
    gemm_f16_n128<<<dim3(D_ / 128, M_ / 128, 1), 256, GEMM2_SMEM>>>(
        ah, al, wh + 3 * (size_t)nW, bo, bo, bo, out, nullptr, nullptr);
}